// round 5
// baseline (speedup 1.0000x reference)
#include <cuda_runtime.h>
#include <cuda_bf16.h>
#include <cstdint>
#include <math.h>

// ---------------- problem constants ----------------
#define Bb   4
#define Ss   1024
#define Ee   1024
#define Hh   16
#define HDs  64
#define MTOT 4096      // B*S
#define E3   3072      // 3*E
#define Kdim 1024

// ---------------- scratch (device globals) ----------------
__device__ float          g_qkv [MTOT * E3];     // [B*S, 3E] fp32
__device__ float          g_attn[MTOT * Ee];     // [B*S, E]  fp32
__device__ __nv_bfloat16  g_xhi [MTOT * Ee];     // X split; reused as Q_hi after QKV
__device__ __nv_bfloat16  g_xlo [MTOT * Ee];     //           reused as Q_lo
__device__ __nv_bfloat16  g_wqh [E3 * Ee];       // Wqkv^T
__device__ __nv_bfloat16  g_wql [E3 * Ee];
__device__ __nv_bfloat16  g_wph [Ee * Ee];       // Wproj^T
__device__ __nv_bfloat16  g_wpl [Ee * Ee];
__device__ __nv_bfloat16  g_ahi [MTOT * Ee];     // K_hi, then attn_hi for proj
__device__ __nv_bfloat16  g_alo [MTOT * Ee];     // K_lo, then attn_lo
__device__ __nv_bfloat16  g_vth [Bb * Ee * Ss];  // V^T split: [(b*E + h*64+d)*S + s]
__device__ __nv_bfloat16  g_vtl [Bb * Ee * Ss];

// ---------------- helpers ----------------
__device__ __forceinline__ void mma16816(float* c, const uint32_t* a, const uint32_t* b)
{
    asm volatile(
        "mma.sync.aligned.m16n8k16.row.col.f32.bf16.bf16.f32 "
        "{%0,%1,%2,%3}, {%4,%5,%6,%7}, {%8,%9}, {%0,%1,%2,%3};"
        : "+f"(c[0]), "+f"(c[1]), "+f"(c[2]), "+f"(c[3])
        : "r"(a[0]), "r"(a[1]), "r"(a[2]), "r"(a[3]), "r"(b[0]), "r"(b[1]));
}
__device__ __forceinline__ void cp16(uint32_t saddr, const void* g)
{
    asm volatile("cp.async.cg.shared.global [%0], [%1], 16;"
                 :: "r"(saddr), "l"(g));
}
__device__ __forceinline__ uint32_t smem_u32(const void* p) {
    uint32_t a;
    asm("{ .reg .u64 t; cvta.to.shared.u64 t, %1; cvt.u32.u64 %0, t; }"
        : "=r"(a) : "l"(p));
    return a;
}
__device__ __forceinline__ void splitpack(float f0, float f1, uint32_t& hi, uint32_t& lo)
{
    __nv_bfloat16 h0 = __float2bfloat16_rn(f0);
    __nv_bfloat16 h1 = __float2bfloat16_rn(f1);
    __nv_bfloat162 hp = __halves2bfloat162(h0, h1);
    hi = *(uint32_t*)&hp;
    __nv_bfloat162 lp = __floats2bfloat162_rn(f0 - __bfloat162float(h0),
                                              f1 - __bfloat162float(h1));
    lo = *(uint32_t*)&lp;
}

// ---------------- split fp32 -> (bf16 hi, bf16 lo) ----------------
__global__ __launch_bounds__(256)
void split_hi_lo(const float* __restrict__ x,
                 __nv_bfloat16* __restrict__ hi,
                 __nv_bfloat16* __restrict__ lo, int n)
{
    int i = (blockIdx.x * 256 + threadIdx.x) * 4;
    if (i >= n) return;
    float4 v = *(const float4*)(x + i);
    __nv_bfloat16 h[4], l[4];
    float vv[4] = {v.x, v.y, v.z, v.w};
#pragma unroll
    for (int q = 0; q < 4; q++) {
        h[q] = __float2bfloat16_rn(vv[q]);
        l[q] = __float2bfloat16_rn(vv[q] - __bfloat162float(h[q]));
    }
    *(uint2*)(hi + i) = *(uint2*)h;
    *(uint2*)(lo + i) = *(uint2*)l;
}

// ---------------- split Q and K sections of qkv ----------------
__global__ __launch_bounds__(256)
void split_qk(const float* __restrict__ qkv,
              __nv_bfloat16* __restrict__ qh, __nv_bfloat16* __restrict__ ql,
              __nv_bfloat16* __restrict__ kh, __nv_bfloat16* __restrict__ kl)
{
    int t = blockIdx.x * 256 + threadIdx.x;
    int i4 = t * 4;
    if (i4 >= MTOT * Ee) return;
    int row = i4 >> 10, col = i4 & 1023;
    float4 q = *(const float4*)&qkv[(size_t)row * E3 + col];
    float4 k = *(const float4*)&qkv[(size_t)row * E3 + Ee + col];
    float qv[4] = {q.x, q.y, q.z, q.w}, kv[4] = {k.x, k.y, k.z, k.w};
    __nv_bfloat16 qhh[4], qll[4], khh[4], kll[4];
#pragma unroll
    for (int e = 0; e < 4; e++) {
        qhh[e] = __float2bfloat16_rn(qv[e]);
        qll[e] = __float2bfloat16_rn(qv[e] - __bfloat162float(qhh[e]));
        khh[e] = __float2bfloat16_rn(kv[e]);
        kll[e] = __float2bfloat16_rn(kv[e] - __bfloat162float(khh[e]));
    }
    *(uint2*)(qh + i4) = *(uint2*)qhh;
    *(uint2*)(ql + i4) = *(uint2*)qll;
    *(uint2*)(kh + i4) = *(uint2*)khh;
    *(uint2*)(kl + i4) = *(uint2*)kll;
}

// ---------------- transpose+split V: [s][hcol] -> [hcol][s] per batch ----------------
__global__ __launch_bounds__(256)
void transpose_v_split(const float* __restrict__ qkv,
                       __nv_bfloat16* __restrict__ vth, __nv_bfloat16* __restrict__ vtl)
{
    __shared__ float tile[32][33];
    int c0 = blockIdx.x * 32;     // hcol
    int s0 = blockIdx.y * 32;
    int b  = blockIdx.z;
    int tx = threadIdx.x, ty = threadIdx.y;   // 32 x 8
#pragma unroll
    for (int i = 0; i < 32; i += 8)
        tile[ty + i][tx] = qkv[(size_t)(b * Ss + s0 + ty + i) * E3 + 2 * Ee + c0 + tx];
    __syncthreads();
#pragma unroll
    for (int i = 0; i < 32; i += 8) {
        int ccol = c0 + ty + i, srow = s0 + tx;
        float v = tile[tx][ty + i];
        __nv_bfloat16 h = __float2bfloat16_rn(v);
        vth[(size_t)(b * Ee + ccol) * Ss + srow] = h;
        vtl[(size_t)(b * Ee + ccol) * Ss + srow] = __float2bfloat16_rn(v - __bfloat162float(h));
    }
}

// ---------------- transpose + split: W[K][N] -> T_hi/lo[N][K] ----------------
__global__ __launch_bounds__(256)
void transpose_split(const float* __restrict__ W,
                     __nv_bfloat16* __restrict__ Thi,
                     __nv_bfloat16* __restrict__ Tlo, int K, int N)
{
    __shared__ float tile[32][33];
    int n0 = blockIdx.x * 32, k0 = blockIdx.y * 32;
    int tx = threadIdx.x, ty = threadIdx.y;   // 32 x 8
#pragma unroll
    for (int i = 0; i < 32; i += 8)
        tile[ty + i][tx] = W[(size_t)(k0 + ty + i) * N + n0 + tx];
    __syncthreads();
#pragma unroll
    for (int i = 0; i < 32; i += 8) {
        int n = n0 + ty + i, k = k0 + tx;
        float v = tile[tx][ty + i];
        __nv_bfloat16 h = __float2bfloat16_rn(v);
        Thi[(size_t)n * K + k] = h;
        Tlo[(size_t)n * K + k] = __float2bfloat16_rn(v - __bfloat162float(h));
    }
}

// ---------------- split-bf16 tensor-core GEMM (BK=16, 48KB smem, 2 CTAs/SM) ----------------
#define GBK      16
#define GSTRIDE  24                        // 16 elems + 8 pad = 48 B rows (16B-aligned)
#define ARR_B    (128 * GSTRIDE * 2)       // 6144 B per array
#define STAGE_B  (4 * ARR_B)               // 24576 B (Ah, Al, Bh, Bl)
#define GEMM_SMEM (2 * STAGE_B)            // 49152 B

__global__ __launch_bounds__(256, 2)
void gemm_mma(const __nv_bfloat16* __restrict__ Ahi, const __nv_bfloat16* __restrict__ Alo,
              const __nv_bfloat16* __restrict__ Bhi, const __nv_bfloat16* __restrict__ Blo,
              const float* __restrict__ bias, float* __restrict__ C, int N)
{
    extern __shared__ char smem[];
    const uint32_t sb = smem_u32(smem);
    const int tid  = threadIdx.x;
    const int wid  = tid >> 5, lane = tid & 31;
    const int wm   = wid >> 2, wn = wid & 3;          // warp grid 2 x 4
    const int g    = lane >> 2, tig = lane & 3;
    const int bm   = blockIdx.y * 128, bn = blockIdx.x * 128;
    const int NC   = Kdim / GBK;                      // 64 chunks

    float acc[4][4][4];
#pragma unroll
    for (int im = 0; im < 4; im++)
#pragma unroll
        for (int in = 0; in < 4; in++)
#pragma unroll
            for (int q = 0; q < 4; q++) acc[im][in][q] = 0.0f;

    auto prefetch = [&](int c, int st) {
#pragma unroll
        for (int i = 0; i < 4; i++) {
            int idx = tid + i * 256;        // 0..1023
            int arr = idx >> 8;             // 0:Ah 1:Al 2:Bh 3:Bl
            int e   = idx & 255;
            int row = e >> 1;               // 0..127
            int seg = e & 1;                // 16B segment along k
            const __nv_bfloat16* gp;
            size_t koff = (size_t)c * GBK + seg * 8;
            if      (arr == 0) gp = Ahi + (size_t)(bm + row) * Kdim + koff;
            else if (arr == 1) gp = Alo + (size_t)(bm + row) * Kdim + koff;
            else if (arr == 2) gp = Bhi + (size_t)(bn + row) * Kdim + koff;
            else               gp = Blo + (size_t)(bn + row) * Kdim + koff;
            uint32_t sa = sb + st * STAGE_B + arr * ARR_B + (row * GSTRIDE + seg * 8) * 2;
            cp16(sa, gp);
        }
        asm volatile("cp.async.commit_group;");
    };

    prefetch(0, 0);

    for (int c = 0; c < NC; c++) {
        const int st = c & 1;
        if (c + 1 < NC) {
            prefetch(c + 1, (c + 1) & 1);
            asm volatile("cp.async.wait_group 1;");
        } else {
            asm volatile("cp.async.wait_group 0;");
        }
        __syncthreads();

        const __nv_bfloat16* sAh = (const __nv_bfloat16*)(smem + st * STAGE_B);
        const __nv_bfloat16* sAl = (const __nv_bfloat16*)(smem + st * STAGE_B + ARR_B);
        const __nv_bfloat16* sBh = (const __nv_bfloat16*)(smem + st * STAGE_B + 2 * ARR_B);
        const __nv_bfloat16* sBl = (const __nv_bfloat16*)(smem + st * STAGE_B + 3 * ARR_B);

        {
            uint32_t a[4][4], bh[4][2], bl[4][2];
            // B fragments (hi and lo) once, kept in regs
#pragma unroll
            for (int in = 0; in < 4; in++) {
                int n0 = wn * 32 + in * 8 + g;
                bh[in][0] = *(const uint32_t*)&sBh[n0 * GSTRIDE + 2 * tig];
                bh[in][1] = *(const uint32_t*)&sBh[n0 * GSTRIDE + 2 * tig + 8];
                bl[in][0] = *(const uint32_t*)&sBl[n0 * GSTRIDE + 2 * tig];
                bl[in][1] = *(const uint32_t*)&sBl[n0 * GSTRIDE + 2 * tig + 8];
            }
            // Ah pass: Ah*Bh and Ah*Bl
#pragma unroll
            for (int im = 0; im < 4; im++) {
                int r = wm * 64 + im * 16 + g;
                a[im][0] = *(const uint32_t*)&sAh[(r    ) * GSTRIDE + 2 * tig];
                a[im][1] = *(const uint32_t*)&sAh[(r + 8) * GSTRIDE + 2 * tig];
                a[im][2] = *(const uint32_t*)&sAh[(r    ) * GSTRIDE + 2 * tig + 8];
                a[im][3] = *(const uint32_t*)&sAh[(r + 8) * GSTRIDE + 2 * tig + 8];
            }
#pragma unroll
            for (int im = 0; im < 4; im++)
#pragma unroll
                for (int in = 0; in < 4; in++) {
                    mma16816(acc[im][in], a[im], bh[in]);
                    mma16816(acc[im][in], a[im], bl[in]);
                }
            // Al pass: Al*Bh
#pragma unroll
            for (int im = 0; im < 4; im++) {
                int r = wm * 64 + im * 16 + g;
                a[im][0] = *(const uint32_t*)&sAl[(r    ) * GSTRIDE + 2 * tig];
                a[im][1] = *(const uint32_t*)&sAl[(r + 8) * GSTRIDE + 2 * tig];
                a[im][2] = *(const uint32_t*)&sAl[(r    ) * GSTRIDE + 2 * tig + 8];
                a[im][3] = *(const uint32_t*)&sAl[(r + 8) * GSTRIDE + 2 * tig + 8];
            }
#pragma unroll
            for (int im = 0; im < 4; im++)
#pragma unroll
                for (int in = 0; in < 4; in++)
                    mma16816(acc[im][in], a[im], bh[in]);
        }
        __syncthreads();
    }

#pragma unroll
    for (int im = 0; im < 4; im++) {
        int r = bm + wm * 64 + im * 16 + g;
#pragma unroll
        for (int in = 0; in < 4; in++) {
            int ccol = bn + wn * 32 + in * 8 + 2 * tig;
            float2 b01 = *(const float2*)&bias[ccol];
            float2 o0 = make_float2(acc[im][in][0] + b01.x, acc[im][in][1] + b01.y);
            float2 o1 = make_float2(acc[im][in][2] + b01.x, acc[im][in][3] + b01.y);
            *(float2*)&C[(size_t)r * N + ccol]       = o0;
            *(float2*)&C[(size_t)(r + 8) * N + ccol] = o1;
        }
    }
}

// ---------------- tensor-core flash attention (split bf16) ----------------
#define VPAD 72

__global__ __launch_bounds__(256, 1)
void attn_mma(const __nv_bfloat16* __restrict__ qh, const __nv_bfloat16* __restrict__ ql,
              const __nv_bfloat16* __restrict__ kh, const __nv_bfloat16* __restrict__ kl,
              const __nv_bfloat16* __restrict__ vth, const __nv_bfloat16* __restrict__ vtl,
              const int* __restrict__ mask, float* __restrict__ out)
{
    __shared__ __nv_bfloat16 sKh[64][VPAD], sKl[64][VPAD];
    __shared__ __nv_bfloat16 sVh[64][VPAD], sVl[64][VPAD];   // Vt: [hd][kv]
    __shared__ int sMask[64];

    const int tid = threadIdx.x, wid = tid >> 5, lane = tid & 31;
    const int g = lane >> 2, tig = lane & 3;
    const int qt = blockIdx.x, bh = blockIdx.y;
    const int b = bh >> 4, h = bh & 15;
    const int q0 = qt * 128;
    const int wrow = q0 + wid * 16;
    const float scale = 0.125f;

    uint32_t aqh[4][4], aql[4][4];
    {
        const __nv_bfloat16* qb = qh + (size_t)(b * Ss + wrow) * Ee + h * 64;
        const __nv_bfloat16* qbl = ql + (size_t)(b * Ss + wrow) * Ee + h * 64;
#pragma unroll
        for (int s = 0; s < 4; s++) {
            int k0 = s * 16 + 2 * tig;
            aqh[s][0] = *(const uint32_t*)&qb [(size_t)(g    ) * Ee + k0];
            aqh[s][1] = *(const uint32_t*)&qb [(size_t)(g + 8) * Ee + k0];
            aqh[s][2] = *(const uint32_t*)&qb [(size_t)(g    ) * Ee + k0 + 8];
            aqh[s][3] = *(const uint32_t*)&qb [(size_t)(g + 8) * Ee + k0 + 8];
            aql[s][0] = *(const uint32_t*)&qbl[(size_t)(g    ) * Ee + k0];
            aql[s][1] = *(const uint32_t*)&qbl[(size_t)(g + 8) * Ee + k0];
            aql[s][2] = *(const uint32_t*)&qbl[(size_t)(g    ) * Ee + k0 + 8];
            aql[s][3] = *(const uint32_t*)&qbl[(size_t)(g + 8) * Ee + k0 + 8];
        }
    }

    float m0 = -1e30f, m1 = -1e30f, l0 = 0.0f, l1 = 0.0f;
    float o[8][4];
#pragma unroll
    for (int t = 0; t < 8; t++)
#pragma unroll
        for (int e = 0; e < 4; e++) o[t][e] = 0.0f;

    const int row0 = wrow + g, row1 = wrow + 8 + g;
    const int ntiles = (qt + 1) * 2;

    for (int j = 0; j < ntiles; j++) {
        const int kv0 = j * 64;
        __syncthreads();
        for (int i = tid; i < 512; i += 256) {
            int row = i >> 3, seg = (i & 7) * 8;
            *(uint4*)&sKh[row][seg] = *(const uint4*)&kh[(size_t)(b * Ss + kv0 + row) * Ee + h * 64 + seg];
            *(uint4*)&sKl[row][seg] = *(const uint4*)&kl[(size_t)(b * Ss + kv0 + row) * Ee + h * 64 + seg];
            *(uint4*)&sVh[row][seg] = *(const uint4*)&vth[(size_t)(b * Ee + h * 64 + row) * Ss + kv0 + seg];
            *(uint4*)&sVl[row][seg] = *(const uint4*)&vtl[(size_t)(b * Ee + h * 64 + row) * Ss + kv0 + seg];
        }
        if (tid < 64) sMask[tid] = mask[b * Ss + kv0 + tid];
        __syncthreads();

        float c[8][4];
#pragma unroll
        for (int t = 0; t < 8; t++)
#pragma unroll
            for (int e = 0; e < 4; e++) c[t][e] = 0.0f;

#pragma unroll
        for (int s = 0; s < 4; s++) {
            int k0 = s * 16 + 2 * tig;
#pragma unroll
            for (int t = 0; t < 8; t++) {
                uint32_t bhf[2], blf[2];
                bhf[0] = *(const uint32_t*)&sKh[t * 8 + g][k0];
                bhf[1] = *(const uint32_t*)&sKh[t * 8 + g][k0 + 8];
                blf[0] = *(const uint32_t*)&sKl[t * 8 + g][k0];
                blf[1] = *(const uint32_t*)&sKl[t * 8 + g][k0 + 8];
                mma16816(c[t], aqh[s], bhf);
                mma16816(c[t], aqh[s], blf);
                mma16816(c[t], aql[s], bhf);
            }
        }

#pragma unroll
        for (int t = 0; t < 8; t++) {
            int lc0 = t * 8 + 2 * tig;
            int col0 = kv0 + lc0, col1 = col0 + 1;
            bool v0 = sMask[lc0] != 0, v1 = sMask[lc0 + 1] != 0;
            c[t][0] = (v0 && col0 <= row0) ? c[t][0] * scale : -1e30f;
            c[t][1] = (v1 && col1 <= row0) ? c[t][1] * scale : -1e30f;
            c[t][2] = (v0 && col0 <= row1) ? c[t][2] * scale : -1e30f;
            c[t][3] = (v1 && col1 <= row1) ? c[t][3] * scale : -1e30f;
        }

        float ml0 = -1e30f, ml1 = -1e30f;
#pragma unroll
        for (int t = 0; t < 8; t++) {
            ml0 = fmaxf(ml0, fmaxf(c[t][0], c[t][1]));
            ml1 = fmaxf(ml1, fmaxf(c[t][2], c[t][3]));
        }
        ml0 = fmaxf(ml0, __shfl_xor_sync(0xffffffffu, ml0, 1));
        ml0 = fmaxf(ml0, __shfl_xor_sync(0xffffffffu, ml0, 2));
        ml1 = fmaxf(ml1, __shfl_xor_sync(0xffffffffu, ml1, 1));
        ml1 = fmaxf(ml1, __shfl_xor_sync(0xffffffffu, ml1, 2));

        float mn0 = fmaxf(m0, ml0), mn1 = fmaxf(m1, ml1);
        float alpha0 = __expf(m0 - mn0), alpha1 = __expf(m1 - mn1);
        m0 = mn0; m1 = mn1;

        float rs0 = 0.0f, rs1 = 0.0f;
#pragma unroll
        for (int t = 0; t < 8; t++) {
            c[t][0] = __expf(c[t][0] - m0); rs0 += c[t][0];
            c[t][1] = __expf(c[t][1] - m0); rs0 += c[t][1];
            c[t][2] = __expf(c[t][2] - m1); rs1 += c[t][2];
            c[t][3] = __expf(c[t][3] - m1); rs1 += c[t][3];
        }
        rs0 += __shfl_xor_sync(0xffffffffu, rs0, 1);
        rs0 += __shfl_xor_sync(0xffffffffu, rs0, 2);
        rs1 += __shfl_xor_sync(0xffffffffu, rs1, 1);
        rs1 += __shfl_xor_sync(0xffffffffu, rs1, 2);

        l0 = l0 * alpha0 + rs0;
        l1 = l1 * alpha1 + rs1;
#pragma unroll
        for (int t = 0; t < 8; t++) {
            o[t][0] *= alpha0; o[t][1] *= alpha0;
            o[t][2] *= alpha1; o[t][3] *= alpha1;
        }

#pragma unroll
        for (int s = 0; s < 4; s++) {
            uint32_t aph[4], apl[4];
            splitpack(c[2 * s][0],     c[2 * s][1],     aph[0], apl[0]);
            splitpack(c[2 * s][2],     c[2 * s][3],     aph[1], apl[1]);
            splitpack(c[2 * s + 1][0], c[2 * s + 1][1], aph[2], apl[2]);
            splitpack(c[2 * s + 1][2], c[2 * s + 1][3], aph[3], apl[3]);
            int k0 = s * 16 + 2 * tig;
#pragma unroll
            for (int t = 0; t < 8; t++) {
                uint32_t bvh[2], bvl[2];
                bvh[0] = *(const uint32_t*)&sVh[t * 8 + g][k0];
                bvh[1] = *(const uint32_t*)&sVh[t * 8 + g][k0 + 8];
                bvl[0] = *(const uint32_t*)&sVl[t * 8 + g][k0];
                bvl[1] = *(const uint32_t*)&sVl[t * 8 + g][k0 + 8];
                mma16816(o[t], aph, bvh);
                mma16816(o[t], aph, bvl);
                mma16816(o[t], apl, bvh);
            }
        }
    }

    float inv0 = 1.0f / l0, inv1 = 1.0f / l1;
    float* out0 = out + (size_t)(b * Ss + row0) * Ee + h * 64;
    float* out1 = out + (size_t)(b * Ss + row1) * Ee + h * 64;
#pragma unroll
    for (int t = 0; t < 8; t++) {
        int cc = t * 8 + 2 * tig;
        *(float2*)&out0[cc] = make_float2(o[t][0] * inv0, o[t][1] * inv0);
        *(float2*)&out1[cc] = make_float2(o[t][2] * inv1, o[t][3] * inv1);
    }
}

// ---------------- launch ----------------
extern "C" void kernel_launch(void* const* d_in, const int* in_sizes, int n_in,
                              void* d_out, int out_size)
{
    const float* X     = (const float*)d_in[0];
    const int*   mask  = (const int*)  d_in[1];
    const float* Wqkv  = (const float*)d_in[2];
    const float* bqkv  = (const float*)d_in[3];
    const float* Wproj = (const float*)d_in[4];
    const float* bproj = (const float*)d_in[5];
    float* out = (float*)d_out;

    float *qkv, *attn;
    __nv_bfloat16 *xhi, *xlo, *wqh, *wql, *wph, *wpl, *ahi, *alo, *vth, *vtl;
    cudaGetSymbolAddress((void**)&qkv,  g_qkv);
    cudaGetSymbolAddress((void**)&attn, g_attn);
    cudaGetSymbolAddress((void**)&xhi,  g_xhi);
    cudaGetSymbolAddress((void**)&xlo,  g_xlo);
    cudaGetSymbolAddress((void**)&wqh,  g_wqh);
    cudaGetSymbolAddress((void**)&wql,  g_wql);
    cudaGetSymbolAddress((void**)&wph,  g_wph);
    cudaGetSymbolAddress((void**)&wpl,  g_wpl);
    cudaGetSymbolAddress((void**)&ahi,  g_ahi);
    cudaGetSymbolAddress((void**)&alo,  g_alo);
    cudaGetSymbolAddress((void**)&vth,  g_vth);
    cudaGetSymbolAddress((void**)&vtl,  g_vtl);

    cudaFuncSetAttribute(gemm_mma, cudaFuncAttributeMaxDynamicSharedMemorySize, GEMM_SMEM);

    // prep: split X, transpose+split weights
    split_hi_lo<<<(MTOT * Ee) / 4 / 256, 256>>>(X, xhi, xlo, MTOT * Ee);
    {
        dim3 blk(32, 8);
        transpose_split<<<dim3(E3 / 32, Kdim / 32), blk>>>(Wqkv, wqh, wql, Kdim, E3);
        transpose_split<<<dim3(Ee / 32, Kdim / 32), blk>>>(Wproj, wph, wpl, Kdim, Ee);
    }

    // 1) QKV = X @ Wqkv + b  (tensor cores)
    gemm_mma<<<dim3(E3 / 128, MTOT / 128), 256, GEMM_SMEM>>>(xhi, xlo, wqh, wql, bqkv, qkv, E3);

    // 2) attention prep: split Q/K (reuse xhi/xlo as Q, ahi/alo as K), transpose+split V
    split_qk<<<(MTOT * Ee) / 4 / 256, 256>>>(qkv, xhi, xlo, ahi, alo);
    {
        dim3 blk(32, 8);
        transpose_v_split<<<dim3(Ee / 32, Ss / 32, Bb), blk>>>(qkv, vth, vtl);
    }

    // 3) tensor-core flash attention
    attn_mma<<<dim3(Ss / 128, Bb * Hh), 256>>>(xhi, xlo, ahi, alo, vth, vtl, mask, attn);

    // 4) out = attn @ Wproj + b  (tensor cores; reuse ahi/alo for attn split)
    split_hi_lo<<<(MTOT * Ee) / 4 / 256, 256>>>(attn, ahi, alo, MTOT * Ee);
    gemm_mma<<<dim3(Ee / 128, MTOT / 128), 256, GEMM_SMEM>>>(ahi, alo, wph, wpl, bproj, out, Ee);
}

// round 6
// speedup vs baseline: 1.1728x; 1.1728x over previous
#include <cuda_runtime.h>
#include <cuda_bf16.h>
#include <cstdint>
#include <math.h>

// ---------------- problem constants ----------------
#define Bb   4
#define Ss   1024
#define Ee   1024
#define Hh   16
#define HDs  64
#define MTOT 4096      // B*S
#define E3   3072      // 3*E
#define Kdim 1024

// ---------------- scratch (device globals) ----------------
__device__ float          g_qkv [MTOT * E3];     // [B*S, 3E] fp32
__device__ float          g_attn[MTOT * Ee];     // [B*S, E]  fp32
__device__ __nv_bfloat16  g_xhi [MTOT * Ee];     // X split; reused as Q_hi after QKV
__device__ __nv_bfloat16  g_xlo [MTOT * Ee];
__device__ __nv_bfloat16  g_wqh [E3 * Ee];       // Wqkv^T
__device__ __nv_bfloat16  g_wql [E3 * Ee];
__device__ __nv_bfloat16  g_wph [Ee * Ee];       // Wproj^T
__device__ __nv_bfloat16  g_wpl [Ee * Ee];
__device__ __nv_bfloat16  g_ahi [MTOT * Ee];     // K_hi, then attn_hi for proj
__device__ __nv_bfloat16  g_alo [MTOT * Ee];
__device__ __nv_bfloat16  g_vth [Bb * Ee * Ss];  // V^T split
__device__ __nv_bfloat16  g_vtl [Bb * Ee * Ss];

// ---------------- helpers ----------------
__device__ __forceinline__ void mma16816(float* c, const uint32_t* a, const uint32_t* b)
{
    asm volatile(
        "mma.sync.aligned.m16n8k16.row.col.f32.bf16.bf16.f32 "
        "{%0,%1,%2,%3}, {%4,%5,%6,%7}, {%8,%9}, {%0,%1,%2,%3};"
        : "+f"(c[0]), "+f"(c[1]), "+f"(c[2]), "+f"(c[3])
        : "r"(a[0]), "r"(a[1]), "r"(a[2]), "r"(a[3]), "r"(b[0]), "r"(b[1]));
}
__device__ __forceinline__ void cp16(uint32_t saddr, const void* g)
{
    asm volatile("cp.async.cg.shared.global [%0], [%1], 16;"
                 :: "r"(saddr), "l"(g));
}
__device__ __forceinline__ uint32_t smem_u32(const void* p) {
    uint32_t a;
    asm("{ .reg .u64 t; cvta.to.shared.u64 t, %1; cvt.u32.u64 %0, t; }"
        : "=r"(a) : "l"(p));
    return a;
}
__device__ __forceinline__ void splitpack(float f0, float f1, uint32_t& hi, uint32_t& lo)
{
    __nv_bfloat16 h0 = __float2bfloat16_rn(f0);
    __nv_bfloat16 h1 = __float2bfloat16_rn(f1);
    __nv_bfloat162 hp = __halves2bfloat162(h0, h1);
    hi = *(uint32_t*)&hp;
    __nv_bfloat162 lp = __floats2bfloat162_rn(f0 - __bfloat162float(h0),
                                              f1 - __bfloat162float(h1));
    lo = *(uint32_t*)&lp;
}

// ---------------- split fp32 -> (bf16 hi, bf16 lo) ----------------
__global__ __launch_bounds__(256)
void split_hi_lo(const float* __restrict__ x,
                 __nv_bfloat16* __restrict__ hi,
                 __nv_bfloat16* __restrict__ lo, int n)
{
    int i = (blockIdx.x * 256 + threadIdx.x) * 4;
    if (i >= n) return;
    float4 v = *(const float4*)(x + i);
    __nv_bfloat16 h[4], l[4];
    float vv[4] = {v.x, v.y, v.z, v.w};
#pragma unroll
    for (int q = 0; q < 4; q++) {
        h[q] = __float2bfloat16_rn(vv[q]);
        l[q] = __float2bfloat16_rn(vv[q] - __bfloat162float(h[q]));
    }
    *(uint2*)(hi + i) = *(uint2*)h;
    *(uint2*)(lo + i) = *(uint2*)l;
}

// ---------------- split Q and K sections of qkv ----------------
__global__ __launch_bounds__(256)
void split_qk(const float* __restrict__ qkv,
              __nv_bfloat16* __restrict__ qh, __nv_bfloat16* __restrict__ ql,
              __nv_bfloat16* __restrict__ kh, __nv_bfloat16* __restrict__ kl)
{
    int t = blockIdx.x * 256 + threadIdx.x;
    int i4 = t * 4;
    if (i4 >= MTOT * Ee) return;
    int row = i4 >> 10, col = i4 & 1023;
    float4 q = *(const float4*)&qkv[(size_t)row * E3 + col];
    float4 k = *(const float4*)&qkv[(size_t)row * E3 + Ee + col];
    float qv[4] = {q.x, q.y, q.z, q.w}, kv[4] = {k.x, k.y, k.z, k.w};
    __nv_bfloat16 qhh[4], qll[4], khh[4], kll[4];
#pragma unroll
    for (int e = 0; e < 4; e++) {
        qhh[e] = __float2bfloat16_rn(qv[e]);
        qll[e] = __float2bfloat16_rn(qv[e] - __bfloat162float(qhh[e]));
        khh[e] = __float2bfloat16_rn(kv[e]);
        kll[e] = __float2bfloat16_rn(kv[e] - __bfloat162float(khh[e]));
    }
    *(uint2*)(qh + i4) = *(uint2*)qhh;
    *(uint2*)(ql + i4) = *(uint2*)qll;
    *(uint2*)(kh + i4) = *(uint2*)khh;
    *(uint2*)(kl + i4) = *(uint2*)kll;
}

// ---------------- transpose+split V ----------------
__global__ __launch_bounds__(256)
void transpose_v_split(const float* __restrict__ qkv,
                       __nv_bfloat16* __restrict__ vth, __nv_bfloat16* __restrict__ vtl)
{
    __shared__ float tile[32][33];
    int c0 = blockIdx.x * 32;
    int s0 = blockIdx.y * 32;
    int b  = blockIdx.z;
    int tx = threadIdx.x, ty = threadIdx.y;
#pragma unroll
    for (int i = 0; i < 32; i += 8)
        tile[ty + i][tx] = qkv[(size_t)(b * Ss + s0 + ty + i) * E3 + 2 * Ee + c0 + tx];
    __syncthreads();
#pragma unroll
    for (int i = 0; i < 32; i += 8) {
        int ccol = c0 + ty + i, srow = s0 + tx;
        float v = tile[tx][ty + i];
        __nv_bfloat16 h = __float2bfloat16_rn(v);
        vth[(size_t)(b * Ee + ccol) * Ss + srow] = h;
        vtl[(size_t)(b * Ee + ccol) * Ss + srow] = __float2bfloat16_rn(v - __bfloat162float(h));
    }
}

// ---------------- transpose + split W ----------------
__global__ __launch_bounds__(256)
void transpose_split(const float* __restrict__ W,
                     __nv_bfloat16* __restrict__ Thi,
                     __nv_bfloat16* __restrict__ Tlo, int K, int N)
{
    __shared__ float tile[32][33];
    int n0 = blockIdx.x * 32, k0 = blockIdx.y * 32;
    int tx = threadIdx.x, ty = threadIdx.y;
#pragma unroll
    for (int i = 0; i < 32; i += 8)
        tile[ty + i][tx] = W[(size_t)(k0 + ty + i) * N + n0 + tx];
    __syncthreads();
#pragma unroll
    for (int i = 0; i < 32; i += 8) {
        int n = n0 + ty + i, k = k0 + tx;
        float v = tile[tx][ty + i];
        __nv_bfloat16 h = __float2bfloat16_rn(v);
        Thi[(size_t)n * K + k] = h;
        Tlo[(size_t)n * K + k] = __float2bfloat16_rn(v - __bfloat162float(h));
    }
}

// ---------------- split-bf16 GEMM: 4 warps, warp tile 64x64, BK=32 ----------------
#define GBK      32
#define GSTRIDE  40                        // 32 elems + 8 pad (80 B rows, 16B-aligned)
#define ARR_B    (128 * GSTRIDE * 2)       // 10240 B
#define STAGE_B  (4 * ARR_B)               // 40960 B (Ah, Al, Bh, Bl)
#define GEMM_SMEM (2 * STAGE_B)            // 81920 B

__global__ __launch_bounds__(128, 2)
void gemm_mma(const __nv_bfloat16* __restrict__ Ahi, const __nv_bfloat16* __restrict__ Alo,
              const __nv_bfloat16* __restrict__ Bhi, const __nv_bfloat16* __restrict__ Blo,
              const float* __restrict__ bias, float* __restrict__ C, int N)
{
    extern __shared__ char smem[];
    const uint32_t sb = smem_u32(smem);
    const int tid  = threadIdx.x;
    const int wid  = tid >> 5, lane = tid & 31;
    const int wm   = wid >> 1, wn = wid & 1;          // warp grid 2 x 2, tile 64x64
    const int g    = lane >> 2, tig = lane & 3;
    const int bm   = blockIdx.y * 128, bn = blockIdx.x * 128;
    const int NC   = Kdim / GBK;                      // 32 chunks

    float acc[4][8][4];
#pragma unroll
    for (int im = 0; im < 4; im++)
#pragma unroll
        for (int in = 0; in < 8; in++)
#pragma unroll
            for (int q = 0; q < 4; q++) acc[im][in][q] = 0.0f;

    auto prefetch = [&](int c, int st) {
#pragma unroll
        for (int i = 0; i < 16; i++) {
            int idx = tid + i * 128;        // 0..2047 16B-units
            int arr = idx >> 9;             // 0:Ah 1:Al 2:Bh 3:Bl
            int e   = idx & 511;
            int row = e >> 2;               // 0..127
            int seg = e & 3;                // 16B segment along k
            const __nv_bfloat16* gp;
            size_t koff = (size_t)c * GBK + seg * 8;
            if      (arr == 0) gp = Ahi + (size_t)(bm + row) * Kdim + koff;
            else if (arr == 1) gp = Alo + (size_t)(bm + row) * Kdim + koff;
            else if (arr == 2) gp = Bhi + (size_t)(bn + row) * Kdim + koff;
            else               gp = Blo + (size_t)(bn + row) * Kdim + koff;
            uint32_t sa = sb + st * STAGE_B + arr * ARR_B + (row * GSTRIDE + seg * 8) * 2;
            cp16(sa, gp);
        }
        asm volatile("cp.async.commit_group;");
    };

    prefetch(0, 0);

    for (int c = 0; c < NC; c++) {
        const int st = c & 1;
        if (c + 1 < NC) {
            prefetch(c + 1, (c + 1) & 1);
            asm volatile("cp.async.wait_group 1;");
        } else {
            asm volatile("cp.async.wait_group 0;");
        }
        __syncthreads();

        const __nv_bfloat16* sAh = (const __nv_bfloat16*)(smem + st * STAGE_B);
        const __nv_bfloat16* sAl = (const __nv_bfloat16*)(smem + st * STAGE_B + ARR_B);
        const __nv_bfloat16* sBh = (const __nv_bfloat16*)(smem + st * STAGE_B + 2 * ARR_B);
        const __nv_bfloat16* sBl = (const __nv_bfloat16*)(smem + st * STAGE_B + 3 * ARR_B);

#pragma unroll
        for (int kk = 0; kk < GBK; kk += 16) {
            uint32_t a[4][4], bh[8][2], bl[8][2];
            // A-hi fragments (64 rows)
#pragma unroll
            for (int im = 0; im < 4; im++) {
                int r = wm * 64 + im * 16 + g;
                a[im][0] = *(const uint32_t*)&sAh[(r    ) * GSTRIDE + kk + 2 * tig];
                a[im][1] = *(const uint32_t*)&sAh[(r + 8) * GSTRIDE + kk + 2 * tig];
                a[im][2] = *(const uint32_t*)&sAh[(r    ) * GSTRIDE + kk + 2 * tig + 8];
                a[im][3] = *(const uint32_t*)&sAh[(r + 8) * GSTRIDE + kk + 2 * tig + 8];
            }
            // B-hi fragments (64 cols), held across passes
#pragma unroll
            for (int in = 0; in < 8; in++) {
                int n0 = wn * 64 + in * 8 + g;
                bh[in][0] = *(const uint32_t*)&sBh[n0 * GSTRIDE + kk + 2 * tig];
                bh[in][1] = *(const uint32_t*)&sBh[n0 * GSTRIDE + kk + 2 * tig + 8];
            }
            // pass 1: Ah * Bh
#pragma unroll
            for (int im = 0; im < 4; im++)
#pragma unroll
                for (int in = 0; in < 8; in++)
                    mma16816(acc[im][in], a[im], bh[in]);
            // B-lo fragments
#pragma unroll
            for (int in = 0; in < 8; in++) {
                int n0 = wn * 64 + in * 8 + g;
                bl[in][0] = *(const uint32_t*)&sBl[n0 * GSTRIDE + kk + 2 * tig];
                bl[in][1] = *(const uint32_t*)&sBl[n0 * GSTRIDE + kk + 2 * tig + 8];
            }
            // pass 2: Ah * Bl
#pragma unroll
            for (int im = 0; im < 4; im++)
#pragma unroll
                for (int in = 0; in < 8; in++)
                    mma16816(acc[im][in], a[im], bl[in]);
            // A-lo fragments (overwrite a)
#pragma unroll
            for (int im = 0; im < 4; im++) {
                int r = wm * 64 + im * 16 + g;
                a[im][0] = *(const uint32_t*)&sAl[(r    ) * GSTRIDE + kk + 2 * tig];
                a[im][1] = *(const uint32_t*)&sAl[(r + 8) * GSTRIDE + kk + 2 * tig];
                a[im][2] = *(const uint32_t*)&sAl[(r    ) * GSTRIDE + kk + 2 * tig + 8];
                a[im][3] = *(const uint32_t*)&sAl[(r + 8) * GSTRIDE + kk + 2 * tig + 8];
            }
            // pass 3: Al * Bh
#pragma unroll
            for (int im = 0; im < 4; im++)
#pragma unroll
                for (int in = 0; in < 8; in++)
                    mma16816(acc[im][in], a[im], bh[in]);
        }
        __syncthreads();
    }

    // epilogue: acc -> C + bias
#pragma unroll
    for (int im = 0; im < 4; im++) {
        int r = bm + wm * 64 + im * 16 + g;
#pragma unroll
        for (int in = 0; in < 8; in++) {
            int ccol = bn + wn * 64 + in * 8 + 2 * tig;
            float2 b01 = *(const float2*)&bias[ccol];
            float2 o0 = make_float2(acc[im][in][0] + b01.x, acc[im][in][1] + b01.y);
            float2 o1 = make_float2(acc[im][in][2] + b01.x, acc[im][in][3] + b01.y);
            *(float2*)&C[(size_t)r * N + ccol]       = o0;
            *(float2*)&C[(size_t)(r + 8) * N + ccol] = o1;
        }
    }
}

// ---------------- tensor-core flash attention (split bf16, unchanged from R4) ----------------
#define VPAD 72

__global__ __launch_bounds__(256, 1)
void attn_mma(const __nv_bfloat16* __restrict__ qh, const __nv_bfloat16* __restrict__ ql,
              const __nv_bfloat16* __restrict__ kh, const __nv_bfloat16* __restrict__ kl,
              const __nv_bfloat16* __restrict__ vth, const __nv_bfloat16* __restrict__ vtl,
              const int* __restrict__ mask, float* __restrict__ out)
{
    __shared__ __nv_bfloat16 sKh[64][VPAD], sKl[64][VPAD];
    __shared__ __nv_bfloat16 sVh[64][VPAD], sVl[64][VPAD];
    __shared__ int sMask[64];

    const int tid = threadIdx.x, wid = tid >> 5, lane = tid & 31;
    const int g = lane >> 2, tig = lane & 3;
    const int qt = blockIdx.x, bh = blockIdx.y;
    const int b = bh >> 4, h = bh & 15;
    const int q0 = qt * 128;
    const int wrow = q0 + wid * 16;
    const float scale = 0.125f;

    uint32_t aqh[4][4], aql[4][4];
    {
        const __nv_bfloat16* qb = qh + (size_t)(b * Ss + wrow) * Ee + h * 64;
        const __nv_bfloat16* qbl = ql + (size_t)(b * Ss + wrow) * Ee + h * 64;
#pragma unroll
        for (int s = 0; s < 4; s++) {
            int k0 = s * 16 + 2 * tig;
            aqh[s][0] = *(const uint32_t*)&qb [(size_t)(g    ) * Ee + k0];
            aqh[s][1] = *(const uint32_t*)&qb [(size_t)(g + 8) * Ee + k0];
            aqh[s][2] = *(const uint32_t*)&qb [(size_t)(g    ) * Ee + k0 + 8];
            aqh[s][3] = *(const uint32_t*)&qb [(size_t)(g + 8) * Ee + k0 + 8];
            aql[s][0] = *(const uint32_t*)&qbl[(size_t)(g    ) * Ee + k0];
            aql[s][1] = *(const uint32_t*)&qbl[(size_t)(g + 8) * Ee + k0];
            aql[s][2] = *(const uint32_t*)&qbl[(size_t)(g    ) * Ee + k0 + 8];
            aql[s][3] = *(const uint32_t*)&qbl[(size_t)(g + 8) * Ee + k0 + 8];
        }
    }

    float m0 = -1e30f, m1 = -1e30f, l0 = 0.0f, l1 = 0.0f;
    float o[8][4];
#pragma unroll
    for (int t = 0; t < 8; t++)
#pragma unroll
        for (int e = 0; e < 4; e++) o[t][e] = 0.0f;

    const int row0 = wrow + g, row1 = wrow + 8 + g;
    const int ntiles = (qt + 1) * 2;

    for (int j = 0; j < ntiles; j++) {
        const int kv0 = j * 64;
        __syncthreads();
        for (int i = tid; i < 512; i += 256) {
            int row = i >> 3, seg = (i & 7) * 8;
            *(uint4*)&sKh[row][seg] = *(const uint4*)&kh[(size_t)(b * Ss + kv0 + row) * Ee + h * 64 + seg];
            *(uint4*)&sKl[row][seg] = *(const uint4*)&kl[(size_t)(b * Ss + kv0 + row) * Ee + h * 64 + seg];
            *(uint4*)&sVh[row][seg] = *(const uint4*)&vth[(size_t)(b * Ee + h * 64 + row) * Ss + kv0 + seg];
            *(uint4*)&sVl[row][seg] = *(const uint4*)&vtl[(size_t)(b * Ee + h * 64 + row) * Ss + kv0 + seg];
        }
        if (tid < 64) sMask[tid] = mask[b * Ss + kv0 + tid];
        __syncthreads();

        float c[8][4];
#pragma unroll
        for (int t = 0; t < 8; t++)
#pragma unroll
            for (int e = 0; e < 4; e++) c[t][e] = 0.0f;

#pragma unroll
        for (int s = 0; s < 4; s++) {
            int k0 = s * 16 + 2 * tig;
#pragma unroll
            for (int t = 0; t < 8; t++) {
                uint32_t bhf[2], blf[2];
                bhf[0] = *(const uint32_t*)&sKh[t * 8 + g][k0];
                bhf[1] = *(const uint32_t*)&sKh[t * 8 + g][k0 + 8];
                blf[0] = *(const uint32_t*)&sKl[t * 8 + g][k0];
                blf[1] = *(const uint32_t*)&sKl[t * 8 + g][k0 + 8];
                mma16816(c[t], aqh[s], bhf);
                mma16816(c[t], aqh[s], blf);
                mma16816(c[t], aql[s], bhf);
            }
        }

#pragma unroll
        for (int t = 0; t < 8; t++) {
            int lc0 = t * 8 + 2 * tig;
            int col0 = kv0 + lc0, col1 = col0 + 1;
            bool v0 = sMask[lc0] != 0, v1 = sMask[lc0 + 1] != 0;
            c[t][0] = (v0 && col0 <= row0) ? c[t][0] * scale : -1e30f;
            c[t][1] = (v1 && col1 <= row0) ? c[t][1] * scale : -1e30f;
            c[t][2] = (v0 && col0 <= row1) ? c[t][2] * scale : -1e30f;
            c[t][3] = (v1 && col1 <= row1) ? c[t][3] * scale : -1e30f;
        }

        float ml0 = -1e30f, ml1 = -1e30f;
#pragma unroll
        for (int t = 0; t < 8; t++) {
            ml0 = fmaxf(ml0, fmaxf(c[t][0], c[t][1]));
            ml1 = fmaxf(ml1, fmaxf(c[t][2], c[t][3]));
        }
        ml0 = fmaxf(ml0, __shfl_xor_sync(0xffffffffu, ml0, 1));
        ml0 = fmaxf(ml0, __shfl_xor_sync(0xffffffffu, ml0, 2));
        ml1 = fmaxf(ml1, __shfl_xor_sync(0xffffffffu, ml1, 1));
        ml1 = fmaxf(ml1, __shfl_xor_sync(0xffffffffu, ml1, 2));

        float mn0 = fmaxf(m0, ml0), mn1 = fmaxf(m1, ml1);
        float alpha0 = __expf(m0 - mn0), alpha1 = __expf(m1 - mn1);
        m0 = mn0; m1 = mn1;

        float rs0 = 0.0f, rs1 = 0.0f;
#pragma unroll
        for (int t = 0; t < 8; t++) {
            c[t][0] = __expf(c[t][0] - m0); rs0 += c[t][0];
            c[t][1] = __expf(c[t][1] - m0); rs0 += c[t][1];
            c[t][2] = __expf(c[t][2] - m1); rs1 += c[t][2];
            c[t][3] = __expf(c[t][3] - m1); rs1 += c[t][3];
        }
        rs0 += __shfl_xor_sync(0xffffffffu, rs0, 1);
        rs0 += __shfl_xor_sync(0xffffffffu, rs0, 2);
        rs1 += __shfl_xor_sync(0xffffffffu, rs1, 1);
        rs1 += __shfl_xor_sync(0xffffffffu, rs1, 2);

        l0 = l0 * alpha0 + rs0;
        l1 = l1 * alpha1 + rs1;
#pragma unroll
        for (int t = 0; t < 8; t++) {
            o[t][0] *= alpha0; o[t][1] *= alpha0;
            o[t][2] *= alpha1; o[t][3] *= alpha1;
        }

#pragma unroll
        for (int s = 0; s < 4; s++) {
            uint32_t aph[4], apl[4];
            splitpack(c[2 * s][0],     c[2 * s][1],     aph[0], apl[0]);
            splitpack(c[2 * s][2],     c[2 * s][3],     aph[1], apl[1]);
            splitpack(c[2 * s + 1][0], c[2 * s + 1][1], aph[2], apl[2]);
            splitpack(c[2 * s + 1][2], c[2 * s + 1][3], aph[3], apl[3]);
            int k0 = s * 16 + 2 * tig;
#pragma unroll
            for (int t = 0; t < 8; t++) {
                uint32_t bvh[2], bvl[2];
                bvh[0] = *(const uint32_t*)&sVh[t * 8 + g][k0];
                bvh[1] = *(const uint32_t*)&sVh[t * 8 + g][k0 + 8];
                bvl[0] = *(const uint32_t*)&sVl[t * 8 + g][k0];
                bvl[1] = *(const uint32_t*)&sVl[t * 8 + g][k0 + 8];
                mma16816(o[t], aph, bvh);
                mma16816(o[t], aph, bvl);
                mma16816(o[t], apl, bvh);
            }
        }
    }

    float inv0 = 1.0f / l0, inv1 = 1.0f / l1;
    float* out0 = out + (size_t)(b * Ss + row0) * Ee + h * 64;
    float* out1 = out + (size_t)(b * Ss + row1) * Ee + h * 64;
#pragma unroll
    for (int t = 0; t < 8; t++) {
        int cc = t * 8 + 2 * tig;
        *(float2*)&out0[cc] = make_float2(o[t][0] * inv0, o[t][1] * inv0);
        *(float2*)&out1[cc] = make_float2(o[t][2] * inv1, o[t][3] * inv1);
    }
}

// ---------------- launch ----------------
extern "C" void kernel_launch(void* const* d_in, const int* in_sizes, int n_in,
                              void* d_out, int out_size)
{
    const float* X     = (const float*)d_in[0];
    const int*   mask  = (const int*)  d_in[1];
    const float* Wqkv  = (const float*)d_in[2];
    const float* bqkv  = (const float*)d_in[3];
    const float* Wproj = (const float*)d_in[4];
    const float* bproj = (const float*)d_in[5];
    float* out = (float*)d_out;

    float *qkv, *attn;
    __nv_bfloat16 *xhi, *xlo, *wqh, *wql, *wph, *wpl, *ahi, *alo, *vth, *vtl;
    cudaGetSymbolAddress((void**)&qkv,  g_qkv);
    cudaGetSymbolAddress((void**)&attn, g_attn);
    cudaGetSymbolAddress((void**)&xhi,  g_xhi);
    cudaGetSymbolAddress((void**)&xlo,  g_xlo);
    cudaGetSymbolAddress((void**)&wqh,  g_wqh);
    cudaGetSymbolAddress((void**)&wql,  g_wql);
    cudaGetSymbolAddress((void**)&wph,  g_wph);
    cudaGetSymbolAddress((void**)&wpl,  g_wpl);
    cudaGetSymbolAddress((void**)&ahi,  g_ahi);
    cudaGetSymbolAddress((void**)&alo,  g_alo);
    cudaGetSymbolAddress((void**)&vth,  g_vth);
    cudaGetSymbolAddress((void**)&vtl,  g_vtl);

    cudaFuncSetAttribute(gemm_mma, cudaFuncAttributeMaxDynamicSharedMemorySize, GEMM_SMEM);

    // prep: split X, transpose+split weights
    split_hi_lo<<<(MTOT * Ee) / 4 / 256, 256>>>(X, xhi, xlo, MTOT * Ee);
    {
        dim3 blk(32, 8);
        transpose_split<<<dim3(E3 / 32, Kdim / 32), blk>>>(Wqkv, wqh, wql, Kdim, E3);
        transpose_split<<<dim3(Ee / 32, Kdim / 32), blk>>>(Wproj, wph, wpl, Kdim, Ee);
    }

    // 1) QKV = X @ Wqkv + b  (tensor cores)
    gemm_mma<<<dim3(E3 / 128, MTOT / 128), 128, GEMM_SMEM>>>(xhi, xlo, wqh, wql, bqkv, qkv, E3);

    // 2) attention prep
    split_qk<<<(MTOT * Ee) / 4 / 256, 256>>>(qkv, xhi, xlo, ahi, alo);
    {
        dim3 blk(32, 8);
        transpose_v_split<<<dim3(Ee / 32, Ss / 32, Bb), blk>>>(qkv, vth, vtl);
    }

    // 3) tensor-core flash attention
    attn_mma<<<dim3(Ss / 128, Bb * Hh), 256>>>(xhi, xlo, ahi, alo, vth, vtl, mask, attn);

    // 4) out = attn @ Wproj + b
    split_hi_lo<<<(MTOT * Ee) / 4 / 256, 256>>>(attn, ahi, alo, MTOT * Ee);
    gemm_mma<<<dim3(Ee / 128, MTOT / 128), 128, GEMM_SMEM>>>(ahi, alo, wph, wpl, bproj, out, Ee);
}

// round 7
// speedup vs baseline: 1.2026x; 1.0254x over previous
#include <cuda_runtime.h>
#include <cuda_bf16.h>
#include <cstdint>
#include <math.h>

// ---------------- problem constants ----------------
#define Bb   4
#define Ss   1024
#define Ee   1024
#define Hh   16
#define HDs  64
#define MTOT 4096      // B*S
#define E3   3072      // 3*E
#define Kdim 1024

// ---------------- scratch (device globals) ----------------
__device__ float          g_qkv [MTOT * E3];     // [B*S, 3E] fp32
__device__ __nv_bfloat16  g_xhi [MTOT * Ee];     // X split; reused as Q_hi after QKV
__device__ __nv_bfloat16  g_xlo [MTOT * Ee];
__device__ __nv_bfloat16  g_wqh [E3 * Ee];       // Wqkv^T
__device__ __nv_bfloat16  g_wql [E3 * Ee];
__device__ __nv_bfloat16  g_wph [Ee * Ee];       // Wproj^T
__device__ __nv_bfloat16  g_wpl [Ee * Ee];
__device__ __nv_bfloat16  g_ahi [MTOT * Ee];     // K_hi
__device__ __nv_bfloat16  g_alo [MTOT * Ee];     // K_lo
__device__ __nv_bfloat16  g_vth [Bb * Ee * Ss];  // V^T split
__device__ __nv_bfloat16  g_vtl [Bb * Ee * Ss];
__device__ __nv_bfloat16  g_ohi [MTOT * Ee];     // attention output split (proj input)
__device__ __nv_bfloat16  g_olo [MTOT * Ee];

// ---------------- helpers ----------------
__device__ __forceinline__ void mma16816(float* c, const uint32_t* a, const uint32_t* b)
{
    asm volatile(
        "mma.sync.aligned.m16n8k16.row.col.f32.bf16.bf16.f32 "
        "{%0,%1,%2,%3}, {%4,%5,%6,%7}, {%8,%9}, {%0,%1,%2,%3};"
        : "+f"(c[0]), "+f"(c[1]), "+f"(c[2]), "+f"(c[3])
        : "r"(a[0]), "r"(a[1]), "r"(a[2]), "r"(a[3]), "r"(b[0]), "r"(b[1]));
}
__device__ __forceinline__ void ldsm4(uint32_t& r0, uint32_t& r1, uint32_t& r2, uint32_t& r3,
                                      uint32_t addr)
{
    asm volatile("ldmatrix.sync.aligned.m8n8.x4.shared.b16 {%0,%1,%2,%3}, [%4];"
                 : "=r"(r0), "=r"(r1), "=r"(r2), "=r"(r3) : "r"(addr));
}
__device__ __forceinline__ void cp16(uint32_t saddr, const void* g)
{
    asm volatile("cp.async.cg.shared.global [%0], [%1], 16;"
                 :: "r"(saddr), "l"(g));
}
__device__ __forceinline__ uint32_t smem_u32(const void* p) {
    uint32_t a;
    asm("{ .reg .u64 t; cvta.to.shared.u64 t, %1; cvt.u32.u64 %0, t; }"
        : "=r"(a) : "l"(p));
    return a;
}
__device__ __forceinline__ void splitpack(float f0, float f1, uint32_t& hi, uint32_t& lo)
{
    __nv_bfloat16 h0 = __float2bfloat16_rn(f0);
    __nv_bfloat16 h1 = __float2bfloat16_rn(f1);
    __nv_bfloat162 hp = __halves2bfloat162(h0, h1);
    hi = *(uint32_t*)&hp;
    __nv_bfloat162 lp = __floats2bfloat162_rn(f0 - __bfloat162float(h0),
                                              f1 - __bfloat162float(h1));
    lo = *(uint32_t*)&lp;
}

// ---------------- split fp32 -> (bf16 hi, bf16 lo) ----------------
__global__ __launch_bounds__(256)
void split_hi_lo(const float* __restrict__ x,
                 __nv_bfloat16* __restrict__ hi,
                 __nv_bfloat16* __restrict__ lo, int n)
{
    int i = (blockIdx.x * 256 + threadIdx.x) * 4;
    if (i >= n) return;
    float4 v = *(const float4*)(x + i);
    __nv_bfloat16 h[4], l[4];
    float vv[4] = {v.x, v.y, v.z, v.w};
#pragma unroll
    for (int q = 0; q < 4; q++) {
        h[q] = __float2bfloat16_rn(vv[q]);
        l[q] = __float2bfloat16_rn(vv[q] - __bfloat162float(h[q]));
    }
    *(uint2*)(hi + i) = *(uint2*)h;
    *(uint2*)(lo + i) = *(uint2*)l;
}

// ---------------- split Q and K sections of qkv ----------------
__global__ __launch_bounds__(256)
void split_qk(const float* __restrict__ qkv,
              __nv_bfloat16* __restrict__ qh, __nv_bfloat16* __restrict__ ql,
              __nv_bfloat16* __restrict__ kh, __nv_bfloat16* __restrict__ kl)
{
    int t = blockIdx.x * 256 + threadIdx.x;
    int i4 = t * 4;
    if (i4 >= MTOT * Ee) return;
    int row = i4 >> 10, col = i4 & 1023;
    float4 q = *(const float4*)&qkv[(size_t)row * E3 + col];
    float4 k = *(const float4*)&qkv[(size_t)row * E3 + Ee + col];
    float qv[4] = {q.x, q.y, q.z, q.w}, kv[4] = {k.x, k.y, k.z, k.w};
    __nv_bfloat16 qhh[4], qll[4], khh[4], kll[4];
#pragma unroll
    for (int e = 0; e < 4; e++) {
        qhh[e] = __float2bfloat16_rn(qv[e]);
        qll[e] = __float2bfloat16_rn(qv[e] - __bfloat162float(qhh[e]));
        khh[e] = __float2bfloat16_rn(kv[e]);
        kll[e] = __float2bfloat16_rn(kv[e] - __bfloat162float(khh[e]));
    }
    *(uint2*)(qh + i4) = *(uint2*)qhh;
    *(uint2*)(ql + i4) = *(uint2*)qll;
    *(uint2*)(kh + i4) = *(uint2*)khh;
    *(uint2*)(kl + i4) = *(uint2*)kll;
}

// ---------------- transpose+split V ----------------
__global__ __launch_bounds__(256)
void transpose_v_split(const float* __restrict__ qkv,
                       __nv_bfloat16* __restrict__ vth, __nv_bfloat16* __restrict__ vtl)
{
    __shared__ float tile[32][33];
    int c0 = blockIdx.x * 32;
    int s0 = blockIdx.y * 32;
    int b  = blockIdx.z;
    int tx = threadIdx.x, ty = threadIdx.y;
#pragma unroll
    for (int i = 0; i < 32; i += 8)
        tile[ty + i][tx] = qkv[(size_t)(b * Ss + s0 + ty + i) * E3 + 2 * Ee + c0 + tx];
    __syncthreads();
#pragma unroll
    for (int i = 0; i < 32; i += 8) {
        int ccol = c0 + ty + i, srow = s0 + tx;
        float v = tile[tx][ty + i];
        __nv_bfloat16 h = __float2bfloat16_rn(v);
        vth[(size_t)(b * Ee + ccol) * Ss + srow] = h;
        vtl[(size_t)(b * Ee + ccol) * Ss + srow] = __float2bfloat16_rn(v - __bfloat162float(h));
    }
}

// ---------------- transpose + split W ----------------
__global__ __launch_bounds__(256)
void transpose_split(const float* __restrict__ W,
                     __nv_bfloat16* __restrict__ Thi,
                     __nv_bfloat16* __restrict__ Tlo, int K, int N)
{
    __shared__ float tile[32][33];
    int n0 = blockIdx.x * 32, k0 = blockIdx.y * 32;
    int tx = threadIdx.x, ty = threadIdx.y;
#pragma unroll
    for (int i = 0; i < 32; i += 8)
        tile[ty + i][tx] = W[(size_t)(k0 + ty + i) * N + n0 + tx];
    __syncthreads();
#pragma unroll
    for (int i = 0; i < 32; i += 8) {
        int n = n0 + ty + i, k = k0 + tx;
        float v = tile[tx][ty + i];
        __nv_bfloat16 h = __float2bfloat16_rn(v);
        Thi[(size_t)n * K + k] = h;
        Tlo[(size_t)n * K + k] = __float2bfloat16_rn(v - __bfloat162float(h));
    }
}

// ---------------- split-bf16 GEMM: 4 warps, warp tile 64x64, BK=32, ldmatrix ----------------
#define GBK      32
#define GSTRIDE  40                        // 32 elems + 8 pad (80 B rows)
#define ROWB     (GSTRIDE * 2)             // 80 bytes per row
#define ARR_B    (128 * ROWB)              // 10240 B
#define STAGE_B  (4 * ARR_B)               // 40960 B (Ah, Al, Bh, Bl)
#define GEMM_SMEM (2 * STAGE_B)            // 81920 B

__global__ __launch_bounds__(128, 2)
void gemm_mma(const __nv_bfloat16* __restrict__ Ahi, const __nv_bfloat16* __restrict__ Alo,
              const __nv_bfloat16* __restrict__ Bhi, const __nv_bfloat16* __restrict__ Blo,
              const float* __restrict__ bias, float* __restrict__ C, int N)
{
    extern __shared__ char smem[];
    const uint32_t sb = smem_u32(smem);
    const int tid  = threadIdx.x;
    const int wid  = tid >> 5, lane = tid & 31;
    const int wm   = wid >> 1, wn = wid & 1;          // warp grid 2 x 2, tile 64x64
    const int g    = lane >> 2, tig = lane & 3;
    const int bm   = blockIdx.y * 128, bn = blockIdx.x * 128;
    const int NC   = Kdim / GBK;                      // 32 chunks

    // per-lane ldmatrix offsets (bytes within one array)
    const int qd = lane >> 3, il = lane & 7;
    // A m16k16 tile: quadrants (q&1)->+8 rows, (q>>1)->+8 k-cols
    const uint32_t offA = (uint32_t)((wm * 64 + il + (qd & 1) * 8) * ROWB + ((qd >> 1) * 8) * 2);
    // B pair of n8k16 tiles: (q>>1)->+8 n-rows(second tile), (q&1)->+8 k-cols
    const uint32_t offB = (uint32_t)((wn * 64 + il + (qd >> 1) * 8) * ROWB + ((qd & 1) * 8) * 2);

    float acc[4][8][4];
#pragma unroll
    for (int im = 0; im < 4; im++)
#pragma unroll
        for (int in = 0; in < 8; in++)
#pragma unroll
            for (int q = 0; q < 4; q++) acc[im][in][q] = 0.0f;

    auto prefetch = [&](int c, int st) {
#pragma unroll
        for (int i = 0; i < 16; i++) {
            int idx = tid + i * 128;        // 0..2047 16B-units
            int arr = idx >> 9;             // 0:Ah 1:Al 2:Bh 3:Bl
            int e   = idx & 511;
            int row = e >> 2;               // 0..127
            int seg = e & 3;                // 16B segment along k
            const __nv_bfloat16* gp;
            size_t koff = (size_t)c * GBK + seg * 8;
            if      (arr == 0) gp = Ahi + (size_t)(bm + row) * Kdim + koff;
            else if (arr == 1) gp = Alo + (size_t)(bm + row) * Kdim + koff;
            else if (arr == 2) gp = Bhi + (size_t)(bn + row) * Kdim + koff;
            else               gp = Blo + (size_t)(bn + row) * Kdim + koff;
            uint32_t sa = sb + st * STAGE_B + arr * ARR_B + row * ROWB + seg * 16;
            cp16(sa, gp);
        }
        asm volatile("cp.async.commit_group;");
    };

    prefetch(0, 0);

    for (int c = 0; c < NC; c++) {
        const int st = c & 1;
        if (c + 1 < NC) {
            prefetch(c + 1, (c + 1) & 1);
            asm volatile("cp.async.wait_group 1;");
        } else {
            asm volatile("cp.async.wait_group 0;");
        }
        __syncthreads();

        const uint32_t stb = sb + st * STAGE_B;

#pragma unroll
        for (int kk = 0; kk < GBK; kk += 16) {
            const uint32_t kb = (uint32_t)(kk * 2);
            uint32_t a[4][4], bh[8][2], bl[8][2];
            // B-hi: 4x ldmatrix.x4, each covers 2 n-tiles
#pragma unroll
            for (int p = 0; p < 4; p++)
                ldsm4(bh[2*p][0], bh[2*p][1], bh[2*p+1][0], bh[2*p+1][1],
                      stb + 2 * ARR_B + offB + p * (16 * ROWB) + kb);
            // A-hi: 4x ldmatrix.x4 (one per m16 tile)
#pragma unroll
            for (int im = 0; im < 4; im++)
                ldsm4(a[im][0], a[im][1], a[im][2], a[im][3],
                      stb + offA + im * (16 * ROWB) + kb);
            // pass 1: Ah * Bh
#pragma unroll
            for (int im = 0; im < 4; im++)
#pragma unroll
                for (int in = 0; in < 8; in++)
                    mma16816(acc[im][in], a[im], bh[in]);
            // B-lo
#pragma unroll
            for (int p = 0; p < 4; p++)
                ldsm4(bl[2*p][0], bl[2*p][1], bl[2*p+1][0], bl[2*p+1][1],
                      stb + 3 * ARR_B + offB + p * (16 * ROWB) + kb);
            // pass 2: Ah * Bl
#pragma unroll
            for (int im = 0; im < 4; im++)
#pragma unroll
                for (int in = 0; in < 8; in++)
                    mma16816(acc[im][in], a[im], bl[in]);
            // A-lo (overwrite a)
#pragma unroll
            for (int im = 0; im < 4; im++)
                ldsm4(a[im][0], a[im][1], a[im][2], a[im][3],
                      stb + ARR_B + offA + im * (16 * ROWB) + kb);
            // pass 3: Al * Bh
#pragma unroll
            for (int im = 0; im < 4; im++)
#pragma unroll
                for (int in = 0; in < 8; in++)
                    mma16816(acc[im][in], a[im], bh[in]);
        }
        __syncthreads();
    }

    // epilogue: acc -> C + bias
#pragma unroll
    for (int im = 0; im < 4; im++) {
        int r = bm + wm * 64 + im * 16 + g;
#pragma unroll
        for (int in = 0; in < 8; in++) {
            int ccol = bn + wn * 64 + in * 8 + 2 * tig;
            float2 b01 = *(const float2*)&bias[ccol];
            float2 o0 = make_float2(acc[im][in][0] + b01.x, acc[im][in][1] + b01.y);
            float2 o1 = make_float2(acc[im][in][2] + b01.x, acc[im][in][3] + b01.y);
            *(float2*)&C[(size_t)r * N + ccol]       = o0;
            *(float2*)&C[(size_t)(r + 8) * N + ccol] = o1;
        }
    }
}

// ---------------- tensor-core flash attention (split bf16) ----------------
#define VPAD 72

__global__ __launch_bounds__(256, 1)
void attn_mma(const __nv_bfloat16* __restrict__ qh, const __nv_bfloat16* __restrict__ ql,
              const __nv_bfloat16* __restrict__ kh, const __nv_bfloat16* __restrict__ kl,
              const __nv_bfloat16* __restrict__ vth, const __nv_bfloat16* __restrict__ vtl,
              const int* __restrict__ mask,
              __nv_bfloat16* __restrict__ ohi, __nv_bfloat16* __restrict__ olo)
{
    __shared__ __nv_bfloat16 sKh[64][VPAD], sKl[64][VPAD];
    __shared__ __nv_bfloat16 sVh[64][VPAD], sVl[64][VPAD];
    __shared__ int sMask[64];

    const int tid = threadIdx.x, wid = tid >> 5, lane = tid & 31;
    const int g = lane >> 2, tig = lane & 3;
    const int qt = gridDim.x - 1 - blockIdx.x;   // heavy tiles launch first
    const int bh = blockIdx.y;
    const int b = bh >> 4, h = bh & 15;
    const int q0 = qt * 128;
    const int wrow = q0 + wid * 16;
    const float scale = 0.125f;

    uint32_t aqh[4][4], aql[4][4];
    {
        const __nv_bfloat16* qb = qh + (size_t)(b * Ss + wrow) * Ee + h * 64;
        const __nv_bfloat16* qbl = ql + (size_t)(b * Ss + wrow) * Ee + h * 64;
#pragma unroll
        for (int s = 0; s < 4; s++) {
            int k0 = s * 16 + 2 * tig;
            aqh[s][0] = *(const uint32_t*)&qb [(size_t)(g    ) * Ee + k0];
            aqh[s][1] = *(const uint32_t*)&qb [(size_t)(g + 8) * Ee + k0];
            aqh[s][2] = *(const uint32_t*)&qb [(size_t)(g    ) * Ee + k0 + 8];
            aqh[s][3] = *(const uint32_t*)&qb [(size_t)(g + 8) * Ee + k0 + 8];
            aql[s][0] = *(const uint32_t*)&qbl[(size_t)(g    ) * Ee + k0];
            aql[s][1] = *(const uint32_t*)&qbl[(size_t)(g + 8) * Ee + k0];
            aql[s][2] = *(const uint32_t*)&qbl[(size_t)(g    ) * Ee + k0 + 8];
            aql[s][3] = *(const uint32_t*)&qbl[(size_t)(g + 8) * Ee + k0 + 8];
        }
    }

    float m0 = -1e30f, m1 = -1e30f, l0 = 0.0f, l1 = 0.0f;
    float o[8][4];
#pragma unroll
    for (int t = 0; t < 8; t++)
#pragma unroll
        for (int e = 0; e < 4; e++) o[t][e] = 0.0f;

    const int row0 = wrow + g, row1 = wrow + 8 + g;
    const int ntiles = (qt + 1) * 2;

    for (int j = 0; j < ntiles; j++) {
        const int kv0 = j * 64;
        __syncthreads();
        for (int i = tid; i < 512; i += 256) {
            int row = i >> 3, seg = (i & 7) * 8;
            *(uint4*)&sKh[row][seg] = *(const uint4*)&kh[(size_t)(b * Ss + kv0 + row) * Ee + h * 64 + seg];
            *(uint4*)&sKl[row][seg] = *(const uint4*)&kl[(size_t)(b * Ss + kv0 + row) * Ee + h * 64 + seg];
            *(uint4*)&sVh[row][seg] = *(const uint4*)&vth[(size_t)(b * Ee + h * 64 + row) * Ss + kv0 + seg];
            *(uint4*)&sVl[row][seg] = *(const uint4*)&vtl[(size_t)(b * Ee + h * 64 + row) * Ss + kv0 + seg];
        }
        if (tid < 64) sMask[tid] = mask[b * Ss + kv0 + tid];
        __syncthreads();

        float c[8][4];
#pragma unroll
        for (int t = 0; t < 8; t++)
#pragma unroll
            for (int e = 0; e < 4; e++) c[t][e] = 0.0f;

#pragma unroll
        for (int s = 0; s < 4; s++) {
            int k0 = s * 16 + 2 * tig;
#pragma unroll
            for (int t = 0; t < 8; t++) {
                uint32_t bhf[2], blf[2];
                bhf[0] = *(const uint32_t*)&sKh[t * 8 + g][k0];
                bhf[1] = *(const uint32_t*)&sKh[t * 8 + g][k0 + 8];
                blf[0] = *(const uint32_t*)&sKl[t * 8 + g][k0];
                blf[1] = *(const uint32_t*)&sKl[t * 8 + g][k0 + 8];
                mma16816(c[t], aqh[s], bhf);
                mma16816(c[t], aqh[s], blf);
                mma16816(c[t], aql[s], bhf);
            }
        }

#pragma unroll
        for (int t = 0; t < 8; t++) {
            int lc0 = t * 8 + 2 * tig;
            int col0 = kv0 + lc0, col1 = col0 + 1;
            bool v0 = sMask[lc0] != 0, v1 = sMask[lc0 + 1] != 0;
            c[t][0] = (v0 && col0 <= row0) ? c[t][0] * scale : -1e30f;
            c[t][1] = (v1 && col1 <= row0) ? c[t][1] * scale : -1e30f;
            c[t][2] = (v0 && col0 <= row1) ? c[t][2] * scale : -1e30f;
            c[t][3] = (v1 && col1 <= row1) ? c[t][3] * scale : -1e30f;
        }

        float ml0 = -1e30f, ml1 = -1e30f;
#pragma unroll
        for (int t = 0; t < 8; t++) {
            ml0 = fmaxf(ml0, fmaxf(c[t][0], c[t][1]));
            ml1 = fmaxf(ml1, fmaxf(c[t][2], c[t][3]));
        }
        ml0 = fmaxf(ml0, __shfl_xor_sync(0xffffffffu, ml0, 1));
        ml0 = fmaxf(ml0, __shfl_xor_sync(0xffffffffu, ml0, 2));
        ml1 = fmaxf(ml1, __shfl_xor_sync(0xffffffffu, ml1, 1));
        ml1 = fmaxf(ml1, __shfl_xor_sync(0xffffffffu, ml1, 2));

        float mn0 = fmaxf(m0, ml0), mn1 = fmaxf(m1, ml1);
        float alpha0 = __expf(m0 - mn0), alpha1 = __expf(m1 - mn1);
        m0 = mn0; m1 = mn1;

        float rs0 = 0.0f, rs1 = 0.0f;
#pragma unroll
        for (int t = 0; t < 8; t++) {
            c[t][0] = __expf(c[t][0] - m0); rs0 += c[t][0];
            c[t][1] = __expf(c[t][1] - m0); rs0 += c[t][1];
            c[t][2] = __expf(c[t][2] - m1); rs1 += c[t][2];
            c[t][3] = __expf(c[t][3] - m1); rs1 += c[t][3];
        }
        rs0 += __shfl_xor_sync(0xffffffffu, rs0, 1);
        rs0 += __shfl_xor_sync(0xffffffffu, rs0, 2);
        rs1 += __shfl_xor_sync(0xffffffffu, rs1, 1);
        rs1 += __shfl_xor_sync(0xffffffffu, rs1, 2);

        l0 = l0 * alpha0 + rs0;
        l1 = l1 * alpha1 + rs1;
#pragma unroll
        for (int t = 0; t < 8; t++) {
            o[t][0] *= alpha0; o[t][1] *= alpha0;
            o[t][2] *= alpha1; o[t][3] *= alpha1;
        }

#pragma unroll
        for (int s = 0; s < 4; s++) {
            uint32_t aph[4], apl[4];
            splitpack(c[2 * s][0],     c[2 * s][1],     aph[0], apl[0]);
            splitpack(c[2 * s][2],     c[2 * s][3],     aph[1], apl[1]);
            splitpack(c[2 * s + 1][0], c[2 * s + 1][1], aph[2], apl[2]);
            splitpack(c[2 * s + 1][2], c[2 * s + 1][3], aph[3], apl[3]);
            int k0 = s * 16 + 2 * tig;
#pragma unroll
            for (int t = 0; t < 8; t++) {
                uint32_t bvh[2], bvl[2];
                bvh[0] = *(const uint32_t*)&sVh[t * 8 + g][k0];
                bvh[1] = *(const uint32_t*)&sVh[t * 8 + g][k0 + 8];
                bvl[0] = *(const uint32_t*)&sVl[t * 8 + g][k0];
                bvl[1] = *(const uint32_t*)&sVl[t * 8 + g][k0 + 8];
                mma16816(o[t], aph, bvh);
                mma16816(o[t], aph, bvl);
                mma16816(o[t], apl, bvh);
            }
        }
    }

    // epilogue: write bf16 split directly (proj GEMM input)
    float inv0 = 1.0f / l0, inv1 = 1.0f / l1;
    size_t base0 = (size_t)(b * Ss + row0) * Ee + h * 64;
    size_t base1 = (size_t)(b * Ss + row1) * Ee + h * 64;
#pragma unroll
    for (int t = 0; t < 8; t++) {
        int cc = t * 8 + 2 * tig;
        uint32_t hi0, lo0, hi1, lo1;
        splitpack(o[t][0] * inv0, o[t][1] * inv0, hi0, lo0);
        splitpack(o[t][2] * inv1, o[t][3] * inv1, hi1, lo1);
        *(uint32_t*)&ohi[base0 + cc] = hi0;
        *(uint32_t*)&olo[base0 + cc] = lo0;
        *(uint32_t*)&ohi[base1 + cc] = hi1;
        *(uint32_t*)&olo[base1 + cc] = lo1;
    }
}

// ---------------- launch ----------------
extern "C" void kernel_launch(void* const* d_in, const int* in_sizes, int n_in,
                              void* d_out, int out_size)
{
    const float* X     = (const float*)d_in[0];
    const int*   mask  = (const int*)  d_in[1];
    const float* Wqkv  = (const float*)d_in[2];
    const float* bqkv  = (const float*)d_in[3];
    const float* Wproj = (const float*)d_in[4];
    const float* bproj = (const float*)d_in[5];
    float* out = (float*)d_out;

    float *qkv;
    __nv_bfloat16 *xhi, *xlo, *wqh, *wql, *wph, *wpl, *ahi, *alo, *vth, *vtl, *ohi, *olo;
    cudaGetSymbolAddress((void**)&qkv,  g_qkv);
    cudaGetSymbolAddress((void**)&xhi,  g_xhi);
    cudaGetSymbolAddress((void**)&xlo,  g_xlo);
    cudaGetSymbolAddress((void**)&wqh,  g_wqh);
    cudaGetSymbolAddress((void**)&wql,  g_wql);
    cudaGetSymbolAddress((void**)&wph,  g_wph);
    cudaGetSymbolAddress((void**)&wpl,  g_wpl);
    cudaGetSymbolAddress((void**)&ahi,  g_ahi);
    cudaGetSymbolAddress((void**)&alo,  g_alo);
    cudaGetSymbolAddress((void**)&vth,  g_vth);
    cudaGetSymbolAddress((void**)&vtl,  g_vtl);
    cudaGetSymbolAddress((void**)&ohi,  g_ohi);
    cudaGetSymbolAddress((void**)&olo,  g_olo);

    cudaFuncSetAttribute(gemm_mma, cudaFuncAttributeMaxDynamicSharedMemorySize, GEMM_SMEM);

    // prep: split X, transpose+split weights
    split_hi_lo<<<(MTOT * Ee) / 4 / 256, 256>>>(X, xhi, xlo, MTOT * Ee);
    {
        dim3 blk(32, 8);
        transpose_split<<<dim3(E3 / 32, Kdim / 32), blk>>>(Wqkv, wqh, wql, Kdim, E3);
        transpose_split<<<dim3(Ee / 32, Kdim / 32), blk>>>(Wproj, wph, wpl, Kdim, Ee);
    }

    // 1) QKV = X @ Wqkv + b  (tensor cores)
    gemm_mma<<<dim3(E3 / 128, MTOT / 128), 128, GEMM_SMEM>>>(xhi, xlo, wqh, wql, bqkv, qkv, E3);

    // 2) attention prep
    split_qk<<<(MTOT * Ee) / 4 / 256, 256>>>(qkv, xhi, xlo, ahi, alo);
    {
        dim3 blk(32, 8);
        transpose_v_split<<<dim3(Ee / 32, Ss / 32, Bb), blk>>>(qkv, vth, vtl);
    }

    // 3) tensor-core flash attention (writes split output directly)
    attn_mma<<<dim3(Ss / 128, Bb * Hh), 256>>>(xhi, xlo, ahi, alo, vth, vtl, mask, ohi, olo);

    // 4) out = attn @ Wproj + b
    gemm_mma<<<dim3(Ee / 128, MTOT / 128), 128, GEMM_SMEM>>>(ohi, olo, wph, wpl, bproj, out, Ee);
}

// round 8
// speedup vs baseline: 1.2979x; 1.0792x over previous
#include <cuda_runtime.h>
#include <cuda_bf16.h>
#include <cstdint>
#include <math.h>

// ---------------- problem constants ----------------
#define Bb   4
#define Ss   1024
#define Ee   1024
#define Hh   16
#define HDs  64
#define MTOT 4096      // B*S
#define E3   3072      // 3*E
#define Kdim 1024

// ---------------- scratch (device globals) ----------------
__device__ float          g_qkv [MTOT * E3];     // [B*S, 3E] fp32
__device__ __nv_bfloat16  g_xhi [MTOT * Ee];     // X split; reused as Q_hi after QKV
__device__ __nv_bfloat16  g_xlo [MTOT * Ee];
__device__ __nv_bfloat16  g_wqh [E3 * Ee];       // Wqkv^T
__device__ __nv_bfloat16  g_wql [E3 * Ee];
__device__ __nv_bfloat16  g_wph [Ee * Ee];       // Wproj^T
__device__ __nv_bfloat16  g_wpl [Ee * Ee];
__device__ __nv_bfloat16  g_ahi [MTOT * Ee];     // K_hi
__device__ __nv_bfloat16  g_alo [MTOT * Ee];     // K_lo
__device__ __nv_bfloat16  g_vth [Bb * Ee * Ss];  // V^T split
__device__ __nv_bfloat16  g_vtl [Bb * Ee * Ss];
__device__ __nv_bfloat16  g_ohi [MTOT * Ee];     // attention output split (proj input)
__device__ __nv_bfloat16  g_olo [MTOT * Ee];

// ---------------- helpers ----------------
__device__ __forceinline__ void mma16816(float* c, const uint32_t* a, const uint32_t* b)
{
    asm volatile(
        "mma.sync.aligned.m16n8k16.row.col.f32.bf16.bf16.f32 "
        "{%0,%1,%2,%3}, {%4,%5,%6,%7}, {%8,%9}, {%0,%1,%2,%3};"
        : "+f"(c[0]), "+f"(c[1]), "+f"(c[2]), "+f"(c[3])
        : "r"(a[0]), "r"(a[1]), "r"(a[2]), "r"(a[3]), "r"(b[0]), "r"(b[1]));
}
__device__ __forceinline__ void ldsm4(uint32_t& r0, uint32_t& r1, uint32_t& r2, uint32_t& r3,
                                      uint32_t addr)
{
    asm volatile("ldmatrix.sync.aligned.m8n8.x4.shared.b16 {%0,%1,%2,%3}, [%4];"
                 : "=r"(r0), "=r"(r1), "=r"(r2), "=r"(r3) : "r"(addr));
}
__device__ __forceinline__ void cp16(uint32_t saddr, const void* g)
{
    asm volatile("cp.async.cg.shared.global [%0], [%1], 16;"
                 :: "r"(saddr), "l"(g));
}
__device__ __forceinline__ uint32_t smem_u32(const void* p) {
    uint32_t a;
    asm("{ .reg .u64 t; cvta.to.shared.u64 t, %1; cvt.u32.u64 %0, t; }"
        : "=r"(a) : "l"(p));
    return a;
}
__device__ __forceinline__ void splitpack(float f0, float f1, uint32_t& hi, uint32_t& lo)
{
    __nv_bfloat16 h0 = __float2bfloat16_rn(f0);
    __nv_bfloat16 h1 = __float2bfloat16_rn(f1);
    __nv_bfloat162 hp = __halves2bfloat162(h0, h1);
    hi = *(uint32_t*)&hp;
    __nv_bfloat162 lp = __floats2bfloat162_rn(f0 - __bfloat162float(h0),
                                              f1 - __bfloat162float(h1));
    lo = *(uint32_t*)&lp;
}

// ---------------- split fp32 -> (bf16 hi, bf16 lo) ----------------
__global__ __launch_bounds__(256)
void split_hi_lo(const float* __restrict__ x,
                 __nv_bfloat16* __restrict__ hi,
                 __nv_bfloat16* __restrict__ lo, int n)
{
    int i = (blockIdx.x * 256 + threadIdx.x) * 4;
    if (i >= n) return;
    float4 v = *(const float4*)(x + i);
    __nv_bfloat16 h[4], l[4];
    float vv[4] = {v.x, v.y, v.z, v.w};
#pragma unroll
    for (int q = 0; q < 4; q++) {
        h[q] = __float2bfloat16_rn(vv[q]);
        l[q] = __float2bfloat16_rn(vv[q] - __bfloat162float(h[q]));
    }
    *(uint2*)(hi + i) = *(uint2*)h;
    *(uint2*)(lo + i) = *(uint2*)l;
}

// ---------------- split Q and K sections of qkv ----------------
__global__ __launch_bounds__(256)
void split_qk(const float* __restrict__ qkv,
              __nv_bfloat16* __restrict__ qh, __nv_bfloat16* __restrict__ ql,
              __nv_bfloat16* __restrict__ kh, __nv_bfloat16* __restrict__ kl)
{
    int t = blockIdx.x * 256 + threadIdx.x;
    int i4 = t * 4;
    if (i4 >= MTOT * Ee) return;
    int row = i4 >> 10, col = i4 & 1023;
    float4 q = *(const float4*)&qkv[(size_t)row * E3 + col];
    float4 k = *(const float4*)&qkv[(size_t)row * E3 + Ee + col];
    float qv[4] = {q.x, q.y, q.z, q.w}, kv[4] = {k.x, k.y, k.z, k.w};
    __nv_bfloat16 qhh[4], qll[4], khh[4], kll[4];
#pragma unroll
    for (int e = 0; e < 4; e++) {
        qhh[e] = __float2bfloat16_rn(qv[e]);
        qll[e] = __float2bfloat16_rn(qv[e] - __bfloat162float(qhh[e]));
        khh[e] = __float2bfloat16_rn(kv[e]);
        kll[e] = __float2bfloat16_rn(kv[e] - __bfloat162float(khh[e]));
    }
    *(uint2*)(qh + i4) = *(uint2*)qhh;
    *(uint2*)(ql + i4) = *(uint2*)qll;
    *(uint2*)(kh + i4) = *(uint2*)khh;
    *(uint2*)(kl + i4) = *(uint2*)kll;
}

// ---------------- transpose+split V ----------------
__global__ __launch_bounds__(256)
void transpose_v_split(const float* __restrict__ qkv,
                       __nv_bfloat16* __restrict__ vth, __nv_bfloat16* __restrict__ vtl)
{
    __shared__ float tile[32][33];
    int c0 = blockIdx.x * 32;
    int s0 = blockIdx.y * 32;
    int b  = blockIdx.z;
    int tx = threadIdx.x, ty = threadIdx.y;
#pragma unroll
    for (int i = 0; i < 32; i += 8)
        tile[ty + i][tx] = qkv[(size_t)(b * Ss + s0 + ty + i) * E3 + 2 * Ee + c0 + tx];
    __syncthreads();
#pragma unroll
    for (int i = 0; i < 32; i += 8) {
        int ccol = c0 + ty + i, srow = s0 + tx;
        float v = tile[tx][ty + i];
        __nv_bfloat16 h = __float2bfloat16_rn(v);
        vth[(size_t)(b * Ee + ccol) * Ss + srow] = h;
        vtl[(size_t)(b * Ee + ccol) * Ss + srow] = __float2bfloat16_rn(v - __bfloat162float(h));
    }
}

// ---------------- transpose + split W ----------------
__global__ __launch_bounds__(256)
void transpose_split(const float* __restrict__ W,
                     __nv_bfloat16* __restrict__ Thi,
                     __nv_bfloat16* __restrict__ Tlo, int K, int N)
{
    __shared__ float tile[32][33];
    int n0 = blockIdx.x * 32, k0 = blockIdx.y * 32;
    int tx = threadIdx.x, ty = threadIdx.y;
#pragma unroll
    for (int i = 0; i < 32; i += 8)
        tile[ty + i][tx] = W[(size_t)(k0 + ty + i) * N + n0 + tx];
    __syncthreads();
#pragma unroll
    for (int i = 0; i < 32; i += 8) {
        int n = n0 + ty + i, k = k0 + tx;
        float v = tile[tx][ty + i];
        __nv_bfloat16 h = __float2bfloat16_rn(v);
        Thi[(size_t)n * K + k] = h;
        Tlo[(size_t)n * K + k] = __float2bfloat16_rn(v - __bfloat162float(h));
    }
}

// ---------------- split-bf16 GEMM (unchanged from R7) ----------------
#define GBK      32
#define GSTRIDE  40
#define ROWB     (GSTRIDE * 2)
#define ARR_B    (128 * ROWB)
#define STAGE_B  (4 * ARR_B)
#define GEMM_SMEM (2 * STAGE_B)

__global__ __launch_bounds__(128, 2)
void gemm_mma(const __nv_bfloat16* __restrict__ Ahi, const __nv_bfloat16* __restrict__ Alo,
              const __nv_bfloat16* __restrict__ Bhi, const __nv_bfloat16* __restrict__ Blo,
              const float* __restrict__ bias, float* __restrict__ C, int N)
{
    extern __shared__ char smem[];
    const uint32_t sb = smem_u32(smem);
    const int tid  = threadIdx.x;
    const int wid  = tid >> 5, lane = tid & 31;
    const int wm   = wid >> 1, wn = wid & 1;
    const int g    = lane >> 2, tig = lane & 3;
    const int bm   = blockIdx.y * 128, bn = blockIdx.x * 128;
    const int NC   = Kdim / GBK;

    const int qd = lane >> 3, il = lane & 7;
    const uint32_t offA = (uint32_t)((wm * 64 + il + (qd & 1) * 8) * ROWB + ((qd >> 1) * 8) * 2);
    const uint32_t offB = (uint32_t)((wn * 64 + il + (qd >> 1) * 8) * ROWB + ((qd & 1) * 8) * 2);

    float acc[4][8][4];
#pragma unroll
    for (int im = 0; im < 4; im++)
#pragma unroll
        for (int in = 0; in < 8; in++)
#pragma unroll
            for (int q = 0; q < 4; q++) acc[im][in][q] = 0.0f;

    auto prefetch = [&](int c, int st) {
#pragma unroll
        for (int i = 0; i < 16; i++) {
            int idx = tid + i * 128;
            int arr = idx >> 9;
            int e   = idx & 511;
            int row = e >> 2;
            int seg = e & 3;
            const __nv_bfloat16* gp;
            size_t koff = (size_t)c * GBK + seg * 8;
            if      (arr == 0) gp = Ahi + (size_t)(bm + row) * Kdim + koff;
            else if (arr == 1) gp = Alo + (size_t)(bm + row) * Kdim + koff;
            else if (arr == 2) gp = Bhi + (size_t)(bn + row) * Kdim + koff;
            else               gp = Blo + (size_t)(bn + row) * Kdim + koff;
            uint32_t sa = sb + st * STAGE_B + arr * ARR_B + row * ROWB + seg * 16;
            cp16(sa, gp);
        }
        asm volatile("cp.async.commit_group;");
    };

    prefetch(0, 0);

    for (int c = 0; c < NC; c++) {
        const int st = c & 1;
        if (c + 1 < NC) {
            prefetch(c + 1, (c + 1) & 1);
            asm volatile("cp.async.wait_group 1;");
        } else {
            asm volatile("cp.async.wait_group 0;");
        }
        __syncthreads();

        const uint32_t stb = sb + st * STAGE_B;

#pragma unroll
        for (int kk = 0; kk < GBK; kk += 16) {
            const uint32_t kb = (uint32_t)(kk * 2);
            uint32_t a[4][4], bh[8][2], bl[8][2];
#pragma unroll
            for (int p = 0; p < 4; p++)
                ldsm4(bh[2*p][0], bh[2*p][1], bh[2*p+1][0], bh[2*p+1][1],
                      stb + 2 * ARR_B + offB + p * (16 * ROWB) + kb);
#pragma unroll
            for (int im = 0; im < 4; im++)
                ldsm4(a[im][0], a[im][1], a[im][2], a[im][3],
                      stb + offA + im * (16 * ROWB) + kb);
#pragma unroll
            for (int im = 0; im < 4; im++)
#pragma unroll
                for (int in = 0; in < 8; in++)
                    mma16816(acc[im][in], a[im], bh[in]);
#pragma unroll
            for (int p = 0; p < 4; p++)
                ldsm4(bl[2*p][0], bl[2*p][1], bl[2*p+1][0], bl[2*p+1][1],
                      stb + 3 * ARR_B + offB + p * (16 * ROWB) + kb);
#pragma unroll
            for (int im = 0; im < 4; im++)
#pragma unroll
                for (int in = 0; in < 8; in++)
                    mma16816(acc[im][in], a[im], bl[in]);
#pragma unroll
            for (int im = 0; im < 4; im++)
                ldsm4(a[im][0], a[im][1], a[im][2], a[im][3],
                      stb + ARR_B + offA + im * (16 * ROWB) + kb);
#pragma unroll
            for (int im = 0; im < 4; im++)
#pragma unroll
                for (int in = 0; in < 8; in++)
                    mma16816(acc[im][in], a[im], bh[in]);
        }
        __syncthreads();
    }

#pragma unroll
    for (int im = 0; im < 4; im++) {
        int r = bm + wm * 64 + im * 16 + g;
#pragma unroll
        for (int in = 0; in < 8; in++) {
            int ccol = bn + wn * 64 + in * 8 + 2 * tig;
            float2 b01 = *(const float2*)&bias[ccol];
            float2 o0 = make_float2(acc[im][in][0] + b01.x, acc[im][in][1] + b01.y);
            float2 o1 = make_float2(acc[im][in][2] + b01.x, acc[im][in][3] + b01.y);
            *(float2*)&C[(size_t)r * N + ccol]       = o0;
            *(float2*)&C[(size_t)(r + 8) * N + ccol] = o1;
        }
    }
}

// ---------------- tensor-core flash attention: cp.async double-buffer + ldmatrix ----------------
// KV stage: Kh, Kl, Vh, Vl each [64][72] bf16 (144 B rows). Stage = 4 * 9216 = 36864 B.
#define AKVROW 144
#define AARR   9216
#define AST    36864
#define ATTN_SMEM (2 * AST)

__global__ __launch_bounds__(256, 1)
void attn_mma(const __nv_bfloat16* __restrict__ qh, const __nv_bfloat16* __restrict__ ql,
              const __nv_bfloat16* __restrict__ kh, const __nv_bfloat16* __restrict__ kl,
              const __nv_bfloat16* __restrict__ vth, const __nv_bfloat16* __restrict__ vtl,
              const int* __restrict__ mask,
              __nv_bfloat16* __restrict__ ohi, __nv_bfloat16* __restrict__ olo)
{
    extern __shared__ char asmem[];
    __shared__ int sMask[2][64];
    const uint32_t sb = smem_u32(asmem);
    const uint32_t mb = smem_u32(&sMask[0][0]);

    const int tid = threadIdx.x, wid = tid >> 5, lane = tid & 31;
    const int g = lane >> 2, tig = lane & 3;
    const int qd = lane >> 3, il = lane & 7;
    const uint32_t offKV = (uint32_t)((il + (qd >> 1) * 8) * AKVROW + ((qd & 1) * 8) * 2);

    const int qt = gridDim.x - 1 - blockIdx.x;   // heavy tiles launch first
    const int bh = blockIdx.y;
    const int b = bh >> 4, h = bh & 15;
    const int q0 = qt * 128;
    const int wrow = q0 + wid * 16;
    const float scale = 0.125f;

    // resident Q fragments
    uint32_t aqh[4][4], aql[4][4];
    {
        const __nv_bfloat16* qb  = qh + (size_t)(b * Ss + wrow) * Ee + h * 64;
        const __nv_bfloat16* qbl = ql + (size_t)(b * Ss + wrow) * Ee + h * 64;
#pragma unroll
        for (int s = 0; s < 4; s++) {
            int k0 = s * 16 + 2 * tig;
            aqh[s][0] = *(const uint32_t*)&qb [(size_t)(g    ) * Ee + k0];
            aqh[s][1] = *(const uint32_t*)&qb [(size_t)(g + 8) * Ee + k0];
            aqh[s][2] = *(const uint32_t*)&qb [(size_t)(g    ) * Ee + k0 + 8];
            aqh[s][3] = *(const uint32_t*)&qb [(size_t)(g + 8) * Ee + k0 + 8];
            aql[s][0] = *(const uint32_t*)&qbl[(size_t)(g    ) * Ee + k0];
            aql[s][1] = *(const uint32_t*)&qbl[(size_t)(g + 8) * Ee + k0];
            aql[s][2] = *(const uint32_t*)&qbl[(size_t)(g    ) * Ee + k0 + 8];
            aql[s][3] = *(const uint32_t*)&qbl[(size_t)(g + 8) * Ee + k0 + 8];
        }
    }

    auto prefetch = [&](int j) {
        const int kv0 = j * 64;
        const uint32_t stb = sb + (j & 1) * AST;
        // 4 arrays x 64 rows x 8 x 16B = 2048 units; 8 per thread
#pragma unroll
        for (int i = 0; i < 8; i++) {
            int idx = tid + i * 256;
            int arr = idx >> 9;
            int e   = idx & 511;
            int row = e >> 3;
            int segB = (e & 7) * 16;          // byte offset in row
            const __nv_bfloat16* gp;
            if      (arr == 0) gp = kh  + (size_t)(b * Ss + kv0 + row) * Ee + h * 64 + segB / 2;
            else if (arr == 1) gp = kl  + (size_t)(b * Ss + kv0 + row) * Ee + h * 64 + segB / 2;
            else if (arr == 2) gp = vth + (size_t)(b * Ee + h * 64 + row) * Ss + kv0 + segB / 2;
            else               gp = vtl + (size_t)(b * Ee + h * 64 + row) * Ss + kv0 + segB / 2;
            cp16(stb + arr * AARR + row * AKVROW + segB, gp);
        }
        if (tid < 16)
            cp16(mb + (j & 1) * 256 + tid * 16, &mask[b * Ss + kv0 + tid * 4]);
        asm volatile("cp.async.commit_group;");
    };

    float m0 = -1e30f, m1 = -1e30f, l0 = 0.0f, l1 = 0.0f;
    float o[8][4];
#pragma unroll
    for (int t = 0; t < 8; t++)
#pragma unroll
        for (int e = 0; e < 4; e++) o[t][e] = 0.0f;

    const int row0 = wrow + g, row1 = wrow + 8 + g;
    const int ntiles = (qt + 1) * 2;

    prefetch(0);

    for (int j = 0; j < ntiles; j++) {
        const int kv0 = j * 64;
        const int st = j & 1;
        __syncthreads();                       // writers of buf st^1 may proceed only after readers done
        if (j + 1 < ntiles) {
            prefetch(j + 1);
            asm volatile("cp.async.wait_group 1;");
        } else {
            asm volatile("cp.async.wait_group 0;");
        }
        __syncthreads();                       // visibility of all threads' cp.async data

        const uint32_t stb = sb + st * AST;
        const int* msk = sMask[st];

        // ---- S = Q K^T (3-pass split), K frags via ldmatrix ----
        float c[8][4];
#pragma unroll
        for (int t = 0; t < 8; t++)
#pragma unroll
            for (int e = 0; e < 4; e++) c[t][e] = 0.0f;

#pragma unroll
        for (int s = 0; s < 4; s++) {
            const uint32_t kb = (uint32_t)(s * 32);
            uint32_t kf[8][2], lf[8][2];
#pragma unroll
            for (int p = 0; p < 4; p++)
                ldsm4(kf[2*p][0], kf[2*p][1], kf[2*p+1][0], kf[2*p+1][1],
                      stb + offKV + p * (16 * AKVROW) + kb);
#pragma unroll
            for (int p = 0; p < 4; p++)
                ldsm4(lf[2*p][0], lf[2*p][1], lf[2*p+1][0], lf[2*p+1][1],
                      stb + AARR + offKV + p * (16 * AKVROW) + kb);
#pragma unroll
            for (int t = 0; t < 8; t++) {
                mma16816(c[t], aqh[s], kf[t]);
                mma16816(c[t], aqh[s], lf[t]);
                mma16816(c[t], aql[s], kf[t]);
            }
        }

        // ---- scale + causal + key mask ----
#pragma unroll
        for (int t = 0; t < 8; t++) {
            int lc0 = t * 8 + 2 * tig;
            int col0 = kv0 + lc0, col1 = col0 + 1;
            bool v0 = msk[lc0] != 0, v1 = msk[lc0 + 1] != 0;
            c[t][0] = (v0 && col0 <= row0) ? c[t][0] * scale : -1e30f;
            c[t][1] = (v1 && col1 <= row0) ? c[t][1] * scale : -1e30f;
            c[t][2] = (v0 && col0 <= row1) ? c[t][2] * scale : -1e30f;
            c[t][3] = (v1 && col1 <= row1) ? c[t][3] * scale : -1e30f;
        }

        // ---- online softmax ----
        float ml0 = -1e30f, ml1 = -1e30f;
#pragma unroll
        for (int t = 0; t < 8; t++) {
            ml0 = fmaxf(ml0, fmaxf(c[t][0], c[t][1]));
            ml1 = fmaxf(ml1, fmaxf(c[t][2], c[t][3]));
        }
        ml0 = fmaxf(ml0, __shfl_xor_sync(0xffffffffu, ml0, 1));
        ml0 = fmaxf(ml0, __shfl_xor_sync(0xffffffffu, ml0, 2));
        ml1 = fmaxf(ml1, __shfl_xor_sync(0xffffffffu, ml1, 1));
        ml1 = fmaxf(ml1, __shfl_xor_sync(0xffffffffu, ml1, 2));

        float mn0 = fmaxf(m0, ml0), mn1 = fmaxf(m1, ml1);
        float alpha0 = __expf(m0 - mn0), alpha1 = __expf(m1 - mn1);
        m0 = mn0; m1 = mn1;

        float rs0 = 0.0f, rs1 = 0.0f;
#pragma unroll
        for (int t = 0; t < 8; t++) {
            c[t][0] = __expf(c[t][0] - m0); rs0 += c[t][0];
            c[t][1] = __expf(c[t][1] - m0); rs0 += c[t][1];
            c[t][2] = __expf(c[t][2] - m1); rs1 += c[t][2];
            c[t][3] = __expf(c[t][3] - m1); rs1 += c[t][3];
        }
        rs0 += __shfl_xor_sync(0xffffffffu, rs0, 1);
        rs0 += __shfl_xor_sync(0xffffffffu, rs0, 2);
        rs1 += __shfl_xor_sync(0xffffffffu, rs1, 1);
        rs1 += __shfl_xor_sync(0xffffffffu, rs1, 2);

        l0 = l0 * alpha0 + rs0;
        l1 = l1 * alpha1 + rs1;
#pragma unroll
        for (int t = 0; t < 8; t++) {
            o[t][0] *= alpha0; o[t][1] *= alpha0;
            o[t][2] *= alpha1; o[t][3] *= alpha1;
        }

        // ---- O += P V (3-pass), V frags via ldmatrix ----
#pragma unroll
        for (int s = 0; s < 4; s++) {
            uint32_t aph[4], apl[4];
            splitpack(c[2 * s][0],     c[2 * s][1],     aph[0], apl[0]);
            splitpack(c[2 * s][2],     c[2 * s][3],     aph[1], apl[1]);
            splitpack(c[2 * s + 1][0], c[2 * s + 1][1], aph[2], apl[2]);
            splitpack(c[2 * s + 1][2], c[2 * s + 1][3], aph[3], apl[3]);
            const uint32_t kb = (uint32_t)(s * 32);
            uint32_t vf[8][2], wf[8][2];
#pragma unroll
            for (int p = 0; p < 4; p++)
                ldsm4(vf[2*p][0], vf[2*p][1], vf[2*p+1][0], vf[2*p+1][1],
                      stb + 2 * AARR + offKV + p * (16 * AKVROW) + kb);
#pragma unroll
            for (int p = 0; p < 4; p++)
                ldsm4(wf[2*p][0], wf[2*p][1], wf[2*p+1][0], wf[2*p+1][1],
                      stb + 3 * AARR + offKV + p * (16 * AKVROW) + kb);
#pragma unroll
            for (int t = 0; t < 8; t++) {
                mma16816(o[t], aph, vf[t]);
                mma16816(o[t], aph, wf[t]);
                mma16816(o[t], apl, vf[t]);
            }
        }
    }

    // epilogue: write bf16 split directly (proj GEMM input)
    float inv0 = 1.0f / l0, inv1 = 1.0f / l1;
    size_t base0 = (size_t)(b * Ss + row0) * Ee + h * 64;
    size_t base1 = (size_t)(b * Ss + row1) * Ee + h * 64;
#pragma unroll
    for (int t = 0; t < 8; t++) {
        int cc = t * 8 + 2 * tig;
        uint32_t hi0, lo0, hi1, lo1;
        splitpack(o[t][0] * inv0, o[t][1] * inv0, hi0, lo0);
        splitpack(o[t][2] * inv1, o[t][3] * inv1, hi1, lo1);
        *(uint32_t*)&ohi[base0 + cc] = hi0;
        *(uint32_t*)&olo[base0 + cc] = lo0;
        *(uint32_t*)&ohi[base1 + cc] = hi1;
        *(uint32_t*)&olo[base1 + cc] = lo1;
    }
}

// ---------------- launch ----------------
extern "C" void kernel_launch(void* const* d_in, const int* in_sizes, int n_in,
                              void* d_out, int out_size)
{
    const float* X     = (const float*)d_in[0];
    const int*   mask  = (const int*)  d_in[1];
    const float* Wqkv  = (const float*)d_in[2];
    const float* bqkv  = (const float*)d_in[3];
    const float* Wproj = (const float*)d_in[4];
    const float* bproj = (const float*)d_in[5];
    float* out = (float*)d_out;

    float *qkv;
    __nv_bfloat16 *xhi, *xlo, *wqh, *wql, *wph, *wpl, *ahi, *alo, *vth, *vtl, *ohi, *olo;
    cudaGetSymbolAddress((void**)&qkv,  g_qkv);
    cudaGetSymbolAddress((void**)&xhi,  g_xhi);
    cudaGetSymbolAddress((void**)&xlo,  g_xlo);
    cudaGetSymbolAddress((void**)&wqh,  g_wqh);
    cudaGetSymbolAddress((void**)&wql,  g_wql);
    cudaGetSymbolAddress((void**)&wph,  g_wph);
    cudaGetSymbolAddress((void**)&wpl,  g_wpl);
    cudaGetSymbolAddress((void**)&ahi,  g_ahi);
    cudaGetSymbolAddress((void**)&alo,  g_alo);
    cudaGetSymbolAddress((void**)&vth,  g_vth);
    cudaGetSymbolAddress((void**)&vtl,  g_vtl);
    cudaGetSymbolAddress((void**)&ohi,  g_ohi);
    cudaGetSymbolAddress((void**)&olo,  g_olo);

    cudaFuncSetAttribute(gemm_mma, cudaFuncAttributeMaxDynamicSharedMemorySize, GEMM_SMEM);
    cudaFuncSetAttribute(attn_mma, cudaFuncAttributeMaxDynamicSharedMemorySize, ATTN_SMEM);

    // prep: split X, transpose+split weights
    split_hi_lo<<<(MTOT * Ee) / 4 / 256, 256>>>(X, xhi, xlo, MTOT * Ee);
    {
        dim3 blk(32, 8);
        transpose_split<<<dim3(E3 / 32, Kdim / 32), blk>>>(Wqkv, wqh, wql, Kdim, E3);
        transpose_split<<<dim3(Ee / 32, Kdim / 32), blk>>>(Wproj, wph, wpl, Kdim, Ee);
    }

    // 1) QKV = X @ Wqkv + b
    gemm_mma<<<dim3(E3 / 128, MTOT / 128), 128, GEMM_SMEM>>>(xhi, xlo, wqh, wql, bqkv, qkv, E3);

    // 2) attention prep
    split_qk<<<(MTOT * Ee) / 4 / 256, 256>>>(qkv, xhi, xlo, ahi, alo);
    {
        dim3 blk(32, 8);
        transpose_v_split<<<dim3(Ee / 32, Ss / 32, Bb), blk>>>(qkv, vth, vtl);
    }

    // 3) tensor-core flash attention (pipelined, writes split output directly)
    attn_mma<<<dim3(Ss / 128, Bb * Hh), 256, ATTN_SMEM>>>(xhi, xlo, ahi, alo, vth, vtl, mask, ohi, olo);

    // 4) out = attn @ Wproj + b
    gemm_mma<<<dim3(Ee / 128, MTOT / 128), 128, GEMM_SMEM>>>(ohi, olo, wph, wpl, bproj, out, Ee);
}

// round 9
// speedup vs baseline: 1.3333x; 1.0273x over previous
#include <cuda_runtime.h>
#include <cuda_bf16.h>
#include <cstdint>
#include <math.h>

// ---------------- problem constants ----------------
#define Bb   4
#define Ss   1024
#define Ee   1024
#define Hh   16
#define HDs  64
#define MTOT 4096      // B*S
#define E3   3072      // 3*E
#define Kdim 1024

// ---------------- scratch (device globals) ----------------
__device__ float          g_vf  [MTOT * Ee];     // V section fp32 (compact, stride 1024)
__device__ __nv_bfloat16  g_xhi [MTOT * Ee];     // X split (QKV GEMM A operand)
__device__ __nv_bfloat16  g_xlo [MTOT * Ee];
__device__ __nv_bfloat16  g_qh  [MTOT * Ee];     // Q split (written by fused epilogue)
__device__ __nv_bfloat16  g_ql  [MTOT * Ee];
__device__ __nv_bfloat16  g_wqh [E3 * Ee];       // Wqkv^T
__device__ __nv_bfloat16  g_wql [E3 * Ee];
__device__ __nv_bfloat16  g_wph [Ee * Ee];       // Wproj^T
__device__ __nv_bfloat16  g_wpl [Ee * Ee];
__device__ __nv_bfloat16  g_ahi [MTOT * Ee];     // K split
__device__ __nv_bfloat16  g_alo [MTOT * Ee];
__device__ __nv_bfloat16  g_vth [Bb * Ee * Ss];  // V^T split
__device__ __nv_bfloat16  g_vtl [Bb * Ee * Ss];
__device__ __nv_bfloat16  g_ohi [MTOT * Ee];     // attention output split (proj input)
__device__ __nv_bfloat16  g_olo [MTOT * Ee];

// ---------------- helpers ----------------
__device__ __forceinline__ void mma16816(float* c, const uint32_t* a, const uint32_t* b)
{
    asm volatile(
        "mma.sync.aligned.m16n8k16.row.col.f32.bf16.bf16.f32 "
        "{%0,%1,%2,%3}, {%4,%5,%6,%7}, {%8,%9}, {%0,%1,%2,%3};"
        : "+f"(c[0]), "+f"(c[1]), "+f"(c[2]), "+f"(c[3])
        : "r"(a[0]), "r"(a[1]), "r"(a[2]), "r"(a[3]), "r"(b[0]), "r"(b[1]));
}
__device__ __forceinline__ void ldsm4(uint32_t& r0, uint32_t& r1, uint32_t& r2, uint32_t& r3,
                                      uint32_t addr)
{
    asm volatile("ldmatrix.sync.aligned.m8n8.x4.shared.b16 {%0,%1,%2,%3}, [%4];"
                 : "=r"(r0), "=r"(r1), "=r"(r2), "=r"(r3) : "r"(addr));
}
__device__ __forceinline__ void cp16(uint32_t saddr, const void* g)
{
    asm volatile("cp.async.cg.shared.global [%0], [%1], 16;"
                 :: "r"(saddr), "l"(g));
}
__device__ __forceinline__ uint32_t smem_u32(const void* p) {
    uint32_t a;
    asm("{ .reg .u64 t; cvta.to.shared.u64 t, %1; cvt.u32.u64 %0, t; }"
        : "=r"(a) : "l"(p));
    return a;
}
__device__ __forceinline__ void splitpack(float f0, float f1, uint32_t& hi, uint32_t& lo)
{
    __nv_bfloat16 h0 = __float2bfloat16_rn(f0);
    __nv_bfloat16 h1 = __float2bfloat16_rn(f1);
    __nv_bfloat162 hp = __halves2bfloat162(h0, h1);
    hi = *(uint32_t*)&hp;
    __nv_bfloat162 lp = __floats2bfloat162_rn(f0 - __bfloat162float(h0),
                                              f1 - __bfloat162float(h1));
    lo = *(uint32_t*)&lp;
}

// ---------------- split fp32 -> (bf16 hi, bf16 lo) ----------------
__global__ __launch_bounds__(256)
void split_hi_lo(const float* __restrict__ x,
                 __nv_bfloat16* __restrict__ hi,
                 __nv_bfloat16* __restrict__ lo, int n)
{
    int i = (blockIdx.x * 256 + threadIdx.x) * 4;
    if (i >= n) return;
    float4 v = *(const float4*)(x + i);
    __nv_bfloat16 h[4], l[4];
    float vv[4] = {v.x, v.y, v.z, v.w};
#pragma unroll
    for (int q = 0; q < 4; q++) {
        h[q] = __float2bfloat16_rn(vv[q]);
        l[q] = __float2bfloat16_rn(vv[q] - __bfloat162float(h[q]));
    }
    *(uint2*)(hi + i) = *(uint2*)h;
    *(uint2*)(lo + i) = *(uint2*)l;
}

// ---------------- transpose+split V (compact fp32 input, stride 1024) ----------------
__global__ __launch_bounds__(256)
void transpose_v_split(const float* __restrict__ vf,
                       __nv_bfloat16* __restrict__ vth, __nv_bfloat16* __restrict__ vtl)
{
    __shared__ float tile[32][33];
    int c0 = blockIdx.x * 32;
    int s0 = blockIdx.y * 32;
    int b  = blockIdx.z;
    int tx = threadIdx.x, ty = threadIdx.y;
#pragma unroll
    for (int i = 0; i < 32; i += 8)
        tile[ty + i][tx] = vf[(size_t)(b * Ss + s0 + ty + i) * Ee + c0 + tx];
    __syncthreads();
#pragma unroll
    for (int i = 0; i < 32; i += 8) {
        int ccol = c0 + ty + i, srow = s0 + tx;
        float v = tile[tx][ty + i];
        __nv_bfloat16 h = __float2bfloat16_rn(v);
        vth[(size_t)(b * Ee + ccol) * Ss + srow] = h;
        vtl[(size_t)(b * Ee + ccol) * Ss + srow] = __float2bfloat16_rn(v - __bfloat162float(h));
    }
}

// ---------------- transpose + split W ----------------
__global__ __launch_bounds__(256)
void transpose_split(const float* __restrict__ W,
                     __nv_bfloat16* __restrict__ Thi,
                     __nv_bfloat16* __restrict__ Tlo, int K, int N)
{
    __shared__ float tile[32][33];
    int n0 = blockIdx.x * 32, k0 = blockIdx.y * 32;
    int tx = threadIdx.x, ty = threadIdx.y;
#pragma unroll
    for (int i = 0; i < 32; i += 8)
        tile[ty + i][tx] = W[(size_t)(k0 + ty + i) * N + n0 + tx];
    __syncthreads();
#pragma unroll
    for (int i = 0; i < 32; i += 8) {
        int n = n0 + ty + i, k = k0 + tx;
        float v = tile[tx][ty + i];
        __nv_bfloat16 h = __float2bfloat16_rn(v);
        Thi[(size_t)n * K + k] = h;
        Tlo[(size_t)n * K + k] = __float2bfloat16_rn(v - __bfloat162float(h));
    }
}

// ---------------- split-bf16 GEMM (templated epilogue) ----------------
// FUSE=0: C = A@B^T + bias (fp32, stride N)
// FUSE=1: QKV epilogue — N-cols [0,1024) -> (qh,ql) split; [1024,2048) -> (kh,kl);
//         [2048,3072) -> vf fp32 compact (stride 1024). bias always applied first.
#define GBK      32
#define GSTRIDE  40
#define ROWB     (GSTRIDE * 2)
#define ARR_B    (128 * ROWB)
#define STAGE_B  (4 * ARR_B)
#define GEMM_SMEM (2 * STAGE_B)

template<bool FUSE>
__global__ __launch_bounds__(128, 2)
void gemm_mma(const __nv_bfloat16* __restrict__ Ahi, const __nv_bfloat16* __restrict__ Alo,
              const __nv_bfloat16* __restrict__ Bhi, const __nv_bfloat16* __restrict__ Blo,
              const float* __restrict__ bias, float* __restrict__ C, int N,
              __nv_bfloat16* __restrict__ qh, __nv_bfloat16* __restrict__ ql,
              __nv_bfloat16* __restrict__ kh, __nv_bfloat16* __restrict__ kl,
              float* __restrict__ vf)
{
    extern __shared__ char smem[];
    const uint32_t sb = smem_u32(smem);
    const int tid  = threadIdx.x;
    const int wid  = tid >> 5, lane = tid & 31;
    const int wm   = wid >> 1, wn = wid & 1;
    const int g    = lane >> 2, tig = lane & 3;
    const int bm   = blockIdx.y * 128, bn = blockIdx.x * 128;
    const int NC   = Kdim / GBK;

    const int qd = lane >> 3, il = lane & 7;
    const uint32_t offA = (uint32_t)((wm * 64 + il + (qd & 1) * 8) * ROWB + ((qd >> 1) * 8) * 2);
    const uint32_t offB = (uint32_t)((wn * 64 + il + (qd >> 1) * 8) * ROWB + ((qd & 1) * 8) * 2);

    float acc[4][8][4];
#pragma unroll
    for (int im = 0; im < 4; im++)
#pragma unroll
        for (int in = 0; in < 8; in++)
#pragma unroll
            for (int q = 0; q < 4; q++) acc[im][in][q] = 0.0f;

    auto prefetch = [&](int c, int st) {
#pragma unroll
        for (int i = 0; i < 16; i++) {
            int idx = tid + i * 128;
            int arr = idx >> 9;
            int e   = idx & 511;
            int row = e >> 2;
            int seg = e & 3;
            const __nv_bfloat16* gp;
            size_t koff = (size_t)c * GBK + seg * 8;
            if      (arr == 0) gp = Ahi + (size_t)(bm + row) * Kdim + koff;
            else if (arr == 1) gp = Alo + (size_t)(bm + row) * Kdim + koff;
            else if (arr == 2) gp = Bhi + (size_t)(bn + row) * Kdim + koff;
            else               gp = Blo + (size_t)(bn + row) * Kdim + koff;
            uint32_t sa = sb + st * STAGE_B + arr * ARR_B + row * ROWB + seg * 16;
            cp16(sa, gp);
        }
        asm volatile("cp.async.commit_group;");
    };

    prefetch(0, 0);

    for (int c = 0; c < NC; c++) {
        const int st = c & 1;
        if (c + 1 < NC) {
            prefetch(c + 1, (c + 1) & 1);
            asm volatile("cp.async.wait_group 1;");
        } else {
            asm volatile("cp.async.wait_group 0;");
        }
        __syncthreads();

        const uint32_t stb = sb + st * STAGE_B;

#pragma unroll
        for (int kk = 0; kk < GBK; kk += 16) {
            const uint32_t kb = (uint32_t)(kk * 2);
            uint32_t a[4][4], bh[8][2], bl[8][2];
#pragma unroll
            for (int p = 0; p < 4; p++)
                ldsm4(bh[2*p][0], bh[2*p][1], bh[2*p+1][0], bh[2*p+1][1],
                      stb + 2 * ARR_B + offB + p * (16 * ROWB) + kb);
#pragma unroll
            for (int im = 0; im < 4; im++)
                ldsm4(a[im][0], a[im][1], a[im][2], a[im][3],
                      stb + offA + im * (16 * ROWB) + kb);
#pragma unroll
            for (int im = 0; im < 4; im++)
#pragma unroll
                for (int in = 0; in < 8; in++)
                    mma16816(acc[im][in], a[im], bh[in]);
#pragma unroll
            for (int p = 0; p < 4; p++)
                ldsm4(bl[2*p][0], bl[2*p][1], bl[2*p+1][0], bl[2*p+1][1],
                      stb + 3 * ARR_B + offB + p * (16 * ROWB) + kb);
#pragma unroll
            for (int im = 0; im < 4; im++)
#pragma unroll
                for (int in = 0; in < 8; in++)
                    mma16816(acc[im][in], a[im], bl[in]);
#pragma unroll
            for (int im = 0; im < 4; im++)
                ldsm4(a[im][0], a[im][1], a[im][2], a[im][3],
                      stb + ARR_B + offA + im * (16 * ROWB) + kb);
#pragma unroll
            for (int im = 0; im < 4; im++)
#pragma unroll
                for (int in = 0; in < 8; in++)
                    mma16816(acc[im][in], a[im], bh[in]);
        }
        __syncthreads();
    }

    // epilogue
#pragma unroll
    for (int im = 0; im < 4; im++) {
        int r = bm + wm * 64 + im * 16 + g;
#pragma unroll
        for (int in = 0; in < 8; in++) {
            int ccol = bn + wn * 64 + in * 8 + 2 * tig;
            float2 b01 = *(const float2*)&bias[ccol];
            float2 o0 = make_float2(acc[im][in][0] + b01.x, acc[im][in][1] + b01.y);
            float2 o1 = make_float2(acc[im][in][2] + b01.x, acc[im][in][3] + b01.y);
            if (!FUSE) {
                *(float2*)&C[(size_t)r * N + ccol]       = o0;
                *(float2*)&C[(size_t)(r + 8) * N + ccol] = o1;
            } else {
                if (bn < 1024) {
                    int col = ccol;
                    uint32_t h0, l0, h1, l1;
                    splitpack(o0.x, o0.y, h0, l0);
                    splitpack(o1.x, o1.y, h1, l1);
                    *(uint32_t*)&qh[(size_t)r * 1024 + col]       = h0;
                    *(uint32_t*)&ql[(size_t)r * 1024 + col]       = l0;
                    *(uint32_t*)&qh[(size_t)(r + 8) * 1024 + col] = h1;
                    *(uint32_t*)&ql[(size_t)(r + 8) * 1024 + col] = l1;
                } else if (bn < 2048) {
                    int col = ccol - 1024;
                    uint32_t h0, l0, h1, l1;
                    splitpack(o0.x, o0.y, h0, l0);
                    splitpack(o1.x, o1.y, h1, l1);
                    *(uint32_t*)&kh[(size_t)r * 1024 + col]       = h0;
                    *(uint32_t*)&kl[(size_t)r * 1024 + col]       = l0;
                    *(uint32_t*)&kh[(size_t)(r + 8) * 1024 + col] = h1;
                    *(uint32_t*)&kl[(size_t)(r + 8) * 1024 + col] = l1;
                } else {
                    int col = ccol - 2048;
                    *(float2*)&vf[(size_t)r * 1024 + col]       = o0;
                    *(float2*)&vf[(size_t)(r + 8) * 1024 + col] = o1;
                }
            }
        }
    }
}

// ---------------- tensor-core flash attention: 3-stage cp.async + ldmatrix ----------------
#define AKVROW 144
#define AARR   9216
#define AST    36864
#define ATTN_SMEM (3 * AST)

__global__ __launch_bounds__(256, 1)
void attn_mma(const __nv_bfloat16* __restrict__ qh, const __nv_bfloat16* __restrict__ ql,
              const __nv_bfloat16* __restrict__ kh, const __nv_bfloat16* __restrict__ kl,
              const __nv_bfloat16* __restrict__ vth, const __nv_bfloat16* __restrict__ vtl,
              const int* __restrict__ mask,
              __nv_bfloat16* __restrict__ ohi, __nv_bfloat16* __restrict__ olo)
{
    extern __shared__ char asmem[];
    __shared__ int sMask[3][64];
    const uint32_t sb = smem_u32(asmem);
    const uint32_t mb = smem_u32(&sMask[0][0]);

    const int tid = threadIdx.x, wid = tid >> 5, lane = tid & 31;
    const int g = lane >> 2, tig = lane & 3;
    const int qd = lane >> 3, il = lane & 7;
    const uint32_t offKV = (uint32_t)((il + (qd >> 1) * 8) * AKVROW + ((qd & 1) * 8) * 2);

    const int qt = gridDim.x - 1 - blockIdx.x;   // heavy tiles launch first
    const int bh = blockIdx.y;
    const int b = bh >> 4, h = bh & 15;
    const int q0 = qt * 128;
    const int wrow = q0 + wid * 16;
    const float scale = 0.125f;

    // resident Q fragments
    uint32_t aqh[4][4], aql[4][4];
    {
        const __nv_bfloat16* qb  = qh + (size_t)(b * Ss + wrow) * Ee + h * 64;
        const __nv_bfloat16* qbl = ql + (size_t)(b * Ss + wrow) * Ee + h * 64;
#pragma unroll
        for (int s = 0; s < 4; s++) {
            int k0 = s * 16 + 2 * tig;
            aqh[s][0] = *(const uint32_t*)&qb [(size_t)(g    ) * Ee + k0];
            aqh[s][1] = *(const uint32_t*)&qb [(size_t)(g + 8) * Ee + k0];
            aqh[s][2] = *(const uint32_t*)&qb [(size_t)(g    ) * Ee + k0 + 8];
            aqh[s][3] = *(const uint32_t*)&qb [(size_t)(g + 8) * Ee + k0 + 8];
            aql[s][0] = *(const uint32_t*)&qbl[(size_t)(g    ) * Ee + k0];
            aql[s][1] = *(const uint32_t*)&qbl[(size_t)(g + 8) * Ee + k0];
            aql[s][2] = *(const uint32_t*)&qbl[(size_t)(g    ) * Ee + k0 + 8];
            aql[s][3] = *(const uint32_t*)&qbl[(size_t)(g + 8) * Ee + k0 + 8];
        }
    }

    auto prefetch = [&](int j) {
        const int kv0 = j * 64;
        const int st = j % 3;
        const uint32_t stb = sb + st * AST;
#pragma unroll
        for (int i = 0; i < 8; i++) {
            int idx = tid + i * 256;
            int arr = idx >> 9;
            int e   = idx & 511;
            int row = e >> 3;
            int segB = (e & 7) * 16;
            const __nv_bfloat16* gp;
            if      (arr == 0) gp = kh  + (size_t)(b * Ss + kv0 + row) * Ee + h * 64 + segB / 2;
            else if (arr == 1) gp = kl  + (size_t)(b * Ss + kv0 + row) * Ee + h * 64 + segB / 2;
            else if (arr == 2) gp = vth + (size_t)(b * Ee + h * 64 + row) * Ss + kv0 + segB / 2;
            else               gp = vtl + (size_t)(b * Ee + h * 64 + row) * Ss + kv0 + segB / 2;
            cp16(stb + arr * AARR + row * AKVROW + segB, gp);
        }
        if (tid < 16)
            cp16(mb + st * 256 + tid * 16, &mask[b * Ss + kv0 + tid * 4]);
        asm volatile("cp.async.commit_group;");
    };

    float m0 = -1e30f, m1 = -1e30f, l0 = 0.0f, l1 = 0.0f;
    float o[8][4];
#pragma unroll
    for (int t = 0; t < 8; t++)
#pragma unroll
        for (int e = 0; e < 4; e++) o[t][e] = 0.0f;

    const int row0 = wrow + g, row1 = wrow + 8 + g;
    const int ntiles = (qt + 1) * 2;

    prefetch(0);

    for (int j = 0; j < ntiles; j++) {
        const int kv0 = j * 64;
        const int st = j % 3;
        if (j + 1 < ntiles) {
            prefetch(j + 1);                   // writes buf (j+1)%3, last read at iter j-2 (barrier-ordered)
            asm volatile("cp.async.wait_group 1;");
        } else {
            asm volatile("cp.async.wait_group 0;");
        }
        __syncthreads();                       // all threads' stage-j data visible; no warp >1 iter behind

        const uint32_t stb = sb + st * AST;
        const int* msk = sMask[st];

        // ---- S = Q K^T (3-pass split) ----
        float c[8][4];
#pragma unroll
        for (int t = 0; t < 8; t++)
#pragma unroll
            for (int e = 0; e < 4; e++) c[t][e] = 0.0f;

#pragma unroll
        for (int s = 0; s < 4; s++) {
            const uint32_t kb = (uint32_t)(s * 32);
            uint32_t kf[8][2], lf[8][2];
#pragma unroll
            for (int p = 0; p < 4; p++)
                ldsm4(kf[2*p][0], kf[2*p][1], kf[2*p+1][0], kf[2*p+1][1],
                      stb + offKV + p * (16 * AKVROW) + kb);
#pragma unroll
            for (int p = 0; p < 4; p++)
                ldsm4(lf[2*p][0], lf[2*p][1], lf[2*p+1][0], lf[2*p+1][1],
                      stb + AARR + offKV + p * (16 * AKVROW) + kb);
#pragma unroll
            for (int t = 0; t < 8; t++) {
                mma16816(c[t], aqh[s], kf[t]);
                mma16816(c[t], aqh[s], lf[t]);
                mma16816(c[t], aql[s], kf[t]);
            }
        }

        // ---- scale + causal + key mask ----
#pragma unroll
        for (int t = 0; t < 8; t++) {
            int lc0 = t * 8 + 2 * tig;
            int col0 = kv0 + lc0, col1 = col0 + 1;
            bool v0 = msk[lc0] != 0, v1 = msk[lc0 + 1] != 0;
            c[t][0] = (v0 && col0 <= row0) ? c[t][0] * scale : -1e30f;
            c[t][1] = (v1 && col1 <= row0) ? c[t][1] * scale : -1e30f;
            c[t][2] = (v0 && col0 <= row1) ? c[t][2] * scale : -1e30f;
            c[t][3] = (v1 && col1 <= row1) ? c[t][3] * scale : -1e30f;
        }

        // ---- online softmax ----
        float ml0 = -1e30f, ml1 = -1e30f;
#pragma unroll
        for (int t = 0; t < 8; t++) {
            ml0 = fmaxf(ml0, fmaxf(c[t][0], c[t][1]));
            ml1 = fmaxf(ml1, fmaxf(c[t][2], c[t][3]));
        }
        ml0 = fmaxf(ml0, __shfl_xor_sync(0xffffffffu, ml0, 1));
        ml0 = fmaxf(ml0, __shfl_xor_sync(0xffffffffu, ml0, 2));
        ml1 = fmaxf(ml1, __shfl_xor_sync(0xffffffffu, ml1, 1));
        ml1 = fmaxf(ml1, __shfl_xor_sync(0xffffffffu, ml1, 2));

        float mn0 = fmaxf(m0, ml0), mn1 = fmaxf(m1, ml1);
        float alpha0 = __expf(m0 - mn0), alpha1 = __expf(m1 - mn1);
        m0 = mn0; m1 = mn1;

        float rs0 = 0.0f, rs1 = 0.0f;
#pragma unroll
        for (int t = 0; t < 8; t++) {
            c[t][0] = __expf(c[t][0] - m0); rs0 += c[t][0];
            c[t][1] = __expf(c[t][1] - m0); rs0 += c[t][1];
            c[t][2] = __expf(c[t][2] - m1); rs1 += c[t][2];
            c[t][3] = __expf(c[t][3] - m1); rs1 += c[t][3];
        }
        rs0 += __shfl_xor_sync(0xffffffffu, rs0, 1);
        rs0 += __shfl_xor_sync(0xffffffffu, rs0, 2);
        rs1 += __shfl_xor_sync(0xffffffffu, rs1, 1);
        rs1 += __shfl_xor_sync(0xffffffffu, rs1, 2);

        l0 = l0 * alpha0 + rs0;
        l1 = l1 * alpha1 + rs1;
#pragma unroll
        for (int t = 0; t < 8; t++) {
            o[t][0] *= alpha0; o[t][1] *= alpha0;
            o[t][2] *= alpha1; o[t][3] *= alpha1;
        }

        // ---- O += P V (3-pass) ----
#pragma unroll
        for (int s = 0; s < 4; s++) {
            uint32_t aph[4], apl[4];
            splitpack(c[2 * s][0],     c[2 * s][1],     aph[0], apl[0]);
            splitpack(c[2 * s][2],     c[2 * s][3],     aph[1], apl[1]);
            splitpack(c[2 * s + 1][0], c[2 * s + 1][1], aph[2], apl[2]);
            splitpack(c[2 * s + 1][2], c[2 * s + 1][3], aph[3], apl[3]);
            const uint32_t kb = (uint32_t)(s * 32);
            uint32_t vf2[8][2], wf[8][2];
#pragma unroll
            for (int p = 0; p < 4; p++)
                ldsm4(vf2[2*p][0], vf2[2*p][1], vf2[2*p+1][0], vf2[2*p+1][1],
                      stb + 2 * AARR + offKV + p * (16 * AKVROW) + kb);
#pragma unroll
            for (int p = 0; p < 4; p++)
                ldsm4(wf[2*p][0], wf[2*p][1], wf[2*p+1][0], wf[2*p+1][1],
                      stb + 3 * AARR + offKV + p * (16 * AKVROW) + kb);
#pragma unroll
            for (int t = 0; t < 8; t++) {
                mma16816(o[t], aph, vf2[t]);
                mma16816(o[t], aph, wf[t]);
                mma16816(o[t], apl, vf2[t]);
            }
        }
    }

    // epilogue: write bf16 split directly (proj GEMM input)
    float inv0 = 1.0f / l0, inv1 = 1.0f / l1;
    size_t base0 = (size_t)(b * Ss + row0) * Ee + h * 64;
    size_t base1 = (size_t)(b * Ss + row1) * Ee + h * 64;
#pragma unroll
    for (int t = 0; t < 8; t++) {
        int cc = t * 8 + 2 * tig;
        uint32_t hi0, lo0, hi1, lo1;
        splitpack(o[t][0] * inv0, o[t][1] * inv0, hi0, lo0);
        splitpack(o[t][2] * inv1, o[t][3] * inv1, hi1, lo1);
        *(uint32_t*)&ohi[base0 + cc] = hi0;
        *(uint32_t*)&olo[base0 + cc] = lo0;
        *(uint32_t*)&ohi[base1 + cc] = hi1;
        *(uint32_t*)&olo[base1 + cc] = lo1;
    }
}

// ---------------- launch ----------------
extern "C" void kernel_launch(void* const* d_in, const int* in_sizes, int n_in,
                              void* d_out, int out_size)
{
    const float* X     = (const float*)d_in[0];
    const int*   mask  = (const int*)  d_in[1];
    const float* Wqkv  = (const float*)d_in[2];
    const float* bqkv  = (const float*)d_in[3];
    const float* Wproj = (const float*)d_in[4];
    const float* bproj = (const float*)d_in[5];
    float* out = (float*)d_out;

    float *vf;
    __nv_bfloat16 *xhi, *xlo, *qh, *ql, *wqh, *wql, *wph, *wpl, *ahi, *alo, *vth, *vtl, *ohi, *olo;
    cudaGetSymbolAddress((void**)&vf,   g_vf);
    cudaGetSymbolAddress((void**)&xhi,  g_xhi);
    cudaGetSymbolAddress((void**)&xlo,  g_xlo);
    cudaGetSymbolAddress((void**)&qh,   g_qh);
    cudaGetSymbolAddress((void**)&ql,   g_ql);
    cudaGetSymbolAddress((void**)&wqh,  g_wqh);
    cudaGetSymbolAddress((void**)&wql,  g_wql);
    cudaGetSymbolAddress((void**)&wph,  g_wph);
    cudaGetSymbolAddress((void**)&wpl,  g_wpl);
    cudaGetSymbolAddress((void**)&ahi,  g_ahi);
    cudaGetSymbolAddress((void**)&alo,  g_alo);
    cudaGetSymbolAddress((void**)&vth,  g_vth);
    cudaGetSymbolAddress((void**)&vtl,  g_vtl);
    cudaGetSymbolAddress((void**)&ohi,  g_ohi);
    cudaGetSymbolAddress((void**)&olo,  g_olo);

    cudaFuncSetAttribute(gemm_mma<true>,  cudaFuncAttributeMaxDynamicSharedMemorySize, GEMM_SMEM);
    cudaFuncSetAttribute(gemm_mma<false>, cudaFuncAttributeMaxDynamicSharedMemorySize, GEMM_SMEM);
    cudaFuncSetAttribute(attn_mma, cudaFuncAttributeMaxDynamicSharedMemorySize, ATTN_SMEM);

    // prep: split X, transpose+split weights
    split_hi_lo<<<(MTOT * Ee) / 4 / 256, 256>>>(X, xhi, xlo, MTOT * Ee);
    {
        dim3 blk(32, 8);
        transpose_split<<<dim3(E3 / 32, Kdim / 32), blk>>>(Wqkv, wqh, wql, Kdim, E3);
        transpose_split<<<dim3(Ee / 32, Kdim / 32), blk>>>(Wproj, wph, wpl, Kdim, Ee);
    }

    // 1) QKV = X @ Wqkv + b, fused epilogue: Q/K split bf16, V compact fp32
    gemm_mma<true><<<dim3(E3 / 128, MTOT / 128), 128, GEMM_SMEM>>>(
        xhi, xlo, wqh, wql, bqkv, vf, E3, qh, ql, ahi, alo, vf);

    // 2) V transpose+split
    {
        dim3 blk(32, 8);
        transpose_v_split<<<dim3(Ee / 32, Ss / 32, Bb), blk>>>(vf, vth, vtl);
    }

    // 3) tensor-core flash attention (pipelined, writes split output directly)
    attn_mma<<<dim3(Ss / 128, Bb * Hh), 256, ATTN_SMEM>>>(qh, ql, ahi, alo, vth, vtl, mask, ohi, olo);

    // 4) out = attn @ Wproj + b
    gemm_mma<false><<<dim3(Ee / 128, MTOT / 128), 128, GEMM_SMEM>>>(
        ohi, olo, wph, wpl, bproj, out, Ee, qh, ql, ahi, alo, vf);
}

// round 10
// speedup vs baseline: 1.3394x; 1.0046x over previous
#include <cuda_runtime.h>
#include <cuda_bf16.h>
#include <cstdint>
#include <math.h>

// ---------------- problem constants ----------------
#define Bb   4
#define Ss   1024
#define Ee   1024
#define Hh   16
#define HDs  64
#define MTOT 4096      // B*S
#define E3   3072      // 3*E
#define Kdim 1024

// ---------------- scratch (device globals) ----------------
__device__ __nv_bfloat16  g_xhi [MTOT * Ee];     // X split (QKV GEMM A operand)
__device__ __nv_bfloat16  g_xlo [MTOT * Ee];
__device__ __nv_bfloat16  g_qh  [MTOT * Ee];     // Q split (fused epilogue)
__device__ __nv_bfloat16  g_ql  [MTOT * Ee];
__device__ __nv_bfloat16  g_kh  [MTOT * Ee];     // K split
__device__ __nv_bfloat16  g_kl  [MTOT * Ee];
__device__ __nv_bfloat16  g_vh  [MTOT * Ee];     // V split, row-major [s][hd] (trans-ldsm in attn)
__device__ __nv_bfloat16  g_vl  [MTOT * Ee];
__device__ __nv_bfloat16  g_wqh [E3 * Ee];       // Wqkv^T
__device__ __nv_bfloat16  g_wql [E3 * Ee];
__device__ __nv_bfloat16  g_wph [Ee * Ee];       // Wproj^T
__device__ __nv_bfloat16  g_wpl [Ee * Ee];
__device__ __nv_bfloat16  g_ohi [MTOT * Ee];     // attention output split (proj input)
__device__ __nv_bfloat16  g_olo [MTOT * Ee];

// ---------------- helpers ----------------
__device__ __forceinline__ void mma16816(float* c, const uint32_t* a, const uint32_t* b)
{
    asm volatile(
        "mma.sync.aligned.m16n8k16.row.col.f32.bf16.bf16.f32 "
        "{%0,%1,%2,%3}, {%4,%5,%6,%7}, {%8,%9}, {%0,%1,%2,%3};"
        : "+f"(c[0]), "+f"(c[1]), "+f"(c[2]), "+f"(c[3])
        : "r"(a[0]), "r"(a[1]), "r"(a[2]), "r"(a[3]), "r"(b[0]), "r"(b[1]));
}
__device__ __forceinline__ void ldsm4(uint32_t& r0, uint32_t& r1, uint32_t& r2, uint32_t& r3,
                                      uint32_t addr)
{
    asm volatile("ldmatrix.sync.aligned.m8n8.x4.shared.b16 {%0,%1,%2,%3}, [%4];"
                 : "=r"(r0), "=r"(r1), "=r"(r2), "=r"(r3) : "r"(addr));
}
__device__ __forceinline__ void ldsm4t(uint32_t& r0, uint32_t& r1, uint32_t& r2, uint32_t& r3,
                                       uint32_t addr)
{
    asm volatile("ldmatrix.sync.aligned.m8n8.x4.trans.shared.b16 {%0,%1,%2,%3}, [%4];"
                 : "=r"(r0), "=r"(r1), "=r"(r2), "=r"(r3) : "r"(addr));
}
__device__ __forceinline__ void cp16(uint32_t saddr, const void* g)
{
    asm volatile("cp.async.cg.shared.global [%0], [%1], 16;"
                 :: "r"(saddr), "l"(g));
}
__device__ __forceinline__ uint32_t smem_u32(const void* p) {
    uint32_t a;
    asm("{ .reg .u64 t; cvta.to.shared.u64 t, %1; cvt.u32.u64 %0, t; }"
        : "=r"(a) : "l"(p));
    return a;
}
__device__ __forceinline__ void splitpack(float f0, float f1, uint32_t& hi, uint32_t& lo)
{
    __nv_bfloat16 h0 = __float2bfloat16_rn(f0);
    __nv_bfloat16 h1 = __float2bfloat16_rn(f1);
    __nv_bfloat162 hp = __halves2bfloat162(h0, h1);
    hi = *(uint32_t*)&hp;
    __nv_bfloat162 lp = __floats2bfloat162_rn(f0 - __bfloat162float(h0),
                                              f1 - __bfloat162float(h1));
    lo = *(uint32_t*)&lp;
}

// ---------------- split fp32 -> (bf16 hi, bf16 lo) ----------------
__global__ __launch_bounds__(256)
void split_hi_lo(const float* __restrict__ x,
                 __nv_bfloat16* __restrict__ hi,
                 __nv_bfloat16* __restrict__ lo, int n)
{
    int i = (blockIdx.x * 256 + threadIdx.x) * 4;
    if (i >= n) return;
    float4 v = *(const float4*)(x + i);
    __nv_bfloat16 h[4], l[4];
    float vv[4] = {v.x, v.y, v.z, v.w};
#pragma unroll
    for (int q = 0; q < 4; q++) {
        h[q] = __float2bfloat16_rn(vv[q]);
        l[q] = __float2bfloat16_rn(vv[q] - __bfloat162float(h[q]));
    }
    *(uint2*)(hi + i) = *(uint2*)h;
    *(uint2*)(lo + i) = *(uint2*)l;
}

// ---------------- transpose + split W ----------------
__global__ __launch_bounds__(256)
void transpose_split(const float* __restrict__ W,
                     __nv_bfloat16* __restrict__ Thi,
                     __nv_bfloat16* __restrict__ Tlo, int K, int N)
{
    __shared__ float tile[32][33];
    int n0 = blockIdx.x * 32, k0 = blockIdx.y * 32;
    int tx = threadIdx.x, ty = threadIdx.y;
#pragma unroll
    for (int i = 0; i < 32; i += 8)
        tile[ty + i][tx] = W[(size_t)(k0 + ty + i) * N + n0 + tx];
    __syncthreads();
#pragma unroll
    for (int i = 0; i < 32; i += 8) {
        int n = n0 + ty + i, k = k0 + tx;
        float v = tile[tx][ty + i];
        __nv_bfloat16 h = __float2bfloat16_rn(v);
        Thi[(size_t)n * K + k] = h;
        Tlo[(size_t)n * K + k] = __float2bfloat16_rn(v - __bfloat162float(h));
    }
}

// ---------------- split-bf16 GEMM (templated epilogue) ----------------
// FUSE=0: C = A@B^T + bias (fp32, stride N)
// FUSE=1: QKV epilogue — all N-sections written as split bf16 (compact stride 1024):
//         [0,1024)->qh/ql, [1024,2048)->kh/kl, [2048,3072)->vh/vl.
#define GBK      32
#define GSTRIDE  40
#define ROWB     (GSTRIDE * 2)
#define ARR_B    (128 * ROWB)
#define STAGE_B  (4 * ARR_B)
#define GEMM_SMEM (2 * STAGE_B)

template<bool FUSE>
__global__ __launch_bounds__(128, 2)
void gemm_mma(const __nv_bfloat16* __restrict__ Ahi, const __nv_bfloat16* __restrict__ Alo,
              const __nv_bfloat16* __restrict__ Bhi, const __nv_bfloat16* __restrict__ Blo,
              const float* __restrict__ bias, float* __restrict__ C, int N,
              __nv_bfloat16* __restrict__ qh, __nv_bfloat16* __restrict__ ql,
              __nv_bfloat16* __restrict__ kh, __nv_bfloat16* __restrict__ kl,
              __nv_bfloat16* __restrict__ vh, __nv_bfloat16* __restrict__ vl)
{
    extern __shared__ char smem[];
    const uint32_t sb = smem_u32(smem);
    const int tid  = threadIdx.x;
    const int wid  = tid >> 5, lane = tid & 31;
    const int wm   = wid >> 1, wn = wid & 1;
    const int g    = lane >> 2, tig = lane & 3;
    const int bm   = blockIdx.y * 128, bn = blockIdx.x * 128;
    const int NC   = Kdim / GBK;

    const int qd = lane >> 3, il = lane & 7;
    const uint32_t offA = (uint32_t)((wm * 64 + il + (qd & 1) * 8) * ROWB + ((qd >> 1) * 8) * 2);
    const uint32_t offB = (uint32_t)((wn * 64 + il + (qd >> 1) * 8) * ROWB + ((qd & 1) * 8) * 2);

    float acc[4][8][4];
#pragma unroll
    for (int im = 0; im < 4; im++)
#pragma unroll
        for (int in = 0; in < 8; in++)
#pragma unroll
            for (int q = 0; q < 4; q++) acc[im][in][q] = 0.0f;

    auto prefetch = [&](int c, int st) {
#pragma unroll
        for (int i = 0; i < 16; i++) {
            int idx = tid + i * 128;
            int arr = idx >> 9;
            int e   = idx & 511;
            int row = e >> 2;
            int seg = e & 3;
            const __nv_bfloat16* gp;
            size_t koff = (size_t)c * GBK + seg * 8;
            if      (arr == 0) gp = Ahi + (size_t)(bm + row) * Kdim + koff;
            else if (arr == 1) gp = Alo + (size_t)(bm + row) * Kdim + koff;
            else if (arr == 2) gp = Bhi + (size_t)(bn + row) * Kdim + koff;
            else               gp = Blo + (size_t)(bn + row) * Kdim + koff;
            uint32_t sa = sb + st * STAGE_B + arr * ARR_B + row * ROWB + seg * 16;
            cp16(sa, gp);
        }
        asm volatile("cp.async.commit_group;");
    };

    prefetch(0, 0);

    for (int c = 0; c < NC; c++) {
        const int st = c & 1;
        if (c + 1 < NC) {
            prefetch(c + 1, (c + 1) & 1);
            asm volatile("cp.async.wait_group 1;");
        } else {
            asm volatile("cp.async.wait_group 0;");
        }
        __syncthreads();

        const uint32_t stb = sb + st * STAGE_B;

#pragma unroll
        for (int kk = 0; kk < GBK; kk += 16) {
            const uint32_t kb = (uint32_t)(kk * 2);
            uint32_t a[4][4], bh[8][2], bl[8][2];
#pragma unroll
            for (int p = 0; p < 4; p++)
                ldsm4(bh[2*p][0], bh[2*p][1], bh[2*p+1][0], bh[2*p+1][1],
                      stb + 2 * ARR_B + offB + p * (16 * ROWB) + kb);
#pragma unroll
            for (int im = 0; im < 4; im++)
                ldsm4(a[im][0], a[im][1], a[im][2], a[im][3],
                      stb + offA + im * (16 * ROWB) + kb);
#pragma unroll
            for (int im = 0; im < 4; im++)
#pragma unroll
                for (int in = 0; in < 8; in++)
                    mma16816(acc[im][in], a[im], bh[in]);
#pragma unroll
            for (int p = 0; p < 4; p++)
                ldsm4(bl[2*p][0], bl[2*p][1], bl[2*p+1][0], bl[2*p+1][1],
                      stb + 3 * ARR_B + offB + p * (16 * ROWB) + kb);
#pragma unroll
            for (int im = 0; im < 4; im++)
#pragma unroll
                for (int in = 0; in < 8; in++)
                    mma16816(acc[im][in], a[im], bl[in]);
#pragma unroll
            for (int im = 0; im < 4; im++)
                ldsm4(a[im][0], a[im][1], a[im][2], a[im][3],
                      stb + ARR_B + offA + im * (16 * ROWB) + kb);
#pragma unroll
            for (int im = 0; im < 4; im++)
#pragma unroll
                for (int in = 0; in < 8; in++)
                    mma16816(acc[im][in], a[im], bh[in]);
        }
        __syncthreads();
    }

    // epilogue
    __nv_bfloat16 *dh = qh, *dl = ql;
    if (FUSE) {
        int sec = bn >> 10;                 // uniform per CTA
        if (sec == 1) { dh = kh; dl = kl; }
        else if (sec == 2) { dh = vh; dl = vl; }
    }
#pragma unroll
    for (int im = 0; im < 4; im++) {
        int r = bm + wm * 64 + im * 16 + g;
#pragma unroll
        for (int in = 0; in < 8; in++) {
            int ccol = bn + wn * 64 + in * 8 + 2 * tig;
            float2 b01 = *(const float2*)&bias[ccol];
            float2 o0 = make_float2(acc[im][in][0] + b01.x, acc[im][in][1] + b01.y);
            float2 o1 = make_float2(acc[im][in][2] + b01.x, acc[im][in][3] + b01.y);
            if (!FUSE) {
                *(float2*)&C[(size_t)r * N + ccol]       = o0;
                *(float2*)&C[(size_t)(r + 8) * N + ccol] = o1;
            } else {
                int col = ccol & 1023;
                uint32_t h0, l0, h1, l1;
                splitpack(o0.x, o0.y, h0, l0);
                splitpack(o1.x, o1.y, h1, l1);
                *(uint32_t*)&dh[(size_t)r * 1024 + col]       = h0;
                *(uint32_t*)&dl[(size_t)r * 1024 + col]       = l0;
                *(uint32_t*)&dh[(size_t)(r + 8) * 1024 + col] = h1;
                *(uint32_t*)&dl[(size_t)(r + 8) * 1024 + col] = l1;
            }
        }
    }
}

// ---------------- tensor-core flash attention: 3-stage cp.async + ldmatrix ----------------
// Stage: Kh, Kl, Vh, Vl each [64 rows][72 bf16] (144 B rows), all row-major [kv][hd].
// V fragments come via ldmatrix.trans (in-register transpose) — no V^T scratch needed.
#define AKVROW 144
#define AARR   9216
#define AST    36864
#define ATTN_SMEM (3 * AST)

__global__ __launch_bounds__(256, 1)
void attn_mma(const __nv_bfloat16* __restrict__ qh, const __nv_bfloat16* __restrict__ ql,
              const __nv_bfloat16* __restrict__ kh, const __nv_bfloat16* __restrict__ kl,
              const __nv_bfloat16* __restrict__ vh, const __nv_bfloat16* __restrict__ vl,
              const int* __restrict__ mask,
              __nv_bfloat16* __restrict__ ohi, __nv_bfloat16* __restrict__ olo)
{
    extern __shared__ char asmem[];
    __shared__ int sMask[3][64];
    const uint32_t sb = smem_u32(asmem);
    const uint32_t mb = smem_u32(&sMask[0][0]);

    const int tid = threadIdx.x, wid = tid >> 5, lane = tid & 31;
    const int g = lane >> 2, tig = lane & 3;
    const int qd = lane >> 3, il = lane & 7;
    // K (non-trans, [n=kv][k=hd]): quadrant (qd>>1)->+8 n-rows, (qd&1)->+8 k-cols
    const uint32_t offKV  = (uint32_t)((il + (qd >> 1) * 8) * AKVROW + ((qd & 1) * 8) * 2);
    // V (trans, [k=kv][n=hd]): quadrant (qd&1)->+8 k-rows, (qd>>1)->+8 n-cols
    const uint32_t offKVt = (uint32_t)((il + (qd & 1) * 8) * AKVROW + ((qd >> 1) * 8) * 2);

    const int qt = gridDim.x - 1 - blockIdx.x;   // heavy tiles launch first
    const int bh = blockIdx.y;
    const int b = bh >> 4, h = bh & 15;
    const int q0 = qt * 128;
    const int wrow = q0 + wid * 16;
    const float scale = 0.125f;

    // resident Q fragments
    uint32_t aqh[4][4], aql[4][4];
    {
        const __nv_bfloat16* qb  = qh + (size_t)(b * Ss + wrow) * Ee + h * 64;
        const __nv_bfloat16* qbl = ql + (size_t)(b * Ss + wrow) * Ee + h * 64;
#pragma unroll
        for (int s = 0; s < 4; s++) {
            int k0 = s * 16 + 2 * tig;
            aqh[s][0] = *(const uint32_t*)&qb [(size_t)(g    ) * Ee + k0];
            aqh[s][1] = *(const uint32_t*)&qb [(size_t)(g + 8) * Ee + k0];
            aqh[s][2] = *(const uint32_t*)&qb [(size_t)(g    ) * Ee + k0 + 8];
            aqh[s][3] = *(const uint32_t*)&qb [(size_t)(g + 8) * Ee + k0 + 8];
            aql[s][0] = *(const uint32_t*)&qbl[(size_t)(g    ) * Ee + k0];
            aql[s][1] = *(const uint32_t*)&qbl[(size_t)(g + 8) * Ee + k0];
            aql[s][2] = *(const uint32_t*)&qbl[(size_t)(g    ) * Ee + k0 + 8];
            aql[s][3] = *(const uint32_t*)&qbl[(size_t)(g + 8) * Ee + k0 + 8];
        }
    }

    auto prefetch = [&](int j) {
        const int kv0 = j * 64;
        const int st = j % 3;
        const uint32_t stb = sb + st * AST;
#pragma unroll
        for (int i = 0; i < 8; i++) {
            int idx = tid + i * 256;
            int arr = idx >> 9;
            int e   = idx & 511;
            int row = e >> 3;
            int segB = (e & 7) * 16;
            const __nv_bfloat16* gp;
            if      (arr == 0) gp = kh + (size_t)(b * Ss + kv0 + row) * Ee + h * 64 + segB / 2;
            else if (arr == 1) gp = kl + (size_t)(b * Ss + kv0 + row) * Ee + h * 64 + segB / 2;
            else if (arr == 2) gp = vh + (size_t)(b * Ss + kv0 + row) * Ee + h * 64 + segB / 2;
            else               gp = vl + (size_t)(b * Ss + kv0 + row) * Ee + h * 64 + segB / 2;
            cp16(stb + arr * AARR + row * AKVROW + segB, gp);
        }
        if (tid < 16)
            cp16(mb + st * 256 + tid * 16, &mask[b * Ss + kv0 + tid * 4]);
        asm volatile("cp.async.commit_group;");
    };

    float m0 = -1e30f, m1 = -1e30f, l0 = 0.0f, l1 = 0.0f;
    float o[8][4];
#pragma unroll
    for (int t = 0; t < 8; t++)
#pragma unroll
        for (int e = 0; e < 4; e++) o[t][e] = 0.0f;

    const int row0 = wrow + g, row1 = wrow + 8 + g;
    const int ntiles = (qt + 1) * 2;

    prefetch(0);

    for (int j = 0; j < ntiles; j++) {
        const int kv0 = j * 64;
        const int st = j % 3;
        if (j + 1 < ntiles) {
            prefetch(j + 1);                   // writes buf (j+1)%3, last read at iter j-2 (barrier-ordered)
            asm volatile("cp.async.wait_group 1;");
        } else {
            asm volatile("cp.async.wait_group 0;");
        }
        __syncthreads();

        const uint32_t stb = sb + st * AST;
        const int* msk = sMask[st];

        // ---- S = Q K^T (3-pass split) ----
        float c[8][4];
#pragma unroll
        for (int t = 0; t < 8; t++)
#pragma unroll
            for (int e = 0; e < 4; e++) c[t][e] = 0.0f;

#pragma unroll
        for (int s = 0; s < 4; s++) {
            const uint32_t kb = (uint32_t)(s * 32);
            uint32_t kf[8][2], lf[8][2];
#pragma unroll
            for (int p = 0; p < 4; p++)
                ldsm4(kf[2*p][0], kf[2*p][1], kf[2*p+1][0], kf[2*p+1][1],
                      stb + offKV + p * (16 * AKVROW) + kb);
#pragma unroll
            for (int p = 0; p < 4; p++)
                ldsm4(lf[2*p][0], lf[2*p][1], lf[2*p+1][0], lf[2*p+1][1],
                      stb + AARR + offKV + p * (16 * AKVROW) + kb);
#pragma unroll
            for (int t = 0; t < 8; t++) {
                mma16816(c[t], aqh[s], kf[t]);
                mma16816(c[t], aqh[s], lf[t]);
                mma16816(c[t], aql[s], kf[t]);
            }
        }

        // ---- scale + causal + key mask ----
#pragma unroll
        for (int t = 0; t < 8; t++) {
            int lc0 = t * 8 + 2 * tig;
            int col0 = kv0 + lc0, col1 = col0 + 1;
            bool v0 = msk[lc0] != 0, v1 = msk[lc0 + 1] != 0;
            c[t][0] = (v0 && col0 <= row0) ? c[t][0] * scale : -1e30f;
            c[t][1] = (v1 && col1 <= row0) ? c[t][1] * scale : -1e30f;
            c[t][2] = (v0 && col0 <= row1) ? c[t][2] * scale : -1e30f;
            c[t][3] = (v1 && col1 <= row1) ? c[t][3] * scale : -1e30f;
        }

        // ---- online softmax ----
        float ml0 = -1e30f, ml1 = -1e30f;
#pragma unroll
        for (int t = 0; t < 8; t++) {
            ml0 = fmaxf(ml0, fmaxf(c[t][0], c[t][1]));
            ml1 = fmaxf(ml1, fmaxf(c[t][2], c[t][3]));
        }
        ml0 = fmaxf(ml0, __shfl_xor_sync(0xffffffffu, ml0, 1));
        ml0 = fmaxf(ml0, __shfl_xor_sync(0xffffffffu, ml0, 2));
        ml1 = fmaxf(ml1, __shfl_xor_sync(0xffffffffu, ml1, 1));
        ml1 = fmaxf(ml1, __shfl_xor_sync(0xffffffffu, ml1, 2));

        float mn0 = fmaxf(m0, ml0), mn1 = fmaxf(m1, ml1);
        float alpha0 = __expf(m0 - mn0), alpha1 = __expf(m1 - mn1);
        m0 = mn0; m1 = mn1;

        float rs0 = 0.0f, rs1 = 0.0f;
#pragma unroll
        for (int t = 0; t < 8; t++) {
            c[t][0] = __expf(c[t][0] - m0); rs0 += c[t][0];
            c[t][1] = __expf(c[t][1] - m0); rs0 += c[t][1];
            c[t][2] = __expf(c[t][2] - m1); rs1 += c[t][2];
            c[t][3] = __expf(c[t][3] - m1); rs1 += c[t][3];
        }
        rs0 += __shfl_xor_sync(0xffffffffu, rs0, 1);
        rs0 += __shfl_xor_sync(0xffffffffu, rs0, 2);
        rs1 += __shfl_xor_sync(0xffffffffu, rs1, 1);
        rs1 += __shfl_xor_sync(0xffffffffu, rs1, 2);

        l0 = l0 * alpha0 + rs0;
        l1 = l1 * alpha1 + rs1;
#pragma unroll
        for (int t = 0; t < 8; t++) {
            o[t][0] *= alpha0; o[t][1] *= alpha0;
            o[t][2] *= alpha1; o[t][3] *= alpha1;
        }

        // ---- O += P V (3-pass), V frags via ldmatrix.trans from row-major [kv][hd] ----
#pragma unroll
        for (int s = 0; s < 4; s++) {
            uint32_t aph[4], apl[4];
            splitpack(c[2 * s][0],     c[2 * s][1],     aph[0], apl[0]);
            splitpack(c[2 * s][2],     c[2 * s][3],     aph[1], apl[1]);
            splitpack(c[2 * s + 1][0], c[2 * s + 1][1], aph[2], apl[2]);
            splitpack(c[2 * s + 1][2], c[2 * s + 1][3], aph[3], apl[3]);
            const uint32_t krow = (uint32_t)(s * 16 * AKVROW);   // k = kv rows
            uint32_t vf2[8][2], wf[8][2];
#pragma unroll
            for (int p = 0; p < 4; p++)
                ldsm4t(vf2[2*p][0], vf2[2*p][1], vf2[2*p+1][0], vf2[2*p+1][1],
                       stb + 2 * AARR + offKVt + krow + p * 32);
#pragma unroll
            for (int p = 0; p < 4; p++)
                ldsm4t(wf[2*p][0], wf[2*p][1], wf[2*p+1][0], wf[2*p+1][1],
                       stb + 3 * AARR + offKVt + krow + p * 32);
#pragma unroll
            for (int t = 0; t < 8; t++) {
                mma16816(o[t], aph, vf2[t]);
                mma16816(o[t], aph, wf[t]);
                mma16816(o[t], apl, vf2[t]);
            }
        }
    }

    // epilogue: write bf16 split directly (proj GEMM input)
    float inv0 = 1.0f / l0, inv1 = 1.0f / l1;
    size_t base0 = (size_t)(b * Ss + row0) * Ee + h * 64;
    size_t base1 = (size_t)(b * Ss + row1) * Ee + h * 64;
#pragma unroll
    for (int t = 0; t < 8; t++) {
        int cc = t * 8 + 2 * tig;
        uint32_t hi0, lo0, hi1, lo1;
        splitpack(o[t][0] * inv0, o[t][1] * inv0, hi0, lo0);
        splitpack(o[t][2] * inv1, o[t][3] * inv1, hi1, lo1);
        *(uint32_t*)&ohi[base0 + cc] = hi0;
        *(uint32_t*)&olo[base0 + cc] = lo0;
        *(uint32_t*)&ohi[base1 + cc] = hi1;
        *(uint32_t*)&olo[base1 + cc] = lo1;
    }
}

// ---------------- launch ----------------
extern "C" void kernel_launch(void* const* d_in, const int* in_sizes, int n_in,
                              void* d_out, int out_size)
{
    const float* X     = (const float*)d_in[0];
    const int*   mask  = (const int*)  d_in[1];
    const float* Wqkv  = (const float*)d_in[2];
    const float* bqkv  = (const float*)d_in[3];
    const float* Wproj = (const float*)d_in[4];
    const float* bproj = (const float*)d_in[5];
    float* out = (float*)d_out;

    __nv_bfloat16 *xhi, *xlo, *qh, *ql, *kh, *kl, *vh, *vl, *wqh, *wql, *wph, *wpl, *ohi, *olo;
    cudaGetSymbolAddress((void**)&xhi,  g_xhi);
    cudaGetSymbolAddress((void**)&xlo,  g_xlo);
    cudaGetSymbolAddress((void**)&qh,   g_qh);
    cudaGetSymbolAddress((void**)&ql,   g_ql);
    cudaGetSymbolAddress((void**)&kh,   g_kh);
    cudaGetSymbolAddress((void**)&kl,   g_kl);
    cudaGetSymbolAddress((void**)&vh,   g_vh);
    cudaGetSymbolAddress((void**)&vl,   g_vl);
    cudaGetSymbolAddress((void**)&wqh,  g_wqh);
    cudaGetSymbolAddress((void**)&wql,  g_wql);
    cudaGetSymbolAddress((void**)&wph,  g_wph);
    cudaGetSymbolAddress((void**)&wpl,  g_wpl);
    cudaGetSymbolAddress((void**)&ohi,  g_ohi);
    cudaGetSymbolAddress((void**)&olo,  g_olo);

    cudaFuncSetAttribute(gemm_mma<true>,  cudaFuncAttributeMaxDynamicSharedMemorySize, GEMM_SMEM);
    cudaFuncSetAttribute(gemm_mma<false>, cudaFuncAttributeMaxDynamicSharedMemorySize, GEMM_SMEM);
    cudaFuncSetAttribute(attn_mma, cudaFuncAttributeMaxDynamicSharedMemorySize, ATTN_SMEM);

    // prep: split X, transpose+split weights
    split_hi_lo<<<(MTOT * Ee) / 4 / 256, 256>>>(X, xhi, xlo, MTOT * Ee);
    {
        dim3 blk(32, 8);
        transpose_split<<<dim3(E3 / 32, Kdim / 32), blk>>>(Wqkv, wqh, wql, Kdim, E3);
        transpose_split<<<dim3(Ee / 32, Kdim / 32), blk>>>(Wproj, wph, wpl, Kdim, Ee);
    }

    // 1) QKV = X @ Wqkv + b, fused epilogue: Q/K/V all written as split bf16
    gemm_mma<true><<<dim3(E3 / 128, MTOT / 128), 128, GEMM_SMEM>>>(
        xhi, xlo, wqh, wql, bqkv, nullptr, E3, qh, ql, kh, kl, vh, vl);

    // 2) tensor-core flash attention (pipelined; V transposed in-register via ldmatrix.trans)
    attn_mma<<<dim3(Ss / 128, Bb * Hh), 256, ATTN_SMEM>>>(qh, ql, kh, kl, vh, vl, mask, ohi, olo);

    // 3) out = attn @ Wproj + b
    gemm_mma<false><<<dim3(Ee / 128, MTOT / 128), 128, GEMM_SMEM>>>(
        ohi, olo, wph, wpl, bproj, out, Ee, qh, ql, kh, kl, vh, vl);
}

// round 11
// speedup vs baseline: 1.8321x; 1.3678x over previous
#include <cuda_runtime.h>
#include <cuda_fp16.h>
#include <cstdint>
#include <math.h>

// ---------------- problem constants ----------------
#define Bb   4
#define Ss   1024
#define Ee   1024
#define Hh   16
#define HDs  64
#define MTOT 4096      // B*S
#define E3   3072      // 3*E
#define Kdim 1024

// ---------------- scratch (device globals, fp16) ----------------
__device__ __half  g_xh  [MTOT * Ee];     // X as fp16 (QKV GEMM A operand, single)
__device__ __half  g_qh  [MTOT * Ee];     // Q fp16 (fused epilogue, single)
__device__ __half  g_kh  [MTOT * Ee];     // K split hi
__device__ __half  g_kl  [MTOT * Ee];     // K split lo
__device__ __half  g_vh  [MTOT * Ee];     // V split hi, row-major [s][hd]
__device__ __half  g_vl  [MTOT * Ee];     // V split lo
__device__ __half  g_wqh [E3 * Ee];       // Wqkv^T split
__device__ __half  g_wql [E3 * Ee];
__device__ __half  g_wph [Ee * Ee];       // Wproj^T split
__device__ __half  g_wpl [Ee * Ee];
__device__ __half  g_oh  [MTOT * Ee];     // attention output fp16 (proj A operand, single)

// ---------------- helpers ----------------
__device__ __forceinline__ void mma16816(float* c, const uint32_t* a, const uint32_t* b)
{
    asm volatile(
        "mma.sync.aligned.m16n8k16.row.col.f32.f16.f16.f32 "
        "{%0,%1,%2,%3}, {%4,%5,%6,%7}, {%8,%9}, {%0,%1,%2,%3};"
        : "+f"(c[0]), "+f"(c[1]), "+f"(c[2]), "+f"(c[3])
        : "r"(a[0]), "r"(a[1]), "r"(a[2]), "r"(a[3]), "r"(b[0]), "r"(b[1]));
}
__device__ __forceinline__ void ldsm4(uint32_t& r0, uint32_t& r1, uint32_t& r2, uint32_t& r3,
                                      uint32_t addr)
{
    asm volatile("ldmatrix.sync.aligned.m8n8.x4.shared.b16 {%0,%1,%2,%3}, [%4];"
                 : "=r"(r0), "=r"(r1), "=r"(r2), "=r"(r3) : "r"(addr));
}
__device__ __forceinline__ void ldsm4t(uint32_t& r0, uint32_t& r1, uint32_t& r2, uint32_t& r3,
                                       uint32_t addr)
{
    asm volatile("ldmatrix.sync.aligned.m8n8.x4.trans.shared.b16 {%0,%1,%2,%3}, [%4];"
                 : "=r"(r0), "=r"(r1), "=r"(r2), "=r"(r3) : "r"(addr));
}
__device__ __forceinline__ void cp16(uint32_t saddr, const void* g)
{
    asm volatile("cp.async.cg.shared.global [%0], [%1], 16;"
                 :: "r"(saddr), "l"(g));
}
__device__ __forceinline__ uint32_t smem_u32(const void* p) {
    uint32_t a;
    asm("{ .reg .u64 t; cvta.to.shared.u64 t, %1; cvt.u32.u64 %0, t; }"
        : "=r"(a) : "l"(p));
    return a;
}
__device__ __forceinline__ uint32_t pack2h(float f0, float f1)
{
    __half2 p = __floats2half2_rn(f0, f1);
    return *(uint32_t*)&p;
}
__device__ __forceinline__ void splitpack_h(float f0, float f1, uint32_t& hi, uint32_t& lo)
{
    __half h0 = __float2half_rn(f0);
    __half h1 = __float2half_rn(f1);
    __half2 hp = __halves2half2(h0, h1);
    hi = *(uint32_t*)&hp;
    __half2 lp = __floats2half2_rn(f0 - __half2float(h0), f1 - __half2float(h1));
    lo = *(uint32_t*)&lp;
}

// ---------------- fp32 -> fp16 convert ----------------
__global__ __launch_bounds__(256)
void to_half(const float* __restrict__ x, __half* __restrict__ h, int n)
{
    int i = (blockIdx.x * 256 + threadIdx.x) * 4;
    if (i >= n) return;
    float4 v = *(const float4*)(x + i);
    __half hh[4] = {__float2half_rn(v.x), __float2half_rn(v.y),
                    __float2half_rn(v.z), __float2half_rn(v.w)};
    *(uint2*)(h + i) = *(uint2*)hh;
}

// ---------------- transpose + split W: W[K][N] -> T_hi/lo[N][K] (fp16) ----------------
__global__ __launch_bounds__(256)
void transpose_split(const float* __restrict__ W,
                     __half* __restrict__ Thi, __half* __restrict__ Tlo, int K, int N)
{
    __shared__ float tile[32][33];
    int n0 = blockIdx.x * 32, k0 = blockIdx.y * 32;
    int tx = threadIdx.x, ty = threadIdx.y;
#pragma unroll
    for (int i = 0; i < 32; i += 8)
        tile[ty + i][tx] = W[(size_t)(k0 + ty + i) * N + n0 + tx];
    __syncthreads();
#pragma unroll
    for (int i = 0; i < 32; i += 8) {
        int n = n0 + ty + i, k = k0 + tx;
        float v = tile[tx][ty + i];
        __half h = __float2half_rn(v);
        Thi[(size_t)n * K + k] = h;
        Tlo[(size_t)n * K + k] = __float2half_rn(v - __half2float(h));
    }
}

// ---------------- fp16 2-pass GEMM: C = A @ (Bh+Bl)^T + bias ----------------
// FUSE=0: C fp32 out. FUSE=1: QKV epilogue — sec0 -> qh (fp16 single);
//         sec1 -> kh/kl split; sec2 -> vh/vl split (all compact stride 1024).
#define GBK      32
#define GSTRIDE  40
#define ROWB     (GSTRIDE * 2)
#define ARR_B    (128 * ROWB)              // 10240 B
#define STAGE_B  (3 * ARR_B)               // A, Bh, Bl
#define GEMM_SMEM (2 * STAGE_B)            // 61440 B

template<bool FUSE>
__global__ __launch_bounds__(128, 2)
void gemm_mma(const __half* __restrict__ A,
              const __half* __restrict__ Bhi, const __half* __restrict__ Blo,
              const float* __restrict__ bias, float* __restrict__ C, int N,
              __half* __restrict__ qh,
              __half* __restrict__ kh, __half* __restrict__ kl,
              __half* __restrict__ vh, __half* __restrict__ vl)
{
    extern __shared__ char smem[];
    const uint32_t sb = smem_u32(smem);
    const int tid  = threadIdx.x;
    const int wid  = tid >> 5, lane = tid & 31;
    const int wm   = wid >> 1, wn = wid & 1;          // warp grid 2x2, tile 64x64
    const int g    = lane >> 2, tig = lane & 3;
    const int bm   = blockIdx.y * 128, bn = blockIdx.x * 128;
    const int NC   = Kdim / GBK;

    const int qd = lane >> 3, il = lane & 7;
    const uint32_t offA = (uint32_t)((wm * 64 + il + (qd & 1) * 8) * ROWB + ((qd >> 1) * 8) * 2);
    const uint32_t offB = (uint32_t)((wn * 64 + il + (qd >> 1) * 8) * ROWB + ((qd & 1) * 8) * 2);

    float acc[4][8][4];
#pragma unroll
    for (int im = 0; im < 4; im++)
#pragma unroll
        for (int in = 0; in < 8; in++)
#pragma unroll
            for (int q = 0; q < 4; q++) acc[im][in][q] = 0.0f;

    auto prefetch = [&](int c, int st) {
#pragma unroll
        for (int i = 0; i < 12; i++) {
            int idx = tid + i * 128;        // 0..1535 16B-units
            int arr = idx >> 9;             // 0:A 1:Bh 2:Bl
            int e   = idx & 511;
            int row = e >> 2;
            int seg = e & 3;
            const __half* gp;
            size_t koff = (size_t)c * GBK + seg * 8;
            if      (arr == 0) gp = A   + (size_t)(bm + row) * Kdim + koff;
            else if (arr == 1) gp = Bhi + (size_t)(bn + row) * Kdim + koff;
            else               gp = Blo + (size_t)(bn + row) * Kdim + koff;
            uint32_t sa = sb + st * STAGE_B + arr * ARR_B + row * ROWB + seg * 16;
            cp16(sa, gp);
        }
        asm volatile("cp.async.commit_group;");
    };

    prefetch(0, 0);

    for (int c = 0; c < NC; c++) {
        const int st = c & 1;
        if (c + 1 < NC) {
            prefetch(c + 1, (c + 1) & 1);
            asm volatile("cp.async.wait_group 1;");
        } else {
            asm volatile("cp.async.wait_group 0;");
        }
        __syncthreads();

        const uint32_t stb = sb + st * STAGE_B;

#pragma unroll
        for (int kk = 0; kk < GBK; kk += 16) {
            const uint32_t kb = (uint32_t)(kk * 2);
            uint32_t a[4][4], bf[8][2];
            // B-hi fragments
#pragma unroll
            for (int p = 0; p < 4; p++)
                ldsm4(bf[2*p][0], bf[2*p][1], bf[2*p+1][0], bf[2*p+1][1],
                      stb + ARR_B + offB + p * (16 * ROWB) + kb);
            // A fragments
#pragma unroll
            for (int im = 0; im < 4; im++)
                ldsm4(a[im][0], a[im][1], a[im][2], a[im][3],
                      stb + offA + im * (16 * ROWB) + kb);
            // pass 1: A * Bh
#pragma unroll
            for (int im = 0; im < 4; im++)
#pragma unroll
                for (int in = 0; in < 8; in++)
                    mma16816(acc[im][in], a[im], bf[in]);
            // B-lo fragments (reuse regs)
#pragma unroll
            for (int p = 0; p < 4; p++)
                ldsm4(bf[2*p][0], bf[2*p][1], bf[2*p+1][0], bf[2*p+1][1],
                      stb + 2 * ARR_B + offB + p * (16 * ROWB) + kb);
            // pass 2: A * Bl
#pragma unroll
            for (int im = 0; im < 4; im++)
#pragma unroll
                for (int in = 0; in < 8; in++)
                    mma16816(acc[im][in], a[im], bf[in]);
        }
        __syncthreads();
    }

    // epilogue
    int sec = FUSE ? (bn >> 10) : 0;       // uniform per CTA
#pragma unroll
    for (int im = 0; im < 4; im++) {
        int r = bm + wm * 64 + im * 16 + g;
#pragma unroll
        for (int in = 0; in < 8; in++) {
            int ccol = bn + wn * 64 + in * 8 + 2 * tig;
            float2 b01 = *(const float2*)&bias[ccol];
            float2 o0 = make_float2(acc[im][in][0] + b01.x, acc[im][in][1] + b01.y);
            float2 o1 = make_float2(acc[im][in][2] + b01.x, acc[im][in][3] + b01.y);
            if (!FUSE) {
                *(float2*)&C[(size_t)r * N + ccol]       = o0;
                *(float2*)&C[(size_t)(r + 8) * N + ccol] = o1;
            } else {
                int col = ccol & 1023;
                if (sec == 0) {
                    *(uint32_t*)&qh[(size_t)r * 1024 + col]       = pack2h(o0.x, o0.y);
                    *(uint32_t*)&qh[(size_t)(r + 8) * 1024 + col] = pack2h(o1.x, o1.y);
                } else {
                    __half *dh = (sec == 1) ? kh : vh;
                    __half *dl = (sec == 1) ? kl : vl;
                    uint32_t h0, l0, h1, l1;
                    splitpack_h(o0.x, o0.y, h0, l0);
                    splitpack_h(o1.x, o1.y, h1, l1);
                    *(uint32_t*)&dh[(size_t)r * 1024 + col]       = h0;
                    *(uint32_t*)&dl[(size_t)r * 1024 + col]       = l0;
                    *(uint32_t*)&dh[(size_t)(r + 8) * 1024 + col] = h1;
                    *(uint32_t*)&dl[(size_t)(r + 8) * 1024 + col] = l1;
                }
            }
        }
    }
}

// ---------------- fp16 2-pass flash attention: 3-stage cp.async + ldmatrix ----------------
// Stage: Kh, Kl, Vh, Vl each [64 rows][72 fp16] (144 B rows), row-major [kv][hd].
#define AKVROW 144
#define AARR   9216
#define AST    36864
#define ATTN_SMEM (3 * AST)

__global__ __launch_bounds__(256, 1)
void attn_mma(const __half* __restrict__ qh,
              const __half* __restrict__ kh, const __half* __restrict__ kl,
              const __half* __restrict__ vh, const __half* __restrict__ vl,
              const int* __restrict__ mask, __half* __restrict__ oh)
{
    extern __shared__ char asmem[];
    __shared__ int sMask[3][64];
    const uint32_t sb = smem_u32(asmem);
    const uint32_t mb = smem_u32(&sMask[0][0]);

    const int tid = threadIdx.x, wid = tid >> 5, lane = tid & 31;
    const int g = lane >> 2, tig = lane & 3;
    const int qd = lane >> 3, il = lane & 7;
    const uint32_t offKV  = (uint32_t)((il + (qd >> 1) * 8) * AKVROW + ((qd & 1) * 8) * 2);
    const uint32_t offKVt = (uint32_t)((il + (qd & 1) * 8) * AKVROW + ((qd >> 1) * 8) * 2);

    const int qt = gridDim.x - 1 - blockIdx.x;   // heavy tiles launch first
    const int bh = blockIdx.y;
    const int b = bh >> 4, h = bh & 15;
    const int q0 = qt * 128;
    const int wrow = q0 + wid * 16;
    const float scale = 0.125f;

    // resident Q fragments (fp16, single)
    uint32_t aq[4][4];
    {
        const __half* qb = qh + (size_t)(b * Ss + wrow) * Ee + h * 64;
#pragma unroll
        for (int s = 0; s < 4; s++) {
            int k0 = s * 16 + 2 * tig;
            aq[s][0] = *(const uint32_t*)&qb[(size_t)(g    ) * Ee + k0];
            aq[s][1] = *(const uint32_t*)&qb[(size_t)(g + 8) * Ee + k0];
            aq[s][2] = *(const uint32_t*)&qb[(size_t)(g    ) * Ee + k0 + 8];
            aq[s][3] = *(const uint32_t*)&qb[(size_t)(g + 8) * Ee + k0 + 8];
        }
    }

    auto prefetch = [&](int j) {
        const int kv0 = j * 64;
        const int st = j % 3;
        const uint32_t stb = sb + st * AST;
#pragma unroll
        for (int i = 0; i < 8; i++) {
            int idx = tid + i * 256;
            int arr = idx >> 9;
            int e   = idx & 511;
            int row = e >> 3;
            int segB = (e & 7) * 16;
            const __half* gp;
            if      (arr == 0) gp = kh + (size_t)(b * Ss + kv0 + row) * Ee + h * 64 + segB / 2;
            else if (arr == 1) gp = kl + (size_t)(b * Ss + kv0 + row) * Ee + h * 64 + segB / 2;
            else if (arr == 2) gp = vh + (size_t)(b * Ss + kv0 + row) * Ee + h * 64 + segB / 2;
            else               gp = vl + (size_t)(b * Ss + kv0 + row) * Ee + h * 64 + segB / 2;
            cp16(stb + arr * AARR + row * AKVROW + segB, gp);
        }
        if (tid < 16)
            cp16(mb + st * 256 + tid * 16, &mask[b * Ss + kv0 + tid * 4]);
        asm volatile("cp.async.commit_group;");
    };

    float m0 = -1e30f, m1 = -1e30f, l0 = 0.0f, l1 = 0.0f;
    float o[8][4];
#pragma unroll
    for (int t = 0; t < 8; t++)
#pragma unroll
        for (int e = 0; e < 4; e++) o[t][e] = 0.0f;

    const int row0 = wrow + g, row1 = wrow + 8 + g;
    const int ntiles = (qt + 1) * 2;

    prefetch(0);

    for (int j = 0; j < ntiles; j++) {
        const int kv0 = j * 64;
        const int st = j % 3;
        if (j + 1 < ntiles) {
            prefetch(j + 1);
            asm volatile("cp.async.wait_group 1;");
        } else {
            asm volatile("cp.async.wait_group 0;");
        }
        __syncthreads();

        const uint32_t stb = sb + st * AST;
        const int* msk = sMask[st];

        // ---- S = Q (Kh + Kl)^T (2-pass) ----
        float c[8][4];
#pragma unroll
        for (int t = 0; t < 8; t++)
#pragma unroll
            for (int e = 0; e < 4; e++) c[t][e] = 0.0f;

#pragma unroll
        for (int s = 0; s < 4; s++) {
            const uint32_t kb = (uint32_t)(s * 32);
            uint32_t kf[8][2], lf[8][2];
#pragma unroll
            for (int p = 0; p < 4; p++)
                ldsm4(kf[2*p][0], kf[2*p][1], kf[2*p+1][0], kf[2*p+1][1],
                      stb + offKV + p * (16 * AKVROW) + kb);
#pragma unroll
            for (int p = 0; p < 4; p++)
                ldsm4(lf[2*p][0], lf[2*p][1], lf[2*p+1][0], lf[2*p+1][1],
                      stb + AARR + offKV + p * (16 * AKVROW) + kb);
#pragma unroll
            for (int t = 0; t < 8; t++) {
                mma16816(c[t], aq[s], kf[t]);
                mma16816(c[t], aq[s], lf[t]);
            }
        }

        // ---- scale + causal + key mask ----
#pragma unroll
        for (int t = 0; t < 8; t++) {
            int lc0 = t * 8 + 2 * tig;
            int col0 = kv0 + lc0, col1 = col0 + 1;
            bool v0 = msk[lc0] != 0, v1 = msk[lc0 + 1] != 0;
            c[t][0] = (v0 && col0 <= row0) ? c[t][0] * scale : -1e30f;
            c[t][1] = (v1 && col1 <= row0) ? c[t][1] * scale : -1e30f;
            c[t][2] = (v0 && col0 <= row1) ? c[t][2] * scale : -1e30f;
            c[t][3] = (v1 && col1 <= row1) ? c[t][3] * scale : -1e30f;
        }

        // ---- online softmax ----
        float ml0 = -1e30f, ml1 = -1e30f;
#pragma unroll
        for (int t = 0; t < 8; t++) {
            ml0 = fmaxf(ml0, fmaxf(c[t][0], c[t][1]));
            ml1 = fmaxf(ml1, fmaxf(c[t][2], c[t][3]));
        }
        ml0 = fmaxf(ml0, __shfl_xor_sync(0xffffffffu, ml0, 1));
        ml0 = fmaxf(ml0, __shfl_xor_sync(0xffffffffu, ml0, 2));
        ml1 = fmaxf(ml1, __shfl_xor_sync(0xffffffffu, ml1, 1));
        ml1 = fmaxf(ml1, __shfl_xor_sync(0xffffffffu, ml1, 2));

        float mn0 = fmaxf(m0, ml0), mn1 = fmaxf(m1, ml1);
        float alpha0 = __expf(m0 - mn0), alpha1 = __expf(m1 - mn1);
        m0 = mn0; m1 = mn1;

        float rs0 = 0.0f, rs1 = 0.0f;
#pragma unroll
        for (int t = 0; t < 8; t++) {
            c[t][0] = __expf(c[t][0] - m0); rs0 += c[t][0];
            c[t][1] = __expf(c[t][1] - m0); rs0 += c[t][1];
            c[t][2] = __expf(c[t][2] - m1); rs1 += c[t][2];
            c[t][3] = __expf(c[t][3] - m1); rs1 += c[t][3];
        }
        rs0 += __shfl_xor_sync(0xffffffffu, rs0, 1);
        rs0 += __shfl_xor_sync(0xffffffffu, rs0, 2);
        rs1 += __shfl_xor_sync(0xffffffffu, rs1, 1);
        rs1 += __shfl_xor_sync(0xffffffffu, rs1, 2);

        l0 = l0 * alpha0 + rs0;
        l1 = l1 * alpha1 + rs1;
#pragma unroll
        for (int t = 0; t < 8; t++) {
            o[t][0] *= alpha0; o[t][1] *= alpha0;
            o[t][2] *= alpha1; o[t][3] *= alpha1;
        }

        // ---- O += P (Vh + Vl) (2-pass), P single fp16, V via ldmatrix.trans ----
#pragma unroll
        for (int s = 0; s < 4; s++) {
            uint32_t ap[4];
            ap[0] = pack2h(c[2 * s][0],     c[2 * s][1]);
            ap[1] = pack2h(c[2 * s][2],     c[2 * s][3]);
            ap[2] = pack2h(c[2 * s + 1][0], c[2 * s + 1][1]);
            ap[3] = pack2h(c[2 * s + 1][2], c[2 * s + 1][3]);
            const uint32_t krow = (uint32_t)(s * 16 * AKVROW);
            uint32_t vf[8][2], wf[8][2];
#pragma unroll
            for (int p = 0; p < 4; p++)
                ldsm4t(vf[2*p][0], vf[2*p][1], vf[2*p+1][0], vf[2*p+1][1],
                       stb + 2 * AARR + offKVt + krow + p * 32);
#pragma unroll
            for (int p = 0; p < 4; p++)
                ldsm4t(wf[2*p][0], wf[2*p][1], wf[2*p+1][0], wf[2*p+1][1],
                       stb + 3 * AARR + offKVt + krow + p * 32);
#pragma unroll
            for (int t = 0; t < 8; t++) {
                mma16816(o[t], ap, vf[t]);
                mma16816(o[t], ap, wf[t]);
            }
        }
    }

    // epilogue: write fp16 output (proj GEMM A operand)
    float inv0 = 1.0f / l0, inv1 = 1.0f / l1;
    size_t base0 = (size_t)(b * Ss + row0) * Ee + h * 64;
    size_t base1 = (size_t)(b * Ss + row1) * Ee + h * 64;
#pragma unroll
    for (int t = 0; t < 8; t++) {
        int cc = t * 8 + 2 * tig;
        *(uint32_t*)&oh[base0 + cc] = pack2h(o[t][0] * inv0, o[t][1] * inv0);
        *(uint32_t*)&oh[base1 + cc] = pack2h(o[t][2] * inv1, o[t][3] * inv1);
    }
}

// ---------------- launch ----------------
extern "C" void kernel_launch(void* const* d_in, const int* in_sizes, int n_in,
                              void* d_out, int out_size)
{
    const float* X     = (const float*)d_in[0];
    const int*   mask  = (const int*)  d_in[1];
    const float* Wqkv  = (const float*)d_in[2];
    const float* bqkv  = (const float*)d_in[3];
    const float* Wproj = (const float*)d_in[4];
    const float* bproj = (const float*)d_in[5];
    float* out = (float*)d_out;

    __half *xh, *qh, *kh, *kl, *vh, *vl, *wqh, *wql, *wph, *wpl, *oh;
    cudaGetSymbolAddress((void**)&xh,   g_xh);
    cudaGetSymbolAddress((void**)&qh,   g_qh);
    cudaGetSymbolAddress((void**)&kh,   g_kh);
    cudaGetSymbolAddress((void**)&kl,   g_kl);
    cudaGetSymbolAddress((void**)&vh,   g_vh);
    cudaGetSymbolAddress((void**)&vl,   g_vl);
    cudaGetSymbolAddress((void**)&wqh,  g_wqh);
    cudaGetSymbolAddress((void**)&wql,  g_wql);
    cudaGetSymbolAddress((void**)&wph,  g_wph);
    cudaGetSymbolAddress((void**)&wpl,  g_wpl);
    cudaGetSymbolAddress((void**)&oh,   g_oh);

    cudaFuncSetAttribute(gemm_mma<true>,  cudaFuncAttributeMaxDynamicSharedMemorySize, GEMM_SMEM);
    cudaFuncSetAttribute(gemm_mma<false>, cudaFuncAttributeMaxDynamicSharedMemorySize, GEMM_SMEM);
    cudaFuncSetAttribute(attn_mma, cudaFuncAttributeMaxDynamicSharedMemorySize, ATTN_SMEM);

    // prep: X -> fp16; transpose+split weights
    to_half<<<(MTOT * Ee) / 4 / 256, 256>>>(X, xh, MTOT * Ee);
    {
        dim3 blk(32, 8);
        transpose_split<<<dim3(E3 / 32, Kdim / 32), blk>>>(Wqkv, wqh, wql, Kdim, E3);
        transpose_split<<<dim3(Ee / 32, Kdim / 32), blk>>>(Wproj, wph, wpl, Kdim, Ee);
    }

    // 1) QKV = X @ Wqkv + b (fp16 2-pass), fused epilogue
    gemm_mma<true><<<dim3(E3 / 128, MTOT / 128), 128, GEMM_SMEM>>>(
        xh, wqh, wql, bqkv, nullptr, E3, qh, kh, kl, vh, vl);

    // 2) flash attention (fp16 2-pass)
    attn_mma<<<dim3(Ss / 128, Bb * Hh), 256, ATTN_SMEM>>>(qh, kh, kl, vh, vl, mask, oh);

    // 3) out = attn @ Wproj + b (fp16 2-pass, fp32 out)
    gemm_mma<false><<<dim3(Ee / 128, MTOT / 128), 128, GEMM_SMEM>>>(
        oh, wph, wpl, bproj, out, Ee, qh, kh, kl, vh, vl);
}

// round 12
// speedup vs baseline: 3.2357x; 1.7662x over previous
#include <cuda_runtime.h>
#include <cuda_fp16.h>
#include <cstdint>
#include <math.h>

// ---------------- problem constants ----------------
#define Bb   4
#define Ss   1024
#define Ee   1024
#define Hh   16
#define HDs  64
#define MTOT 4096      // B*S
#define E3   3072      // 3*E
#define Kdim 1024

// ---------------- scratch (device globals, fp16 single-precision path) ----------------
__device__ __half  g_xh [MTOT * Ee];     // X fp16 (QKV GEMM A)
__device__ __half  g_qh [MTOT * Ee];     // Q fp16
__device__ __half  g_kh [MTOT * Ee];     // K fp16
__device__ __half  g_vh [MTOT * Ee];     // V fp16, row-major [s][hd]
__device__ __half  g_wq [E3 * Ee];       // Wqkv^T fp16
__device__ __half  g_wp [Ee * Ee];       // Wproj^T fp16
__device__ __half  g_oh [MTOT * Ee];     // attention output fp16 (proj A)

// ---------------- helpers ----------------
__device__ __forceinline__ void mma16816(float* c, const uint32_t* a, const uint32_t* b)
{
    asm volatile(
        "mma.sync.aligned.m16n8k16.row.col.f32.f16.f16.f32 "
        "{%0,%1,%2,%3}, {%4,%5,%6,%7}, {%8,%9}, {%0,%1,%2,%3};"
        : "+f"(c[0]), "+f"(c[1]), "+f"(c[2]), "+f"(c[3])
        : "r"(a[0]), "r"(a[1]), "r"(a[2]), "r"(a[3]), "r"(b[0]), "r"(b[1]));
}
__device__ __forceinline__ void ldsm4(uint32_t& r0, uint32_t& r1, uint32_t& r2, uint32_t& r3,
                                      uint32_t addr)
{
    asm volatile("ldmatrix.sync.aligned.m8n8.x4.shared.b16 {%0,%1,%2,%3}, [%4];"
                 : "=r"(r0), "=r"(r1), "=r"(r2), "=r"(r3) : "r"(addr));
}
__device__ __forceinline__ void ldsm4t(uint32_t& r0, uint32_t& r1, uint32_t& r2, uint32_t& r3,
                                       uint32_t addr)
{
    asm volatile("ldmatrix.sync.aligned.m8n8.x4.trans.shared.b16 {%0,%1,%2,%3}, [%4];"
                 : "=r"(r0), "=r"(r1), "=r"(r2), "=r"(r3) : "r"(addr));
}
__device__ __forceinline__ void cp16(uint32_t saddr, const void* g)
{
    asm volatile("cp.async.cg.shared.global [%0], [%1], 16;"
                 :: "r"(saddr), "l"(g));
}
__device__ __forceinline__ uint32_t smem_u32(const void* p) {
    uint32_t a;
    asm("{ .reg .u64 t; cvta.to.shared.u64 t, %1; cvt.u32.u64 %0, t; }"
        : "=r"(a) : "l"(p));
    return a;
}
__device__ __forceinline__ uint32_t pack2h(float f0, float f1)
{
    __half2 p = __floats2half2_rn(f0, f1);
    return *(uint32_t*)&p;
}

// ---------------- fp32 -> fp16 convert ----------------
__global__ __launch_bounds__(256)
void to_half(const float* __restrict__ x, __half* __restrict__ h, int n)
{
    int i = (blockIdx.x * 256 + threadIdx.x) * 4;
    if (i >= n) return;
    float4 v = *(const float4*)(x + i);
    __half hh[4] = {__float2half_rn(v.x), __float2half_rn(v.y),
                    __float2half_rn(v.z), __float2half_rn(v.w)};
    *(uint2*)(h + i) = *(uint2*)hh;
}

// ---------------- transpose W: W[K][N] -> T[N][K] (fp16) ----------------
__global__ __launch_bounds__(256)
void transpose_h(const float* __restrict__ W, __half* __restrict__ T, int K, int N)
{
    __shared__ float tile[32][33];
    int n0 = blockIdx.x * 32, k0 = blockIdx.y * 32;
    int tx = threadIdx.x, ty = threadIdx.y;
#pragma unroll
    for (int i = 0; i < 32; i += 8)
        tile[ty + i][tx] = W[(size_t)(k0 + ty + i) * N + n0 + tx];
    __syncthreads();
#pragma unroll
    for (int i = 0; i < 32; i += 8) {
        int n = n0 + ty + i, k = k0 + tx;
        T[(size_t)n * K + k] = __float2half_rn(tile[tx][ty + i]);
    }
}

// ---------------- fp16 single-pass GEMM: C = A @ B^T + bias ----------------
// FUSE=0: C fp32 out. FUSE=1: QKV epilogue — sec0->qh, sec1->kh, sec2->vh (fp16, stride 1024).
#define GBK      32
#define GSTRIDE  40
#define ROWB     (GSTRIDE * 2)
#define ARR_B    (128 * ROWB)              // 10240 B
#define STAGE_B  (2 * ARR_B)               // A, B
#define GEMM_SMEM (2 * STAGE_B)            // 40960 B

template<bool FUSE>
__global__ __launch_bounds__(128, 2)
void gemm_mma(const __half* __restrict__ A, const __half* __restrict__ B,
              const float* __restrict__ bias, float* __restrict__ C, int N,
              __half* __restrict__ qh, __half* __restrict__ kh, __half* __restrict__ vh)
{
    extern __shared__ char smem[];
    const uint32_t sb = smem_u32(smem);
    const int tid  = threadIdx.x;
    const int wid  = tid >> 5, lane = tid & 31;
    const int wm   = wid >> 1, wn = wid & 1;          // warp grid 2x2, tile 64x64
    const int g    = lane >> 2, tig = lane & 3;
    const int bm   = blockIdx.y * 128, bn = blockIdx.x * 128;
    const int NC   = Kdim / GBK;

    const int qd = lane >> 3, il = lane & 7;
    const uint32_t offA = (uint32_t)((wm * 64 + il + (qd & 1) * 8) * ROWB + ((qd >> 1) * 8) * 2);
    const uint32_t offB = (uint32_t)((wn * 64 + il + (qd >> 1) * 8) * ROWB + ((qd & 1) * 8) * 2);

    float acc[4][8][4];
#pragma unroll
    for (int im = 0; im < 4; im++)
#pragma unroll
        for (int in = 0; in < 8; in++)
#pragma unroll
            for (int q = 0; q < 4; q++) acc[im][in][q] = 0.0f;

    auto prefetch = [&](int c, int st) {
#pragma unroll
        for (int i = 0; i < 8; i++) {
            int idx = tid + i * 128;        // 0..1023 16B-units
            int arr = idx >> 9;             // 0:A 1:B
            int e   = idx & 511;
            int row = e >> 2;
            int seg = e & 3;
            const __half* gp;
            size_t koff = (size_t)c * GBK + seg * 8;
            if (arr == 0) gp = A + (size_t)(bm + row) * Kdim + koff;
            else          gp = B + (size_t)(bn + row) * Kdim + koff;
            uint32_t sa = sb + st * STAGE_B + arr * ARR_B + row * ROWB + seg * 16;
            cp16(sa, gp);
        }
        asm volatile("cp.async.commit_group;");
    };

    prefetch(0, 0);

    for (int c = 0; c < NC; c++) {
        const int st = c & 1;
        if (c + 1 < NC) {
            prefetch(c + 1, (c + 1) & 1);
            asm volatile("cp.async.wait_group 1;");
        } else {
            asm volatile("cp.async.wait_group 0;");
        }
        __syncthreads();

        const uint32_t stb = sb + st * STAGE_B;

#pragma unroll
        for (int kk = 0; kk < GBK; kk += 16) {
            const uint32_t kb = (uint32_t)(kk * 2);
            uint32_t a[4][4], bf[8][2];
#pragma unroll
            for (int p = 0; p < 4; p++)
                ldsm4(bf[2*p][0], bf[2*p][1], bf[2*p+1][0], bf[2*p+1][1],
                      stb + ARR_B + offB + p * (16 * ROWB) + kb);
#pragma unroll
            for (int im = 0; im < 4; im++)
                ldsm4(a[im][0], a[im][1], a[im][2], a[im][3],
                      stb + offA + im * (16 * ROWB) + kb);
#pragma unroll
            for (int im = 0; im < 4; im++)
#pragma unroll
                for (int in = 0; in < 8; in++)
                    mma16816(acc[im][in], a[im], bf[in]);
        }
        __syncthreads();
    }

    // epilogue
    __half* d = qh;
    if (FUSE) {
        int sec = bn >> 10;                // uniform per CTA
        if (sec == 1) d = kh;
        else if (sec == 2) d = vh;
    }
#pragma unroll
    for (int im = 0; im < 4; im++) {
        int r = bm + wm * 64 + im * 16 + g;
#pragma unroll
        for (int in = 0; in < 8; in++) {
            int ccol = bn + wn * 64 + in * 8 + 2 * tig;
            float2 b01 = *(const float2*)&bias[ccol];
            float2 o0 = make_float2(acc[im][in][0] + b01.x, acc[im][in][1] + b01.y);
            float2 o1 = make_float2(acc[im][in][2] + b01.x, acc[im][in][3] + b01.y);
            if (!FUSE) {
                *(float2*)&C[(size_t)r * N + ccol]       = o0;
                *(float2*)&C[(size_t)(r + 8) * N + ccol] = o1;
            } else {
                int col = ccol & 1023;
                *(uint32_t*)&d[(size_t)r * 1024 + col]       = pack2h(o0.x, o0.y);
                *(uint32_t*)&d[(size_t)(r + 8) * 1024 + col] = pack2h(o1.x, o1.y);
            }
        }
    }
}

// ---------------- fp16 single-pass flash attention: 3-stage cp.async + ldmatrix ----------------
// Stage: K, V each [64 rows][72 fp16] (144 B rows), row-major [kv][hd].
#define AKVROW 144
#define AARR   9216
#define AST    (2 * AARR)                  // 18432
#define ATTN_SMEM (3 * AST)                // 55296

__global__ __launch_bounds__(256, 1)
void attn_mma(const __half* __restrict__ qh,
              const __half* __restrict__ kh, const __half* __restrict__ vh,
              const int* __restrict__ mask, __half* __restrict__ oh)
{
    extern __shared__ char asmem[];
    __shared__ int sMask[3][64];
    const uint32_t sb = smem_u32(asmem);
    const uint32_t mb = smem_u32(&sMask[0][0]);

    const int tid = threadIdx.x, wid = tid >> 5, lane = tid & 31;
    const int g = lane >> 2, tig = lane & 3;
    const int qd = lane >> 3, il = lane & 7;
    const uint32_t offKV  = (uint32_t)((il + (qd >> 1) * 8) * AKVROW + ((qd & 1) * 8) * 2);
    const uint32_t offKVt = (uint32_t)((il + (qd & 1) * 8) * AKVROW + ((qd >> 1) * 8) * 2);

    const int qt = gridDim.x - 1 - blockIdx.x;   // heavy tiles launch first
    const int bh = blockIdx.y;
    const int b = bh >> 4, h = bh & 15;
    const int q0 = qt * 128;
    const int wrow = q0 + wid * 16;
    const float scale = 0.125f;

    // resident Q fragments
    uint32_t aq[4][4];
    {
        const __half* qb = qh + (size_t)(b * Ss + wrow) * Ee + h * 64;
#pragma unroll
        for (int s = 0; s < 4; s++) {
            int k0 = s * 16 + 2 * tig;
            aq[s][0] = *(const uint32_t*)&qb[(size_t)(g    ) * Ee + k0];
            aq[s][1] = *(const uint32_t*)&qb[(size_t)(g + 8) * Ee + k0];
            aq[s][2] = *(const uint32_t*)&qb[(size_t)(g    ) * Ee + k0 + 8];
            aq[s][3] = *(const uint32_t*)&qb[(size_t)(g + 8) * Ee + k0 + 8];
        }
    }

    auto prefetch = [&](int j) {
        const int kv0 = j * 64;
        const int st = j % 3;
        const uint32_t stb = sb + st * AST;
        // 2 arrays x 64 rows x 8 x 16B = 1024 units; 4 per thread
#pragma unroll
        for (int i = 0; i < 4; i++) {
            int idx = tid + i * 256;
            int arr = idx >> 9;             // 0:K 1:V
            int e   = idx & 511;
            int row = e >> 3;
            int segB = (e & 7) * 16;
            const __half* gp = (arr == 0 ? kh : vh)
                             + (size_t)(b * Ss + kv0 + row) * Ee + h * 64 + segB / 2;
            cp16(stb + arr * AARR + row * AKVROW + segB, gp);
        }
        if (tid < 16)
            cp16(mb + st * 256 + tid * 16, &mask[b * Ss + kv0 + tid * 4]);
        asm volatile("cp.async.commit_group;");
    };

    float m0 = -1e30f, m1 = -1e30f, l0 = 0.0f, l1 = 0.0f;
    float o[8][4];
#pragma unroll
    for (int t = 0; t < 8; t++)
#pragma unroll
        for (int e = 0; e < 4; e++) o[t][e] = 0.0f;

    const int row0 = wrow + g, row1 = wrow + 8 + g;
    const int ntiles = (qt + 1) * 2;

    prefetch(0);

    for (int j = 0; j < ntiles; j++) {
        const int kv0 = j * 64;
        const int st = j % 3;
        if (j + 1 < ntiles) {
            prefetch(j + 1);
            asm volatile("cp.async.wait_group 1;");
        } else {
            asm volatile("cp.async.wait_group 0;");
        }
        __syncthreads();

        const uint32_t stb = sb + st * AST;
        const int* msk = sMask[st];

        // ---- S = Q K^T (single pass) ----
        float c[8][4];
#pragma unroll
        for (int t = 0; t < 8; t++)
#pragma unroll
            for (int e = 0; e < 4; e++) c[t][e] = 0.0f;

#pragma unroll
        for (int s = 0; s < 4; s++) {
            const uint32_t kb = (uint32_t)(s * 32);
            uint32_t kf[8][2];
#pragma unroll
            for (int p = 0; p < 4; p++)
                ldsm4(kf[2*p][0], kf[2*p][1], kf[2*p+1][0], kf[2*p+1][1],
                      stb + offKV + p * (16 * AKVROW) + kb);
#pragma unroll
            for (int t = 0; t < 8; t++)
                mma16816(c[t], aq[s], kf[t]);
        }

        // ---- scale + causal + key mask ----
#pragma unroll
        for (int t = 0; t < 8; t++) {
            int lc0 = t * 8 + 2 * tig;
            int col0 = kv0 + lc0, col1 = col0 + 1;
            bool v0 = msk[lc0] != 0, v1 = msk[lc0 + 1] != 0;
            c[t][0] = (v0 && col0 <= row0) ? c[t][0] * scale : -1e30f;
            c[t][1] = (v1 && col1 <= row0) ? c[t][1] * scale : -1e30f;
            c[t][2] = (v0 && col0 <= row1) ? c[t][2] * scale : -1e30f;
            c[t][3] = (v1 && col1 <= row1) ? c[t][3] * scale : -1e30f;
        }

        // ---- online softmax ----
        float ml0 = -1e30f, ml1 = -1e30f;
#pragma unroll
        for (int t = 0; t < 8; t++) {
            ml0 = fmaxf(ml0, fmaxf(c[t][0], c[t][1]));
            ml1 = fmaxf(ml1, fmaxf(c[t][2], c[t][3]));
        }
        ml0 = fmaxf(ml0, __shfl_xor_sync(0xffffffffu, ml0, 1));
        ml0 = fmaxf(ml0, __shfl_xor_sync(0xffffffffu, ml0, 2));
        ml1 = fmaxf(ml1, __shfl_xor_sync(0xffffffffu, ml1, 1));
        ml1 = fmaxf(ml1, __shfl_xor_sync(0xffffffffu, ml1, 2));

        float mn0 = fmaxf(m0, ml0), mn1 = fmaxf(m1, ml1);
        float alpha0 = __expf(m0 - mn0), alpha1 = __expf(m1 - mn1);
        m0 = mn0; m1 = mn1;

        float rs0 = 0.0f, rs1 = 0.0f;
#pragma unroll
        for (int t = 0; t < 8; t++) {
            c[t][0] = __expf(c[t][0] - m0); rs0 += c[t][0];
            c[t][1] = __expf(c[t][1] - m0); rs0 += c[t][1];
            c[t][2] = __expf(c[t][2] - m1); rs1 += c[t][2];
            c[t][3] = __expf(c[t][3] - m1); rs1 += c[t][3];
        }
        rs0 += __shfl_xor_sync(0xffffffffu, rs0, 1);
        rs0 += __shfl_xor_sync(0xffffffffu, rs0, 2);
        rs1 += __shfl_xor_sync(0xffffffffu, rs1, 1);
        rs1 += __shfl_xor_sync(0xffffffffu, rs1, 2);

        l0 = l0 * alpha0 + rs0;
        l1 = l1 * alpha1 + rs1;
#pragma unroll
        for (int t = 0; t < 8; t++) {
            o[t][0] *= alpha0; o[t][1] *= alpha0;
            o[t][2] *= alpha1; o[t][3] *= alpha1;
        }

        // ---- O += P V (single pass), V via ldmatrix.trans ----
#pragma unroll
        for (int s = 0; s < 4; s++) {
            uint32_t ap[4];
            ap[0] = pack2h(c[2 * s][0],     c[2 * s][1]);
            ap[1] = pack2h(c[2 * s][2],     c[2 * s][3]);
            ap[2] = pack2h(c[2 * s + 1][0], c[2 * s + 1][1]);
            ap[3] = pack2h(c[2 * s + 1][2], c[2 * s + 1][3]);
            const uint32_t krow = (uint32_t)(s * 16 * AKVROW);
            uint32_t vf[8][2];
#pragma unroll
            for (int p = 0; p < 4; p++)
                ldsm4t(vf[2*p][0], vf[2*p][1], vf[2*p+1][0], vf[2*p+1][1],
                       stb + AARR + offKVt + krow + p * 32);
#pragma unroll
            for (int t = 0; t < 8; t++)
                mma16816(o[t], ap, vf[t]);
        }
    }

    // epilogue: write fp16 output (proj GEMM A operand)
    float inv0 = 1.0f / l0, inv1 = 1.0f / l1;
    size_t base0 = (size_t)(b * Ss + row0) * Ee + h * 64;
    size_t base1 = (size_t)(b * Ss + row1) * Ee + h * 64;
#pragma unroll
    for (int t = 0; t < 8; t++) {
        int cc = t * 8 + 2 * tig;
        *(uint32_t*)&oh[base0 + cc] = pack2h(o[t][0] * inv0, o[t][1] * inv0);
        *(uint32_t*)&oh[base1 + cc] = pack2h(o[t][2] * inv1, o[t][3] * inv1);
    }
}

// ---------------- launch ----------------
extern "C" void kernel_launch(void* const* d_in, const int* in_sizes, int n_in,
                              void* d_out, int out_size)
{
    const float* X     = (const float*)d_in[0];
    const int*   mask  = (const int*)  d_in[1];
    const float* Wqkv  = (const float*)d_in[2];
    const float* bqkv  = (const float*)d_in[3];
    const float* Wproj = (const float*)d_in[4];
    const float* bproj = (const float*)d_in[5];
    float* out = (float*)d_out;

    __half *xh, *qh, *kh, *vh, *wq, *wp, *oh;
    cudaGetSymbolAddress((void**)&xh, g_xh);
    cudaGetSymbolAddress((void**)&qh, g_qh);
    cudaGetSymbolAddress((void**)&kh, g_kh);
    cudaGetSymbolAddress((void**)&vh, g_vh);
    cudaGetSymbolAddress((void**)&wq, g_wq);
    cudaGetSymbolAddress((void**)&wp, g_wp);
    cudaGetSymbolAddress((void**)&oh, g_oh);

    cudaFuncSetAttribute(gemm_mma<true>,  cudaFuncAttributeMaxDynamicSharedMemorySize, GEMM_SMEM);
    cudaFuncSetAttribute(gemm_mma<false>, cudaFuncAttributeMaxDynamicSharedMemorySize, GEMM_SMEM);
    cudaFuncSetAttribute(attn_mma, cudaFuncAttributeMaxDynamicSharedMemorySize, ATTN_SMEM);

    // prep: X -> fp16; transpose weights -> fp16
    to_half<<<(MTOT * Ee) / 4 / 256, 256>>>(X, xh, MTOT * Ee);
    {
        dim3 blk(32, 8);
        transpose_h<<<dim3(E3 / 32, Kdim / 32), blk>>>(Wqkv, wq, Kdim, E3);
        transpose_h<<<dim3(Ee / 32, Kdim / 32), blk>>>(Wproj, wp, Kdim, Ee);
    }

    // 1) QKV = X @ Wqkv + b (fp16 single-pass), fused epilogue -> q/k/v fp16
    gemm_mma<true><<<dim3(E3 / 128, MTOT / 128), 128, GEMM_SMEM>>>(
        xh, wq, bqkv, nullptr, E3, qh, kh, vh);

    // 2) flash attention (fp16 single-pass)
    attn_mma<<<dim3(Ss / 128, Bb * Hh), 256, ATTN_SMEM>>>(qh, kh, vh, mask, oh);

    // 3) out = attn @ Wproj + b (fp16 single-pass, fp32 out)
    gemm_mma<false><<<dim3(Ee / 128, MTOT / 128), 128, GEMM_SMEM>>>(
        oh, wp, bproj, out, Ee, qh, kh, vh);
}